// round 2
// baseline (speedup 1.0000x reference)
#include <cuda_runtime.h>

#define SEQ   2048          // B*A
#define NT    121           // tokens
#define HDIM  128           // hidden
#define FIND  12            // feature in
#define NHEAD 4
#define HDH   32            // head dim
#define OUTD  256
#define MTOK  (SEQ*NT)      // 247808
#define KBIG  (NT*HDIM)     // 15488
#define EPSV  1e-5f

// ---------------- scratch (device globals; no allocation allowed) ----------
__device__ float g_x  [(size_t)MTOK * HDIM];
__device__ float g_qkv[(size_t)MTOK * 384];
__device__ float g_att[(size_t)MTOK * HDIM];
__device__ float g_tmp[(size_t)MTOK * HDIM];
__device__ float g_h  [(size_t)MTOK * HDIM];
__device__ float g_y  [(size_t)SEQ * OUTD];

// ---------------- embed: forest @ w_in^T + b_in + tree PE, then permute ----
__global__ void embed_kernel(const float* __restrict__ forest,
                             const int*   __restrict__ perm,
                             const float* __restrict__ w_in,
                             const float* __restrict__ b_in,
                             float* __restrict__ out)
{
    int tok = blockIdx.x;              // 0..MTOK-1 (output token position)
    int s = tok / NT, i = tok - s * NT;
    int node = perm[i];
    int h = threadIdx.x;               // 128
    __shared__ float fs[FIND];
    const float* f = forest + ((size_t)s * NT + node) * FIND;
    if (h < FIND) fs[h] = f[h];
    __syncthreads();
    float acc = b_in[h];
#pragma unroll
    for (int k = 0; k < FIND; k++) acc += fs[k] * w_in[h * FIND + k];
    // tree positional encoding: walk to root, bit (depth-1)*3 + branch
    if (h < 12) {
        int mask = 0, cur = node;
        while (cur > 0) {
            int d = (cur >= 40) ? 4 : (cur >= 13) ? 3 : (cur >= 4) ? 2 : 1;
            int br = (cur - 1) % 3;
            mask |= 1 << ((d - 1) * 3 + br);
            cur = (cur - 1) / 3;
        }
        acc += (float)((mask >> h) & 1);
    }
    out[(size_t)tok * HDIM + h] = acc;
}

// ---------------- generic SGEMM: C[M,Nc] = X[M,K] @ W[Nc,K]^T + bias -------
// 64x64 tile, BK=16, 256 threads, 4x4 microtile. M%64==0, Nc%64==0, K%16==0.
__global__ void gemm_bias_kernel(const float* __restrict__ X,
                                 const float* __restrict__ W,
                                 const float* __restrict__ bias,
                                 float* __restrict__ C,
                                 int M, int Nc, int K, int relu)
{
    __shared__ float Xs[16][68];
    __shared__ float Ws[16][68];
    int tid = threadIdx.x;
    int tx = tid & 15, ty = tid >> 4;
    int row0 = blockIdx.y * 64, col0 = blockIdx.x * 64;
    int lr = tid >> 2;
    int lc = (tid & 3) << 2;
    float acc[4][4] = {};
    const float* Xp = X + (size_t)(row0 + lr) * K + lc;
    const float* Wp = W + (size_t)(col0 + lr) * K + lc;
    for (int k0 = 0; k0 < K; k0 += 16) {
        float4 xv = *(const float4*)(Xp + k0);
        float4 wv = *(const float4*)(Wp + k0);
        Xs[lc + 0][lr] = xv.x; Xs[lc + 1][lr] = xv.y;
        Xs[lc + 2][lr] = xv.z; Xs[lc + 3][lr] = xv.w;
        Ws[lc + 0][lr] = wv.x; Ws[lc + 1][lr] = wv.y;
        Ws[lc + 2][lr] = wv.z; Ws[lc + 3][lr] = wv.w;
        __syncthreads();
#pragma unroll
        for (int kk = 0; kk < 16; kk++) {
            float4 a = *(const float4*)&Xs[kk][ty * 4];
            float4 b = *(const float4*)&Ws[kk][tx * 4];
            float av[4] = {a.x, a.y, a.z, a.w};
            float bv[4] = {b.x, b.y, b.z, b.w};
#pragma unroll
            for (int i = 0; i < 4; i++)
#pragma unroll
                for (int j = 0; j < 4; j++) acc[i][j] += av[i] * bv[j];
        }
        __syncthreads();
    }
#pragma unroll
    for (int i = 0; i < 4; i++) {
        int r = row0 + ty * 4 + i;
#pragma unroll
        for (int j = 0; j < 4; j++) {
            int c = col0 + tx * 4 + j;
            float v = acc[i][j] + bias[c];
            if (relu) v = fmaxf(v, 0.f);
            C[(size_t)r * Nc + c] = v;
        }
    }
}

// ---------------- split-K SGEMM for the deep output projection -------------
__global__ void gemm_splitk_kernel(const float* __restrict__ X,
                                   const float* __restrict__ W,
                                   float* __restrict__ C,
                                   int M, int Nc, int K, int kchunk)
{
    __shared__ float Xs[16][68];
    __shared__ float Ws[16][68];
    int tid = threadIdx.x;
    int tx = tid & 15, ty = tid >> 4;
    int row0 = blockIdx.y * 64, col0 = blockIdx.x * 64;
    int kstart = blockIdx.z * kchunk;
    int lr = tid >> 2;
    int lc = (tid & 3) << 2;
    float acc[4][4] = {};
    const float* Xp = X + (size_t)(row0 + lr) * K + kstart + lc;
    const float* Wp = W + (size_t)(col0 + lr) * K + kstart + lc;
    for (int k0 = 0; k0 < kchunk; k0 += 16) {
        float4 xv = *(const float4*)(Xp + k0);
        float4 wv = *(const float4*)(Wp + k0);
        Xs[lc + 0][lr] = xv.x; Xs[lc + 1][lr] = xv.y;
        Xs[lc + 2][lr] = xv.z; Xs[lc + 3][lr] = xv.w;
        Ws[lc + 0][lr] = wv.x; Ws[lc + 1][lr] = wv.y;
        Ws[lc + 2][lr] = wv.z; Ws[lc + 3][lr] = wv.w;
        __syncthreads();
#pragma unroll
        for (int kk = 0; kk < 16; kk++) {
            float4 a = *(const float4*)&Xs[kk][ty * 4];
            float4 b = *(const float4*)&Ws[kk][tx * 4];
            float av[4] = {a.x, a.y, a.z, a.w};
            float bv[4] = {b.x, b.y, b.z, b.w};
#pragma unroll
            for (int i = 0; i < 4; i++)
#pragma unroll
                for (int j = 0; j < 4; j++) acc[i][j] += av[i] * bv[j];
        }
        __syncthreads();
    }
#pragma unroll
    for (int i = 0; i < 4; i++) {
        int r = row0 + ty * 4 + i;
#pragma unroll
        for (int j = 0; j < 4; j++) {
            int c = col0 + tx * 4 + j;
            atomicAdd(&C[(size_t)r * Nc + c], acc[i][j]);
        }
    }
}

__global__ void init_y_kernel(const float* __restrict__ b_out, float* __restrict__ y)
{
    int i = blockIdx.x * blockDim.x + threadIdx.x;
    y[i] = b_out[i & (OUTD - 1)];
}

// ---------------- fused attention: one block per (seq, head) ---------------
__global__ void attn_kernel(const float* __restrict__ qkv, float* __restrict__ out)
{
    int s  = blockIdx.x >> 2;
    int hh = blockIdx.x & 3;
    int t = threadIdx.x, warp = t >> 5, lane = t & 31;
    __shared__ float qs[NT][33];
    __shared__ float ks[NT][33];
    __shared__ float ps[4][NT];
    const float* base = qkv + (size_t)s * NT * 384;
    for (int idx = t; idx < NT * HDH; idx += 128) {
        int n = idx >> 5, d = idx & 31;
        qs[n][d] = base[(size_t)n * 384 + hh * HDH + d];
        ks[n][d] = base[(size_t)n * 384 + 128 + hh * HDH + d];
    }
    __syncthreads();
    const float scale = 0.17677669529663687f;  // 1/sqrt(32)
    const float* vb = base + 256 + hh * HDH;
    for (int q = warp; q < NT; q += 4) {
        float lg[4];
        float mx = -1e30f;
#pragma unroll
        for (int j = 0; j < 4; j++) {
            int key = lane + j * 32;
            float a = -1e30f;
            if (key < NT) {
                float acc = 0.f;
#pragma unroll
                for (int d = 0; d < HDH; d++) acc += qs[q][d] * ks[key][d];
                a = acc * scale;
            }
            lg[j] = a;
            mx = fmaxf(mx, a);
        }
#pragma unroll
        for (int o = 16; o; o >>= 1) mx = fmaxf(mx, __shfl_xor_sync(0xffffffffu, mx, o));
        float sum = 0.f;
#pragma unroll
        for (int j = 0; j < 4; j++) {
            int key = lane + j * 32;
            float e = (key < NT) ? __expf(lg[j] - mx) : 0.f;
            lg[j] = e;
            sum += e;
        }
#pragma unroll
        for (int o = 16; o; o >>= 1) sum += __shfl_xor_sync(0xffffffffu, sum, o);
        float inv = 1.f / sum;
#pragma unroll
        for (int j = 0; j < 4; j++) {
            int key = lane + j * 32;
            if (key < NT) ps[warp][key] = lg[j] * inv;
        }
        __syncwarp();
        float o0 = 0.f;
        for (int kx = 0; kx < NT; kx++) o0 += ps[warp][kx] * vb[(size_t)kx * 384 + lane];
        out[((size_t)s * NT + q) * HDIM + hh * HDH + lane] = o0;
        __syncwarp();
    }
}

// ---------------- add-residual + LayerNorm (one row per block) -------------
__global__ void addln_kernel(const float* __restrict__ xin,
                             const float* __restrict__ res,
                             const float* __restrict__ g,
                             const float* __restrict__ b,
                             float* __restrict__ out, int C)
{
    int row = blockIdx.x, t = threadIdx.x;   // blockDim.x == C
    size_t base = (size_t)row * C;
    float v = xin[base + t];
    if (res) v += res[base + t];
    __shared__ float red[9];
    int lane = t & 31, warp = t >> 5, nw = blockDim.x >> 5;
    float s = v;
#pragma unroll
    for (int o = 16; o; o >>= 1) s += __shfl_xor_sync(0xffffffffu, s, o);
    if (lane == 0) red[warp] = s;
    __syncthreads();
    if (t == 0) { float tot = 0; for (int i = 0; i < nw; i++) tot += red[i]; red[8] = tot; }
    __syncthreads();
    float mean = red[8] / (float)C;
    float d = v - mean;
    float s2 = d * d;
#pragma unroll
    for (int o = 16; o; o >>= 1) s2 += __shfl_xor_sync(0xffffffffu, s2, o);
    __syncthreads();
    if (lane == 0) red[warp] = s2;
    __syncthreads();
    if (t == 0) { float tot = 0; for (int i = 0; i < nw; i++) tot += red[i]; red[8] = tot; }
    __syncthreads();
    float var = red[8] / (float)C;
    out[base + t] = d * rsqrtf(var + EPSV) * g[t] + b[t];
}

// ---------------- launch ---------------------------------------------------
extern "C" void kernel_launch(void* const* d_in, const int* in_sizes, int n_in,
                              void* d_out, int out_size)
{
    const float* forest = (const float*)d_in[0];
    // d_in[1] = adjacency (deterministic ternary tree; PE computed in closed form)
    const int*   perm   = (const int*)  d_in[2];
    const float* w_in   = (const float*)d_in[3];
    const float* b_in   = (const float*)d_in[4];
    const float* qkv_w  = (const float*)d_in[5];
    const float* qkv_b  = (const float*)d_in[6];
    const float* proj_w = (const float*)d_in[7];
    const float* proj_b = (const float*)d_in[8];
    const float* ff1_w  = (const float*)d_in[9];
    const float* ff1_b  = (const float*)d_in[10];
    const float* ff2_w  = (const float*)d_in[11];
    const float* ff2_b  = (const float*)d_in[12];
    const float* ln1_g  = (const float*)d_in[13];
    const float* ln1_b  = (const float*)d_in[14];
    const float* ln2_g  = (const float*)d_in[15];
    const float* ln2_b  = (const float*)d_in[16];
    const float* w_out  = (const float*)d_in[17];
    const float* b_out  = (const float*)d_in[18];
    const float* lnf_g  = (const float*)d_in[19];
    const float* lnf_b  = (const float*)d_in[20];

    float *xb, *qb, *ab, *tb, *hb, *yb;
    cudaGetSymbolAddress((void**)&xb, g_x);
    cudaGetSymbolAddress((void**)&qb, g_qkv);
    cudaGetSymbolAddress((void**)&ab, g_att);
    cudaGetSymbolAddress((void**)&tb, g_tmp);
    cudaGetSymbolAddress((void**)&hb, g_h);
    cudaGetSymbolAddress((void**)&yb, g_y);

    embed_kernel<<<MTOK, 128>>>(forest, perm, w_in, b_in, xb);

    for (int l = 0; l < 2; l++) {
        gemm_bias_kernel<<<dim3(384 / 64, MTOK / 64), 256>>>(
            xb, qkv_w + (size_t)l * 384 * 128, qkv_b + l * 384, qb, MTOK, 384, 128, 0);
        attn_kernel<<<SEQ * NHEAD, 128>>>(qb, ab);
        gemm_bias_kernel<<<dim3(2, MTOK / 64), 256>>>(
            ab, proj_w + (size_t)l * 128 * 128, proj_b + l * 128, tb, MTOK, 128, 128, 0);
        addln_kernel<<<MTOK, 128>>>(xb, tb, ln1_g + l * 128, ln1_b + l * 128, xb, 128);
        gemm_bias_kernel<<<dim3(2, MTOK / 64), 256>>>(
            xb, ff1_w + (size_t)l * 128 * 128, ff1_b + l * 128, hb, MTOK, 128, 128, 1);
        gemm_bias_kernel<<<dim3(2, MTOK / 64), 256>>>(
            hb, ff2_w + (size_t)l * 128 * 128, ff2_b + l * 128, tb, MTOK, 128, 128, 0);
        addln_kernel<<<MTOK, 128>>>(xb, tb, ln2_g + l * 128, ln2_b + l * 128, xb, 128);
    }

    init_y_kernel<<<(SEQ * OUTD) / 256, 256>>>(b_out, yb);
    gemm_splitk_kernel<<<dim3(OUTD / 64, SEQ / 64, 8), 256>>>(
        xb, w_out, yb, SEQ, OUTD, KBIG, KBIG / 8);
    addln_kernel<<<SEQ, 256>>>(yb, nullptr, lnf_g, lnf_b, (float*)d_out, 256);
}

// round 3
// speedup vs baseline: 1.1877x; 1.1877x over previous
#include <cuda_runtime.h>

#define SEQ   2048          // B*A
#define NT    121           // tokens
#define HDIM  128           // hidden
#define FIND  12            // feature in
#define NHEAD 4
#define HDH   32            // head dim
#define OUTD  256
#define MTOK  (SEQ*NT)      // 247808
#define KBIG  (NT*HDIM)     // 15488
#define SPLITK 8
#define EPSV  1e-5f

// ---------------- scratch (device globals; no allocation allowed) ----------
__device__ float g_x  [(size_t)MTOK * HDIM];
__device__ float g_qkv[(size_t)MTOK * 384];
__device__ float g_att[(size_t)MTOK * HDIM];
__device__ float g_h  [(size_t)MTOK * HDIM];
__device__ float g_py [(size_t)SPLITK * SEQ * OUTD];

// ---------------- embed: forest @ w_in^T + b_in + tree PE, then permute ----
__global__ void embed_kernel(const float* __restrict__ forest,
                             const int*   __restrict__ perm,
                             const float* __restrict__ w_in,
                             const float* __restrict__ b_in,
                             float* __restrict__ out)
{
    int tok = blockIdx.x;
    int s = tok / NT, i = tok - s * NT;
    int node = perm[i];
    int h = threadIdx.x;               // 128
    __shared__ float fs[FIND];
    const float* f = forest + ((size_t)s * NT + node) * FIND;
    if (h < FIND) fs[h] = f[h];
    __syncthreads();
    float acc = b_in[h];
#pragma unroll
    for (int k = 0; k < FIND; k++) acc += fs[k] * w_in[h * FIND + k];
    if (h < 12) {
        int mask = 0, cur = node;
        while (cur > 0) {
            int d = (cur >= 40) ? 4 : (cur >= 13) ? 3 : (cur >= 4) ? 2 : 1;
            int br = (cur - 1) % 3;
            mask |= 1 << ((d - 1) * 3 + br);
            cur = (cur - 1) / 3;
        }
        acc += (float)((mask >> h) & 1);
    }
    out[(size_t)tok * HDIM + h] = acc;
}

// ---------------- SGEMM 128x128x16, 8x8 microtile, double-buffered ---------
// C[M,Nc] = X[M,K] @ W[Nc,K]^T (+ bias) (+ relu) (+ residual & LayerNorm)
// mode 0: +bias          mode 1: +bias, relu
// mode 2: +bias +res, then row LayerNorm (requires Nc==128, gridDim.x==1)
__global__ __launch_bounds__(256, 2)
void gemm_kernel(const float* __restrict__ X, const float* __restrict__ W,
                 const float* __restrict__ bias, const float* __restrict__ res,
                 const float* __restrict__ lng, const float* __restrict__ lnb,
                 float* __restrict__ C, int M, int Nc, int K, int mode)
{
    __shared__ float Xs[2][16][132];
    __shared__ float Ws[2][16][132];
    __shared__ float red[128][17];
    __shared__ float stat[128];
    int tid = threadIdx.x;
    int tx = tid & 15, ty = tid >> 4;
    int row0 = blockIdx.y * 128, col0 = blockIdx.x * 128;
    int lr = tid >> 1, lc = (tid & 1) * 8;
    const float* Xp = X + (size_t)(row0 + lr) * K + lc;
    const float* Wp = W + (size_t)(col0 + lr) * K + lc;
    float acc[8][8] = {};

    float4 x0 = *(const float4*)(Xp);     float4 x1 = *(const float4*)(Xp + 4);
    float4 w0 = *(const float4*)(Wp);     float4 w1 = *(const float4*)(Wp + 4);
    Xs[0][lc+0][lr]=x0.x; Xs[0][lc+1][lr]=x0.y; Xs[0][lc+2][lr]=x0.z; Xs[0][lc+3][lr]=x0.w;
    Xs[0][lc+4][lr]=x1.x; Xs[0][lc+5][lr]=x1.y; Xs[0][lc+6][lr]=x1.z; Xs[0][lc+7][lr]=x1.w;
    Ws[0][lc+0][lr]=w0.x; Ws[0][lc+1][lr]=w0.y; Ws[0][lc+2][lr]=w0.z; Ws[0][lc+3][lr]=w0.w;
    Ws[0][lc+4][lr]=w1.x; Ws[0][lc+5][lr]=w1.y; Ws[0][lc+6][lr]=w1.z; Ws[0][lc+7][lr]=w1.w;
    __syncthreads();

    int buf = 0;
    for (int k0 = 16;; k0 += 16) {
        bool more = (k0 < K);
        float4 nx0, nx1, nw0, nw1;
        if (more) {
            nx0 = *(const float4*)(Xp + k0);     nx1 = *(const float4*)(Xp + k0 + 4);
            nw0 = *(const float4*)(Wp + k0);     nw1 = *(const float4*)(Wp + k0 + 4);
        }
#pragma unroll
        for (int kk = 0; kk < 16; kk++) {
            float a[8], b[8];
            *(float4*)(a)     = *(const float4*)&Xs[buf][kk][ty * 8];
            *(float4*)(a + 4) = *(const float4*)&Xs[buf][kk][ty * 8 + 4];
            *(float4*)(b)     = *(const float4*)&Ws[buf][kk][tx * 8];
            *(float4*)(b + 4) = *(const float4*)&Ws[buf][kk][tx * 8 + 4];
#pragma unroll
            for (int i = 0; i < 8; i++)
#pragma unroll
                for (int j = 0; j < 8; j++) acc[i][j] += a[i] * b[j];
        }
        if (!more) break;
        buf ^= 1;
        Xs[buf][lc+0][lr]=nx0.x; Xs[buf][lc+1][lr]=nx0.y; Xs[buf][lc+2][lr]=nx0.z; Xs[buf][lc+3][lr]=nx0.w;
        Xs[buf][lc+4][lr]=nx1.x; Xs[buf][lc+5][lr]=nx1.y; Xs[buf][lc+6][lr]=nx1.z; Xs[buf][lc+7][lr]=nx1.w;
        Ws[buf][lc+0][lr]=nw0.x; Ws[buf][lc+1][lr]=nw0.y; Ws[buf][lc+2][lr]=nw0.z; Ws[buf][lc+3][lr]=nw0.w;
        Ws[buf][lc+4][lr]=nw1.x; Ws[buf][lc+5][lr]=nw1.y; Ws[buf][lc+6][lr]=nw1.z; Ws[buf][lc+7][lr]=nw1.w;
        __syncthreads();
    }

    if (mode != 2) {
#pragma unroll
        for (int i = 0; i < 8; i++) {
            int r = row0 + ty * 8 + i;
#pragma unroll
            for (int j = 0; j < 8; j++) {
                int c = col0 + tx * 8 + j;
                float v = acc[i][j] + bias[c];
                if (mode == 1) v = fmaxf(v, 0.f);
                C[(size_t)r * Nc + c] = v;
            }
        }
        return;
    }

    // mode 2: bias + residual, then LayerNorm over the 128-wide row
#pragma unroll
    for (int i = 0; i < 8; i++) {
        int r = row0 + ty * 8 + i;
#pragma unroll
        for (int j = 0; j < 8; j++) {
            int c = tx * 8 + j;
            acc[i][j] += bias[c] + res[(size_t)r * 128 + c];
        }
    }
    __syncthreads();   // red[] reuse guard vs Xs/Ws writes (separate arrays; guard ordering)
#pragma unroll
    for (int i = 0; i < 8; i++) {
        float s = 0.f;
#pragma unroll
        for (int j = 0; j < 8; j++) s += acc[i][j];
        red[ty * 8 + i][tx] = s;
    }
    __syncthreads();
    if (tid < 128) {
        float s = 0.f;
#pragma unroll
        for (int t = 0; t < 16; t++) s += red[tid][t];
        stat[tid] = s * (1.f / 128.f);
    }
    __syncthreads();
    float mean_i[8];
#pragma unroll
    for (int i = 0; i < 8; i++) mean_i[i] = stat[ty * 8 + i];
    __syncthreads();
#pragma unroll
    for (int i = 0; i < 8; i++) {
        float s = 0.f;
#pragma unroll
        for (int j = 0; j < 8; j++) {
            float d = acc[i][j] - mean_i[i];
            s += d * d;
        }
        red[ty * 8 + i][tx] = s;
    }
    __syncthreads();
    if (tid < 128) {
        float s = 0.f;
#pragma unroll
        for (int t = 0; t < 16; t++) s += red[tid][t];
        stat[tid] = rsqrtf(s * (1.f / 128.f) + EPSV);
    }
    __syncthreads();
#pragma unroll
    for (int i = 0; i < 8; i++) {
        int r = row0 + ty * 8 + i;
        float rs = stat[ty * 8 + i];
#pragma unroll
        for (int j = 0; j < 8; j++) {
            int c = tx * 8 + j;
            C[(size_t)r * 128 + c] = (acc[i][j] - mean_i[i]) * rs * lng[c] + lnb[c];
        }
    }
}

// ---------------- split-K SGEMM partials for deep output projection --------
__global__ __launch_bounds__(256, 2)
void gemm_splitk_kernel(const float* __restrict__ X, const float* __restrict__ W,
                        float* __restrict__ P, int M, int Nc, int K, int kchunk)
{
    __shared__ float Xs[2][16][132];
    __shared__ float Ws[2][16][132];
    int tid = threadIdx.x;
    int tx = tid & 15, ty = tid >> 4;
    int row0 = blockIdx.y * 128, col0 = blockIdx.x * 128;
    int kstart = blockIdx.z * kchunk;
    int lr = tid >> 1, lc = (tid & 1) * 8;
    const float* Xp = X + (size_t)(row0 + lr) * K + kstart + lc;
    const float* Wp = W + (size_t)(col0 + lr) * K + kstart + lc;
    float acc[8][8] = {};

    float4 x0 = *(const float4*)(Xp);     float4 x1 = *(const float4*)(Xp + 4);
    float4 w0 = *(const float4*)(Wp);     float4 w1 = *(const float4*)(Wp + 4);
    Xs[0][lc+0][lr]=x0.x; Xs[0][lc+1][lr]=x0.y; Xs[0][lc+2][lr]=x0.z; Xs[0][lc+3][lr]=x0.w;
    Xs[0][lc+4][lr]=x1.x; Xs[0][lc+5][lr]=x1.y; Xs[0][lc+6][lr]=x1.z; Xs[0][lc+7][lr]=x1.w;
    Ws[0][lc+0][lr]=w0.x; Ws[0][lc+1][lr]=w0.y; Ws[0][lc+2][lr]=w0.z; Ws[0][lc+3][lr]=w0.w;
    Ws[0][lc+4][lr]=w1.x; Ws[0][lc+5][lr]=w1.y; Ws[0][lc+6][lr]=w1.z; Ws[0][lc+7][lr]=w1.w;
    __syncthreads();

    int buf = 0;
    for (int k0 = 16;; k0 += 16) {
        bool more = (k0 < kchunk);
        float4 nx0, nx1, nw0, nw1;
        if (more) {
            nx0 = *(const float4*)(Xp + k0);     nx1 = *(const float4*)(Xp + k0 + 4);
            nw0 = *(const float4*)(Wp + k0);     nw1 = *(const float4*)(Wp + k0 + 4);
        }
#pragma unroll
        for (int kk = 0; kk < 16; kk++) {
            float a[8], b[8];
            *(float4*)(a)     = *(const float4*)&Xs[buf][kk][ty * 8];
            *(float4*)(a + 4) = *(const float4*)&Xs[buf][kk][ty * 8 + 4];
            *(float4*)(b)     = *(const float4*)&Ws[buf][kk][tx * 8];
            *(float4*)(b + 4) = *(const float4*)&Ws[buf][kk][tx * 8 + 4];
#pragma unroll
            for (int i = 0; i < 8; i++)
#pragma unroll
                for (int j = 0; j < 8; j++) acc[i][j] += a[i] * b[j];
        }
        if (!more) break;
        buf ^= 1;
        Xs[buf][lc+0][lr]=nx0.x; Xs[buf][lc+1][lr]=nx0.y; Xs[buf][lc+2][lr]=nx0.z; Xs[buf][lc+3][lr]=nx0.w;
        Xs[buf][lc+4][lr]=nx1.x; Xs[buf][lc+5][lr]=nx1.y; Xs[buf][lc+6][lr]=nx1.z; Xs[buf][lc+7][lr]=nx1.w;
        Ws[buf][lc+0][lr]=nw0.x; Ws[buf][lc+1][lr]=nw0.y; Ws[buf][lc+2][lr]=nw0.z; Ws[buf][lc+3][lr]=nw0.w;
        Ws[buf][lc+4][lr]=nw1.x; Ws[buf][lc+5][lr]=nw1.y; Ws[buf][lc+6][lr]=nw1.z; Ws[buf][lc+7][lr]=nw1.w;
        __syncthreads();
    }

    float* Pp = P + (size_t)blockIdx.z * M * Nc;
#pragma unroll
    for (int i = 0; i < 8; i++) {
        int r = row0 + ty * 8 + i;
#pragma unroll
        for (int j = 0; j < 8; j++) {
            int c = col0 + tx * 8 + j;
            Pp[(size_t)r * Nc + c] = acc[i][j];
        }
    }
}

// ---------------- fused attention: one block per (seq, head) ---------------
__global__ void attn_kernel(const float* __restrict__ qkv, float* __restrict__ out)
{
    int s  = blockIdx.x >> 2;
    int hh = blockIdx.x & 3;
    int t = threadIdx.x, warp = t >> 5, lane = t & 31;
    __shared__ float qs[NT][33];
    __shared__ float ks[NT][33];
    __shared__ float vs[NT][33];
    const float* base = qkv + (size_t)s * NT * 384;
    for (int idx = t; idx < NT * HDH; idx += 128) {
        int n = idx >> 5, d = idx & 31;
        const float* bn = base + (size_t)n * 384 + hh * HDH + d;
        qs[n][d] = bn[0];
        ks[n][d] = bn[128];
        vs[n][d] = bn[256];
    }
    __syncthreads();
    const float scale = 0.17677669529663687f;  // 1/sqrt(32)
    for (int q = warp; q < NT; q += 4) {
        float lg[4];
        float mx = -1e30f;
#pragma unroll
        for (int j = 0; j < 4; j++) {
            int key = lane + j * 32;
            float a = -1e30f;
            if (key < NT) {
                float acc = 0.f;
#pragma unroll
                for (int d = 0; d < HDH; d++) acc += qs[q][d] * ks[key][d];
                a = acc * scale;
            }
            lg[j] = a;
            mx = fmaxf(mx, a);
        }
#pragma unroll
        for (int o = 16; o; o >>= 1) mx = fmaxf(mx, __shfl_xor_sync(0xffffffffu, mx, o));
        float sum = 0.f;
#pragma unroll
        for (int j = 0; j < 4; j++) {
            int key = lane + j * 32;
            float e = (key < NT) ? __expf(lg[j] - mx) : 0.f;
            lg[j] = e;
            sum += e;
        }
#pragma unroll
        for (int o = 16; o; o >>= 1) sum += __shfl_xor_sync(0xffffffffu, sum, o);
        float inv = 1.f / sum;
#pragma unroll
        for (int j = 0; j < 4; j++) lg[j] *= inv;
        float o0 = 0.f;
        for (int kx = 0; kx < NT; kx++) {
            float p = __shfl_sync(0xffffffffu, lg[kx >> 5], kx & 31);
            o0 += p * vs[kx][lane];
        }
        out[((size_t)s * NT + q) * HDIM + hh * HDH + lane] = o0;
    }
}

// ------- final: reduce split-K partials + bias + LayerNorm over 256 -------
__global__ void out_ln_kernel(const float* __restrict__ part,
                              const float* __restrict__ b_out,
                              const float* __restrict__ g,
                              const float* __restrict__ b,
                              float* __restrict__ out)
{
    int row = blockIdx.x, t = threadIdx.x;  // 256 threads
    size_t idx = (size_t)row * OUTD + t;
    float v = b_out[t];
#pragma unroll
    for (int z = 0; z < SPLITK; z++) v += part[(size_t)z * SEQ * OUTD + idx];
    __shared__ float red[9];
    int lane = t & 31, warp = t >> 5;
    float s = v;
#pragma unroll
    for (int o = 16; o; o >>= 1) s += __shfl_xor_sync(0xffffffffu, s, o);
    if (lane == 0) red[warp] = s;
    __syncthreads();
    if (t == 0) { float tot = 0; for (int i = 0; i < 8; i++) tot += red[i]; red[8] = tot; }
    __syncthreads();
    float mean = red[8] * (1.f / 256.f);
    float d = v - mean;
    float s2 = d * d;
#pragma unroll
    for (int o = 16; o; o >>= 1) s2 += __shfl_xor_sync(0xffffffffu, s2, o);
    __syncthreads();
    if (lane == 0) red[warp] = s2;
    __syncthreads();
    if (t == 0) { float tot = 0; for (int i = 0; i < 8; i++) tot += red[i]; red[8] = tot; }
    __syncthreads();
    float var = red[8] * (1.f / 256.f);
    out[idx] = d * rsqrtf(var + EPSV) * g[t] + b[t];
}

// ---------------- launch ---------------------------------------------------
extern "C" void kernel_launch(void* const* d_in, const int* in_sizes, int n_in,
                              void* d_out, int out_size)
{
    const float* forest = (const float*)d_in[0];
    const int*   perm   = (const int*)  d_in[2];
    const float* w_in   = (const float*)d_in[3];
    const float* b_in   = (const float*)d_in[4];
    const float* qkv_w  = (const float*)d_in[5];
    const float* qkv_b  = (const float*)d_in[6];
    const float* proj_w = (const float*)d_in[7];
    const float* proj_b = (const float*)d_in[8];
    const float* ff1_w  = (const float*)d_in[9];
    const float* ff1_b  = (const float*)d_in[10];
    const float* ff2_w  = (const float*)d_in[11];
    const float* ff2_b  = (const float*)d_in[12];
    const float* ln1_g  = (const float*)d_in[13];
    const float* ln1_b  = (const float*)d_in[14];
    const float* ln2_g  = (const float*)d_in[15];
    const float* ln2_b  = (const float*)d_in[16];
    const float* w_out  = (const float*)d_in[17];
    const float* b_out  = (const float*)d_in[18];
    const float* lnf_g  = (const float*)d_in[19];
    const float* lnf_b  = (const float*)d_in[20];

    float *xb, *qb, *ab, *hb, *pb;
    cudaGetSymbolAddress((void**)&xb, g_x);
    cudaGetSymbolAddress((void**)&qb, g_qkv);
    cudaGetSymbolAddress((void**)&ab, g_att);
    cudaGetSymbolAddress((void**)&hb, g_h);
    cudaGetSymbolAddress((void**)&pb, g_py);

    embed_kernel<<<MTOK, 128>>>(forest, perm, w_in, b_in, xb);

    const int GR = MTOK / 128;  // 1936
    for (int l = 0; l < 2; l++) {
        gemm_kernel<<<dim3(3, GR), 256>>>(
            xb, qkv_w + (size_t)l * 384 * 128, qkv_b + l * 384,
            nullptr, nullptr, nullptr, qb, MTOK, 384, 128, 0);
        attn_kernel<<<SEQ * NHEAD, 128>>>(qb, ab);
        gemm_kernel<<<dim3(1, GR), 256>>>(
            ab, proj_w + (size_t)l * 128 * 128, proj_b + l * 128,
            xb, ln1_g + l * 128, ln1_b + l * 128, xb, MTOK, 128, 128, 2);
        gemm_kernel<<<dim3(1, GR), 256>>>(
            xb, ff1_w + (size_t)l * 128 * 128, ff1_b + l * 128,
            nullptr, nullptr, nullptr, hb, MTOK, 128, 128, 1);
        gemm_kernel<<<dim3(1, GR), 256>>>(
            hb, ff2_w + (size_t)l * 128 * 128, ff2_b + l * 128,
            xb, ln2_g + l * 128, ln2_b + l * 128, xb, MTOK, 128, 128, 2);
    }

    gemm_splitk_kernel<<<dim3(OUTD / 128, SEQ / 128, SPLITK), 256>>>(
        xb, w_out, pb, SEQ, OUTD, KBIG, KBIG / SPLITK);
    out_ln_kernel<<<SEQ, 256>>>(pb, b_out, lnf_g, lnf_b, (float*)d_out);
}

// round 4
// speedup vs baseline: 1.5475x; 1.3029x over previous
#include <cuda_runtime.h>
#include <cstdint>

#define SEQ   2048          // B*A
#define NT    121           // tokens
#define HDIM  128           // hidden
#define FIND  12            // feature in
#define NHEAD 4
#define HDH   32            // head dim
#define OUTD  256
#define MTOK  (SEQ*NT)      // 247808
#define KBIG  (NT*HDIM)     // 15488
#define SPLITK 11
#define EPSV  1e-5f

// ---------------- scratch (device globals; no allocation allowed) ----------
__device__ float g_x  [(size_t)MTOK * HDIM];
__device__ float g_qkv[(size_t)MTOK * 384];
__device__ float g_att[(size_t)MTOK * HDIM];
__device__ float g_h  [(size_t)MTOK * HDIM];
__device__ float g_py [(size_t)SPLITK * SEQ * OUTD];

__device__ __forceinline__ float to_tf32(float x) {
    float r;
    asm("cvt.rna.tf32.f32 %0, %1;" : "=f"(r) : "f"(x));
    return r;
}

__device__ __forceinline__ void mma_tf32(float c[4], uint32_t a0, uint32_t a1,
                                         uint32_t a2, uint32_t a3,
                                         uint32_t b0, uint32_t b1) {
    asm volatile(
        "mma.sync.aligned.m16n8k8.row.col.f32.tf32.tf32.f32 "
        "{%0,%1,%2,%3},{%4,%5,%6,%7},{%8,%9},{%0,%1,%2,%3};\n"
        : "+f"(c[0]), "+f"(c[1]), "+f"(c[2]), "+f"(c[3])
        : "r"(a0), "r"(a1), "r"(a2), "r"(a3), "r"(b0), "r"(b1));
}

// ---------------- embed: forest @ w_in^T + b_in + tree PE, then permute ----
__global__ void embed_kernel(const float* __restrict__ forest,
                             const int*   __restrict__ perm,
                             const float* __restrict__ w_in,
                             const float* __restrict__ b_in,
                             float* __restrict__ out)
{
    int tok = blockIdx.x;
    int s = tok / NT, i = tok - s * NT;
    int node = perm[i];
    int h = threadIdx.x;               // 128
    __shared__ float fs[FIND];
    const float* f = forest + ((size_t)s * NT + node) * FIND;
    if (h < FIND) fs[h] = f[h];
    __syncthreads();
    float acc = b_in[h];
#pragma unroll
    for (int k = 0; k < FIND; k++) acc += fs[k] * w_in[h * FIND + k];
    if (h < 12) {
        int mask = 0, cur = node;
        while (cur > 0) {
            int d = (cur >= 40) ? 4 : (cur >= 13) ? 3 : (cur >= 4) ? 2 : 1;
            int br = (cur - 1) % 3;
            mask |= 1 << ((d - 1) * 3 + br);
            cur = (cur - 1) / 3;
        }
        acc += (float)((mask >> h) & 1);
    }
    out[(size_t)tok * HDIM + h] = acc;
}

// ============ TF32 tensor-core GEMM: C = X[M,K] @ W[Nc,K]^T + epilogue =====
// CTA 128x128, BK=16 double-buffered, 8 warps (64x32 warp tiles).
// mode 0: +bias    mode 1: +bias,relu    mode 2: +bias+res, LayerNorm (Nc=128)
// mode 3: raw partial store to C (split-K; bias/res unused)
struct EpiSmem { float red[128][17]; float stat[128]; };
struct MmSmem  { float As[2][128][20]; float Bs[2][128][20]; };

__global__ __launch_bounds__(256, 2)
void gemm_tf32_kernel(const float* __restrict__ X, const float* __restrict__ W,
                      const float* __restrict__ bias, const float* __restrict__ res,
                      const float* __restrict__ lng, const float* __restrict__ lnb,
                      float* __restrict__ C, int M, int Nc, int K,
                      int kstart, int kchunk, int mode)
{
    __shared__ union { MmSmem mm; EpiSmem ep; } sm;
    int tid = threadIdx.x;
    int lane = tid & 31, warp = tid >> 5;
    int tq = lane >> 2, tr = lane & 3;
    int warpM = warp & 1, warpN = warp >> 1;          // 2 x 4 warps
    int row0 = blockIdx.y * 128, col0 = blockIdx.x * 128;

    // global staging: each thread loads 8 floats (2x float4) per matrix/stage
    int glr = tid >> 1;                                // 0..127
    int glc = (tid & 1) * 8;                           // 0 or 8
    const float* Xp = X + (size_t)(row0 + glr) * K + kstart + glc;
    const float* Wp = W + (size_t)(col0 + glr) * K + kstart + glc;

    float acc[4][4][4] = {};

    // prologue: stage 0
    {
        float4 x0 = *(const float4*)(Xp);   float4 x1 = *(const float4*)(Xp + 4);
        float4 w0 = *(const float4*)(Wp);   float4 w1 = *(const float4*)(Wp + 4);
        float* a = &sm.mm.As[0][glr][glc];
        float* b = &sm.mm.Bs[0][glr][glc];
        a[0]=to_tf32(x0.x); a[1]=to_tf32(x0.y); a[2]=to_tf32(x0.z); a[3]=to_tf32(x0.w);
        a[4]=to_tf32(x1.x); a[5]=to_tf32(x1.y); a[6]=to_tf32(x1.z); a[7]=to_tf32(x1.w);
        b[0]=to_tf32(w0.x); b[1]=to_tf32(w0.y); b[2]=to_tf32(w0.z); b[3]=to_tf32(w0.w);
        b[4]=to_tf32(w1.x); b[5]=to_tf32(w1.y); b[6]=to_tf32(w1.z); b[7]=to_tf32(w1.w);
    }
    __syncthreads();

    int nk = kchunk >> 4;
    for (int kt = 0; kt < nk; kt++) {
        int buf = kt & 1;
        float4 x0, x1, w0, w1;
        bool more = (kt + 1 < nk);
        if (more) {
            const float* xp = Xp + (kt + 1) * 16;
            const float* wp = Wp + (kt + 1) * 16;
            x0 = *(const float4*)(xp);   x1 = *(const float4*)(xp + 4);
            w0 = *(const float4*)(wp);   w1 = *(const float4*)(wp + 4);
        }
#pragma unroll
        for (int k8 = 0; k8 < 16; k8 += 8) {
            uint32_t afrag[4][4], bfrag[4][2];
#pragma unroll
            for (int mi = 0; mi < 4; mi++) {
                int ar = warpM * 64 + mi * 16 + tq;
                afrag[mi][0] = __float_as_uint(sm.mm.As[buf][ar    ][k8 + tr    ]);
                afrag[mi][1] = __float_as_uint(sm.mm.As[buf][ar + 8][k8 + tr    ]);
                afrag[mi][2] = __float_as_uint(sm.mm.As[buf][ar    ][k8 + tr + 4]);
                afrag[mi][3] = __float_as_uint(sm.mm.As[buf][ar + 8][k8 + tr + 4]);
            }
#pragma unroll
            for (int ni = 0; ni < 4; ni++) {
                int br = warpN * 32 + ni * 8 + tq;
                bfrag[ni][0] = __float_as_uint(sm.mm.Bs[buf][br][k8 + tr    ]);
                bfrag[ni][1] = __float_as_uint(sm.mm.Bs[buf][br][k8 + tr + 4]);
            }
#pragma unroll
            for (int mi = 0; mi < 4; mi++)
#pragma unroll
                for (int ni = 0; ni < 4; ni++)
                    mma_tf32(acc[mi][ni], afrag[mi][0], afrag[mi][1],
                             afrag[mi][2], afrag[mi][3],
                             bfrag[ni][0], bfrag[ni][1]);
        }
        if (more) {
            int nb = buf ^ 1;
            float* a = &sm.mm.As[nb][glr][glc];
            float* b = &sm.mm.Bs[nb][glr][glc];
            a[0]=to_tf32(x0.x); a[1]=to_tf32(x0.y); a[2]=to_tf32(x0.z); a[3]=to_tf32(x0.w);
            a[4]=to_tf32(x1.x); a[5]=to_tf32(x1.y); a[6]=to_tf32(x1.z); a[7]=to_tf32(x1.w);
            b[0]=to_tf32(w0.x); b[1]=to_tf32(w0.y); b[2]=to_tf32(w0.z); b[3]=to_tf32(w0.w);
            b[4]=to_tf32(w1.x); b[5]=to_tf32(w1.y); b[6]=to_tf32(w1.z); b[7]=to_tf32(w1.w);
        }
        __syncthreads();
    }

    // ---------------- epilogues -------------------------------------------
    if (mode == 3) {            // raw partial (split-K)
#pragma unroll
        for (int mi = 0; mi < 4; mi++)
#pragma unroll
            for (int h = 0; h < 2; h++) {
                int r = row0 + warpM * 64 + mi * 16 + tq + 8 * h;
#pragma unroll
                for (int ni = 0; ni < 4; ni++) {
                    int c = col0 + warpN * 32 + ni * 8 + 2 * tr;
                    float2 v = make_float2(acc[mi][ni][2 * h], acc[mi][ni][2 * h + 1]);
                    *(float2*)&C[(size_t)r * Nc + c] = v;
                }
            }
        return;
    }
    if (mode != 2) {
#pragma unroll
        for (int mi = 0; mi < 4; mi++)
#pragma unroll
            for (int h = 0; h < 2; h++) {
                int r = row0 + warpM * 64 + mi * 16 + tq + 8 * h;
#pragma unroll
                for (int ni = 0; ni < 4; ni++) {
                    int c = col0 + warpN * 32 + ni * 8 + 2 * tr;
                    float v0 = acc[mi][ni][2 * h]     + bias[c];
                    float v1 = acc[mi][ni][2 * h + 1] + bias[c + 1];
                    if (mode == 1) { v0 = fmaxf(v0, 0.f); v1 = fmaxf(v1, 0.f); }
                    *(float2*)&C[(size_t)r * Nc + c] = make_float2(v0, v1);
                }
            }
        return;
    }

    // mode 2: bias + residual + LayerNorm over 128-wide rows (col0 == 0)
#pragma unroll
    for (int mi = 0; mi < 4; mi++)
#pragma unroll
        for (int h = 0; h < 2; h++) {
            int r = row0 + warpM * 64 + mi * 16 + tq + 8 * h;
#pragma unroll
            for (int ni = 0; ni < 4; ni++) {
                int c = warpN * 32 + ni * 8 + 2 * tr;
                float2 rv = *(const float2*)&res[(size_t)r * 128 + c];
                acc[mi][ni][2 * h]     += bias[c]     + rv.x;
                acc[mi][ni][2 * h + 1] += bias[c + 1] + rv.y;
            }
        }
    int cid = warpN * 4 + tr;      // 16 column-contributors per row
#pragma unroll
    for (int mi = 0; mi < 4; mi++)
#pragma unroll
        for (int h = 0; h < 2; h++) {
            int rl = warpM * 64 + mi * 16 + tq + 8 * h;
            float s = 0.f;
#pragma unroll
            for (int ni = 0; ni < 4; ni++) s += acc[mi][ni][2 * h] + acc[mi][ni][2 * h + 1];
            sm.ep.red[rl][cid] = s;
        }
    __syncthreads();
    if (tid < 128) {
        float s = 0.f;
#pragma unroll
        for (int t = 0; t < 16; t++) s += sm.ep.red[tid][t];
        sm.ep.stat[tid] = s * (1.f / 128.f);
    }
    __syncthreads();
    float mean[4][2];
#pragma unroll
    for (int mi = 0; mi < 4; mi++)
#pragma unroll
        for (int h = 0; h < 2; h++)
            mean[mi][h] = sm.ep.stat[warpM * 64 + mi * 16 + tq + 8 * h];
    __syncthreads();
#pragma unroll
    for (int mi = 0; mi < 4; mi++)
#pragma unroll
        for (int h = 0; h < 2; h++) {
            int rl = warpM * 64 + mi * 16 + tq + 8 * h;
            float s = 0.f;
#pragma unroll
            for (int ni = 0; ni < 4; ni++) {
                float d0 = acc[mi][ni][2 * h]     - mean[mi][h];
                float d1 = acc[mi][ni][2 * h + 1] - mean[mi][h];
                s += d0 * d0 + d1 * d1;
            }
            sm.ep.red[rl][cid] = s;
        }
    __syncthreads();
    if (tid < 128) {
        float s = 0.f;
#pragma unroll
        for (int t = 0; t < 16; t++) s += sm.ep.red[tid][t];
        sm.ep.stat[tid] = rsqrtf(s * (1.f / 128.f) + EPSV);
    }
    __syncthreads();
#pragma unroll
    for (int mi = 0; mi < 4; mi++)
#pragma unroll
        for (int h = 0; h < 2; h++) {
            int rl = warpM * 64 + mi * 16 + tq + 8 * h;
            int r = row0 + rl;
            float rs = sm.ep.stat[rl];
#pragma unroll
            for (int ni = 0; ni < 4; ni++) {
                int c = warpN * 32 + ni * 8 + 2 * tr;
                float v0 = (acc[mi][ni][2 * h]     - mean[mi][h]) * rs * lng[c]     + lnb[c];
                float v1 = (acc[mi][ni][2 * h + 1] - mean[mi][h]) * rs * lng[c + 1] + lnb[c + 1];
                *(float2*)&C[(size_t)r * 128 + c] = make_float2(v0, v1);
            }
        }
}

// ---------------- fused attention: one block per (seq, head) ---------------
__global__ void attn_kernel(const float* __restrict__ qkv, float* __restrict__ out)
{
    int s  = blockIdx.x >> 2;
    int hh = blockIdx.x & 3;
    int t = threadIdx.x, warp = t >> 5, lane = t & 31;
    __shared__ float qs[NT][33];
    __shared__ float ks[NT][33];
    __shared__ float vs[NT][33];
    const float* base = qkv + (size_t)s * NT * 384;
    for (int idx = t; idx < NT * HDH; idx += 128) {
        int n = idx >> 5, d = idx & 31;
        const float* bn = base + (size_t)n * 384 + hh * HDH + d;
        qs[n][d] = bn[0];
        ks[n][d] = bn[128];
        vs[n][d] = bn[256];
    }
    __syncthreads();
    const float scale = 0.17677669529663687f;  // 1/sqrt(32)
    for (int q = warp; q < NT; q += 4) {
        float lg[4];
        float mx = -1e30f;
#pragma unroll
        for (int j = 0; j < 4; j++) {
            int key = lane + j * 32;
            float a = -1e30f;
            if (key < NT) {
                float acc = 0.f;
#pragma unroll
                for (int d = 0; d < HDH; d++) acc += qs[q][d] * ks[key][d];
                a = acc * scale;
            }
            lg[j] = a;
            mx = fmaxf(mx, a);
        }
#pragma unroll
        for (int o = 16; o; o >>= 1) mx = fmaxf(mx, __shfl_xor_sync(0xffffffffu, mx, o));
        float sum = 0.f;
#pragma unroll
        for (int j = 0; j < 4; j++) {
            int key = lane + j * 32;
            float e = (key < NT) ? __expf(lg[j] - mx) : 0.f;
            lg[j] = e;
            sum += e;
        }
#pragma unroll
        for (int o = 16; o; o >>= 1) sum += __shfl_xor_sync(0xffffffffu, sum, o);
        float inv = 1.f / sum;
#pragma unroll
        for (int j = 0; j < 4; j++) lg[j] *= inv;
        float o0 = 0.f;
        for (int kx = 0; kx < NT; kx++) {
            float p = __shfl_sync(0xffffffffu, lg[kx >> 5], kx & 31);
            o0 += p * vs[kx][lane];
        }
        out[((size_t)s * NT + q) * HDIM + hh * HDH + lane] = o0;
    }
}

// ------- final: reduce split-K partials + bias + LayerNorm over 256 -------
__global__ void out_ln_kernel(const float* __restrict__ part,
                              const float* __restrict__ b_out,
                              const float* __restrict__ g,
                              const float* __restrict__ b,
                              float* __restrict__ out)
{
    int row = blockIdx.x, t = threadIdx.x;  // 256 threads
    size_t idx = (size_t)row * OUTD + t;
    float v = b_out[t];
#pragma unroll
    for (int z = 0; z < SPLITK; z++) v += part[(size_t)z * SEQ * OUTD + idx];
    __shared__ float red[9];
    int lane = t & 31, warp = t >> 5;
    float s = v;
#pragma unroll
    for (int o = 16; o; o >>= 1) s += __shfl_xor_sync(0xffffffffu, s, o);
    if (lane == 0) red[warp] = s;
    __syncthreads();
    if (t == 0) { float tot = 0; for (int i = 0; i < 8; i++) tot += red[i]; red[8] = tot; }
    __syncthreads();
    float mean = red[8] * (1.f / 256.f);
    float d = v - mean;
    float s2 = d * d;
#pragma unroll
    for (int o = 16; o; o >>= 1) s2 += __shfl_xor_sync(0xffffffffu, s2, o);
    __syncthreads();
    if (lane == 0) red[warp] = s2;
    __syncthreads();
    if (t == 0) { float tot = 0; for (int i = 0; i < 8; i++) tot += red[i]; red[8] = tot; }
    __syncthreads();
    float var = red[8] * (1.f / 256.f);
    out[idx] = d * rsqrtf(var + EPSV) * g[t] + b[t];
}

// ---------------- launch ---------------------------------------------------
extern "C" void kernel_launch(void* const* d_in, const int* in_sizes, int n_in,
                              void* d_out, int out_size)
{
    const float* forest = (const float*)d_in[0];
    const int*   perm   = (const int*)  d_in[2];
    const float* w_in   = (const float*)d_in[3];
    const float* b_in   = (const float*)d_in[4];
    const float* qkv_w  = (const float*)d_in[5];
    const float* qkv_b  = (const float*)d_in[6];
    const float* proj_w = (const float*)d_in[7];
    const float* proj_b = (const float*)d_in[8];
    const float* ff1_w  = (const float*)d_in[9];
    const float* ff1_b  = (const float*)d_in[10];
    const float* ff2_w  = (const float*)d_in[11];
    const float* ff2_b  = (const float*)d_in[12];
    const float* ln1_g  = (const float*)d_in[13];
    const float* ln1_b  = (const float*)d_in[14];
    const float* ln2_g  = (const float*)d_in[15];
    const float* ln2_b  = (const float*)d_in[16];
    const float* w_out  = (const float*)d_in[17];
    const float* b_out  = (const float*)d_in[18];
    const float* lnf_g  = (const float*)d_in[19];
    const float* lnf_b  = (const float*)d_in[20];

    float *xb, *qb, *ab, *hb, *pb;
    cudaGetSymbolAddress((void**)&xb, g_x);
    cudaGetSymbolAddress((void**)&qb, g_qkv);
    cudaGetSymbolAddress((void**)&ab, g_att);
    cudaGetSymbolAddress((void**)&hb, g_h);
    cudaGetSymbolAddress((void**)&pb, g_py);

    embed_kernel<<<MTOK, 128>>>(forest, perm, w_in, b_in, xb);

    const int GR = MTOK / 128;  // 1936
    for (int l = 0; l < 2; l++) {
        gemm_tf32_kernel<<<dim3(3, GR), 256>>>(
            xb, qkv_w + (size_t)l * 384 * 128, qkv_b + l * 384,
            nullptr, nullptr, nullptr, qb, MTOK, 384, 128, 0, 128, 0);
        attn_kernel<<<SEQ * NHEAD, 128>>>(qb, ab);
        gemm_tf32_kernel<<<dim3(1, GR), 256>>>(
            ab, proj_w + (size_t)l * 128 * 128, proj_b + l * 128,
            xb, ln1_g + l * 128, ln1_b + l * 128, xb, MTOK, 128, 128, 0, 128, 2);
        gemm_tf32_kernel<<<dim3(1, GR), 256>>>(
            xb, ff1_w + (size_t)l * 128 * 128, ff1_b + l * 128,
            nullptr, nullptr, nullptr, hb, MTOK, 128, 128, 0, 128, 1);
        gemm_tf32_kernel<<<dim3(1, GR), 256>>>(
            hb, ff2_w + (size_t)l * 128 * 128, ff2_b + l * 128,
            xb, ln2_g + l * 128, ln2_b + l * 128, xb, MTOK, 128, 128, 0, 128, 2);
    }

    // output projection, split-K = 11 (15488 = 11 * 1408)
    for (int z = 0; z < SPLITK; z++) {
        gemm_tf32_kernel<<<dim3(OUTD / 128, SEQ / 128), 256>>>(
            xb, w_out, nullptr, nullptr, nullptr, nullptr,
            pb + (size_t)z * SEQ * OUTD, SEQ, OUTD, KBIG,
            z * (KBIG / SPLITK), KBIG / SPLITK, 3);
    }
    out_ln_kernel<<<SEQ, 256>>>(pb, b_out, lnf_g, lnf_b, (float*)d_out);
}

// round 5
// speedup vs baseline: 1.8553x; 1.1989x over previous
#include <cuda_runtime.h>
#include <cstdint>

#define SEQ   2048          // B*A
#define NT    121           // tokens
#define HDIM  128           // hidden
#define FIND  12            // feature in
#define NHEAD 4
#define HDH   32            // head dim
#define OUTD  256
#define MTOK  (SEQ*NT)      // 247808
#define KBIG  (NT*HDIM)     // 15488
#define SPLITK 11
#define NSTG  4
#define EPSV  1e-5f

// ---------------- scratch (device globals; no allocation allowed) ----------
__device__ float g_x  [(size_t)MTOK * HDIM];
__device__ float g_qkv[(size_t)MTOK * 384];
__device__ float g_att[(size_t)MTOK * HDIM];
__device__ float g_h  [(size_t)MTOK * HDIM];
__device__ float g_py [(size_t)SPLITK * SEQ * OUTD];

__device__ __forceinline__ void cpasync16(uint32_t dst, const float* src) {
    asm volatile("cp.async.cg.shared.global [%0], [%1], 16;" :: "r"(dst), "l"(src));
}

__device__ __forceinline__ void mma_tf32(float c[4], uint32_t a0, uint32_t a1,
                                         uint32_t a2, uint32_t a3,
                                         uint32_t b0, uint32_t b1) {
    asm volatile(
        "mma.sync.aligned.m16n8k8.row.col.f32.tf32.tf32.f32 "
        "{%0,%1,%2,%3},{%4,%5,%6,%7},{%8,%9},{%0,%1,%2,%3};\n"
        : "+f"(c[0]), "+f"(c[1]), "+f"(c[2]), "+f"(c[3])
        : "r"(a0), "r"(a1), "r"(a2), "r"(a3), "r"(b0), "r"(b1));
}

// ---------------- embed: forest @ w_in^T + b_in + tree PE, then permute ----
__global__ void embed_kernel(const float* __restrict__ forest,
                             const int*   __restrict__ perm,
                             const float* __restrict__ w_in,
                             const float* __restrict__ b_in,
                             float* __restrict__ out)
{
    int tok = blockIdx.x;
    int s = tok / NT, i = tok - s * NT;
    int node = perm[i];
    int h = threadIdx.x;               // 128
    __shared__ float fs[FIND];
    const float* f = forest + ((size_t)s * NT + node) * FIND;
    if (h < FIND) fs[h] = f[h];
    __syncthreads();
    float acc = b_in[h];
#pragma unroll
    for (int k = 0; k < FIND; k++) acc += fs[k] * w_in[h * FIND + k];
    if (h < 12) {
        int mask = 0, cur = node;
        while (cur > 0) {
            int d = (cur >= 40) ? 4 : (cur >= 13) ? 3 : (cur >= 4) ? 2 : 1;
            int br = (cur - 1) % 3;
            mask |= 1 << ((d - 1) * 3 + br);
            cur = (cur - 1) / 3;
        }
        acc += (float)((mask >> h) & 1);
    }
    out[(size_t)tok * HDIM + h] = acc;
}

// ============ TF32 tensor-core GEMM: C = X[M,K] @ W[Nc,K]^T + epilogue =====
// CTA 128x128, BK=8 x 4-stage cp.async pipeline, 8 warps (64x32 warp tiles).
// mode 0: +bias    mode 1: +bias,relu    mode 2: +bias+res, LayerNorm (Nc=128)
// mode 3: raw partial store (split-K over blockIdx.z; kstart = z*kchunk)
struct EpiSmem { float red[128][17]; float stat[128]; };
struct MmSmem  { float As[NSTG][128][12]; float Bs[NSTG][128][12]; };

__global__ __launch_bounds__(256, 2)
void gemm_tf32_kernel(const float* __restrict__ X, const float* __restrict__ W,
                      const float* __restrict__ bias, const float* __restrict__ res,
                      const float* __restrict__ lng, const float* __restrict__ lnb,
                      float* __restrict__ C, int M, int Nc, int K,
                      int kchunk, int mode)
{
    __shared__ union { MmSmem mm; EpiSmem ep; } sm;
    int tid = threadIdx.x;
    int lane = tid & 31, warp = tid >> 5;
    int tq = lane >> 2, tr = lane & 3;
    int warpM = warp & 1, warpN = warp >> 1;          // 2 x 4 warps
    int row0 = blockIdx.y * 128, col0 = blockIdx.x * 128;
    int kstart = blockIdx.z * kchunk;
    if (mode == 3) C += (size_t)blockIdx.z * M * Nc;

    int glr = tid >> 1;                 // row 0..127
    int glc = (tid & 1) * 4;            // float offset 0 or 4 (16 B)
    const float* Xp = X + (size_t)(row0 + glr) * K + kstart + glc;
    const float* Wp = W + (size_t)(col0 + glr) * K + kstart + glc;
    uint32_t sa = (uint32_t)__cvta_generic_to_shared(&sm.mm.As[0][glr][glc]);
    uint32_t sb = (uint32_t)__cvta_generic_to_shared(&sm.mm.Bs[0][glr][glc]);
    const uint32_t STGB = 128 * 12 * 4;  // 6144 B per stage

    int nk8 = kchunk >> 3;

#pragma unroll
    for (int s = 0; s < NSTG - 1; s++) {
        if (s < nk8) {
            cpasync16(sa + s * STGB, Xp + s * 8);
            cpasync16(sb + s * STGB, Wp + s * 8);
        }
        asm volatile("cp.async.commit_group;");
    }

    float acc[4][4][4] = {};
    for (int kt = 0; kt < nk8; kt++) {
        asm volatile("cp.async.wait_group %0;" :: "n"(NSTG - 2));
        __syncthreads();
        int snext = kt + NSTG - 1;
        if (snext < nk8) {
            uint32_t so = (uint32_t)(snext & (NSTG - 1)) * STGB;
            cpasync16(sa + so, Xp + snext * 8);
            cpasync16(sb + so, Wp + snext * 8);
        }
        asm volatile("cp.async.commit_group;");

        int b = kt & (NSTG - 1);
        uint32_t afrag[4][4], bfrag[4][2];
#pragma unroll
        for (int mi = 0; mi < 4; mi++) {
            int ar = warpM * 64 + mi * 16 + tq;
            afrag[mi][0] = __float_as_uint(sm.mm.As[b][ar    ][tr    ]);
            afrag[mi][1] = __float_as_uint(sm.mm.As[b][ar + 8][tr    ]);
            afrag[mi][2] = __float_as_uint(sm.mm.As[b][ar    ][tr + 4]);
            afrag[mi][3] = __float_as_uint(sm.mm.As[b][ar + 8][tr + 4]);
        }
#pragma unroll
        for (int ni = 0; ni < 4; ni++) {
            int br = warpN * 32 + ni * 8 + tq;
            bfrag[ni][0] = __float_as_uint(sm.mm.Bs[b][br][tr    ]);
            bfrag[ni][1] = __float_as_uint(sm.mm.Bs[b][br][tr + 4]);
        }
#pragma unroll
        for (int mi = 0; mi < 4; mi++)
#pragma unroll
            for (int ni = 0; ni < 4; ni++)
                mma_tf32(acc[mi][ni], afrag[mi][0], afrag[mi][1],
                         afrag[mi][2], afrag[mi][3],
                         bfrag[ni][0], bfrag[ni][1]);
    }

    // ---------------- epilogues -------------------------------------------
    if (mode == 3) {            // raw partial (split-K)
#pragma unroll
        for (int mi = 0; mi < 4; mi++)
#pragma unroll
            for (int h = 0; h < 2; h++) {
                int r = row0 + warpM * 64 + mi * 16 + tq + 8 * h;
#pragma unroll
                for (int ni = 0; ni < 4; ni++) {
                    int c = col0 + warpN * 32 + ni * 8 + 2 * tr;
                    *(float2*)&C[(size_t)r * Nc + c] =
                        make_float2(acc[mi][ni][2 * h], acc[mi][ni][2 * h + 1]);
                }
            }
        return;
    }
    if (mode != 2) {
#pragma unroll
        for (int mi = 0; mi < 4; mi++)
#pragma unroll
            for (int h = 0; h < 2; h++) {
                int r = row0 + warpM * 64 + mi * 16 + tq + 8 * h;
#pragma unroll
                for (int ni = 0; ni < 4; ni++) {
                    int c = col0 + warpN * 32 + ni * 8 + 2 * tr;
                    float v0 = acc[mi][ni][2 * h]     + bias[c];
                    float v1 = acc[mi][ni][2 * h + 1] + bias[c + 1];
                    if (mode == 1) { v0 = fmaxf(v0, 0.f); v1 = fmaxf(v1, 0.f); }
                    *(float2*)&C[(size_t)r * Nc + c] = make_float2(v0, v1);
                }
            }
        return;
    }

    // mode 2: bias + residual + LayerNorm over 128-wide rows (col0 == 0)
#pragma unroll
    for (int mi = 0; mi < 4; mi++)
#pragma unroll
        for (int h = 0; h < 2; h++) {
            int r = row0 + warpM * 64 + mi * 16 + tq + 8 * h;
#pragma unroll
            for (int ni = 0; ni < 4; ni++) {
                int c = warpN * 32 + ni * 8 + 2 * tr;
                float2 rv = *(const float2*)&res[(size_t)r * 128 + c];
                acc[mi][ni][2 * h]     += bias[c]     + rv.x;
                acc[mi][ni][2 * h + 1] += bias[c + 1] + rv.y;
            }
        }
    __syncthreads();   // all warps done with sm.mm before reusing as sm.ep
    int cid = warpN * 4 + tr;      // 16 column-contributors per row
#pragma unroll
    for (int mi = 0; mi < 4; mi++)
#pragma unroll
        for (int h = 0; h < 2; h++) {
            int rl = warpM * 64 + mi * 16 + tq + 8 * h;
            float s = 0.f;
#pragma unroll
            for (int ni = 0; ni < 4; ni++) s += acc[mi][ni][2 * h] + acc[mi][ni][2 * h + 1];
            sm.ep.red[rl][cid] = s;
        }
    __syncthreads();
    if (tid < 128) {
        float s = 0.f;
#pragma unroll
        for (int t = 0; t < 16; t++) s += sm.ep.red[tid][t];
        sm.ep.stat[tid] = s * (1.f / 128.f);
    }
    __syncthreads();
    float mean[4][2];
#pragma unroll
    for (int mi = 0; mi < 4; mi++)
#pragma unroll
        for (int h = 0; h < 2; h++)
            mean[mi][h] = sm.ep.stat[warpM * 64 + mi * 16 + tq + 8 * h];
    __syncthreads();
#pragma unroll
    for (int mi = 0; mi < 4; mi++)
#pragma unroll
        for (int h = 0; h < 2; h++) {
            int rl = warpM * 64 + mi * 16 + tq + 8 * h;
            float s = 0.f;
#pragma unroll
            for (int ni = 0; ni < 4; ni++) {
                float d0 = acc[mi][ni][2 * h]     - mean[mi][h];
                float d1 = acc[mi][ni][2 * h + 1] - mean[mi][h];
                s += d0 * d0 + d1 * d1;
            }
            sm.ep.red[rl][cid] = s;
        }
    __syncthreads();
    if (tid < 128) {
        float s = 0.f;
#pragma unroll
        for (int t = 0; t < 16; t++) s += sm.ep.red[tid][t];
        sm.ep.stat[tid] = rsqrtf(s * (1.f / 128.f) + EPSV);
    }
    __syncthreads();
#pragma unroll
    for (int mi = 0; mi < 4; mi++)
#pragma unroll
        for (int h = 0; h < 2; h++) {
            int rl = warpM * 64 + mi * 16 + tq + 8 * h;
            int r = row0 + rl;
            float rs = sm.ep.stat[rl];
#pragma unroll
            for (int ni = 0; ni < 4; ni++) {
                int c = warpN * 32 + ni * 8 + 2 * tr;
                float v0 = (acc[mi][ni][2 * h]     - mean[mi][h]) * rs * lng[c]     + lnb[c];
                float v1 = (acc[mi][ni][2 * h + 1] - mean[mi][h]) * rs * lng[c + 1] + lnb[c + 1];
                *(float2*)&C[(size_t)r * 128 + c] = make_float2(v0, v1);
            }
        }
}

// ---------------- fused attention: one block per (seq, head) ---------------
__global__ void attn_kernel(const float* __restrict__ qkv, float* __restrict__ out)
{
    int s  = blockIdx.x >> 2;
    int hh = blockIdx.x & 3;
    int t = threadIdx.x, warp = t >> 5, lane = t & 31;
    __shared__ float qs[NT][33];
    __shared__ float ks[NT][33];
    __shared__ float vs[NT][33];
    const float* base = qkv + (size_t)s * NT * 384;
    for (int idx = t; idx < NT * HDH; idx += 128) {
        int n = idx >> 5, d = idx & 31;
        const float* bn = base + (size_t)n * 384 + hh * HDH + d;
        qs[n][d] = bn[0];
        ks[n][d] = bn[128];
        vs[n][d] = bn[256];
    }
    __syncthreads();
    const float scale = 0.17677669529663687f;  // 1/sqrt(32)
    for (int q = warp; q < NT; q += 4) {
        float lg[4];
        float mx = -1e30f;
#pragma unroll
        for (int j = 0; j < 4; j++) {
            int key = lane + j * 32;
            float a = -1e30f;
            if (key < NT) {
                float acc = 0.f;
#pragma unroll
                for (int d = 0; d < HDH; d++) acc += qs[q][d] * ks[key][d];
                a = acc * scale;
            }
            lg[j] = a;
            mx = fmaxf(mx, a);
        }
#pragma unroll
        for (int o = 16; o; o >>= 1) mx = fmaxf(mx, __shfl_xor_sync(0xffffffffu, mx, o));
        float sum = 0.f;
#pragma unroll
        for (int j = 0; j < 4; j++) {
            int key = lane + j * 32;
            float e = (key < NT) ? __expf(lg[j] - mx) : 0.f;
            lg[j] = e;
            sum += e;
        }
#pragma unroll
        for (int o = 16; o; o >>= 1) sum += __shfl_xor_sync(0xffffffffu, sum, o);
        float inv = 1.f / sum;
#pragma unroll
        for (int j = 0; j < 4; j++) lg[j] *= inv;
        float o0 = 0.f;
        for (int kx = 0; kx < NT; kx++) {
            float p = __shfl_sync(0xffffffffu, lg[kx >> 5], kx & 31);
            o0 += p * vs[kx][lane];
        }
        out[((size_t)s * NT + q) * HDIM + hh * HDH + lane] = o0;
    }
}

// ------- final: reduce split-K partials + bias + LayerNorm over 256 -------
__global__ void out_ln_kernel(const float* __restrict__ part,
                              const float* __restrict__ b_out,
                              const float* __restrict__ g,
                              const float* __restrict__ b,
                              float* __restrict__ out)
{
    int row = blockIdx.x, t = threadIdx.x;  // 256 threads
    size_t idx = (size_t)row * OUTD + t;
    float v = b_out[t];
#pragma unroll
    for (int z = 0; z < SPLITK; z++) v += part[(size_t)z * SEQ * OUTD + idx];
    __shared__ float red[9];
    int lane = t & 31, warp = t >> 5;
    float s = v;
#pragma unroll
    for (int o = 16; o; o >>= 1) s += __shfl_xor_sync(0xffffffffu, s, o);
    if (lane == 0) red[warp] = s;
    __syncthreads();
    if (t == 0) { float tot = 0; for (int i = 0; i < 8; i++) tot += red[i]; red[8] = tot; }
    __syncthreads();
    float mean = red[8] * (1.f / 256.f);
    float d = v - mean;
    float s2 = d * d;
#pragma unroll
    for (int o = 16; o; o >>= 1) s2 += __shfl_xor_sync(0xffffffffu, s2, o);
    __syncthreads();
    if (lane == 0) red[warp] = s2;
    __syncthreads();
    if (t == 0) { float tot = 0; for (int i = 0; i < 8; i++) tot += red[i]; red[8] = tot; }
    __syncthreads();
    float var = red[8] * (1.f / 256.f);
    out[idx] = d * rsqrtf(var + EPSV) * g[t] + b[t];
}

// ---------------- launch ---------------------------------------------------
extern "C" void kernel_launch(void* const* d_in, const int* in_sizes, int n_in,
                              void* d_out, int out_size)
{
    const float* forest = (const float*)d_in[0];
    const int*   perm   = (const int*)  d_in[2];
    const float* w_in   = (const float*)d_in[3];
    const float* b_in   = (const float*)d_in[4];
    const float* qkv_w  = (const float*)d_in[5];
    const float* qkv_b  = (const float*)d_in[6];
    const float* proj_w = (const float*)d_in[7];
    const float* proj_b = (const float*)d_in[8];
    const float* ff1_w  = (const float*)d_in[9];
    const float* ff1_b  = (const float*)d_in[10];
    const float* ff2_w  = (const float*)d_in[11];
    const float* ff2_b  = (const float*)d_in[12];
    const float* ln1_g  = (const float*)d_in[13];
    const float* ln1_b  = (const float*)d_in[14];
    const float* ln2_g  = (const float*)d_in[15];
    const float* ln2_b  = (const float*)d_in[16];
    const float* w_out  = (const float*)d_in[17];
    const float* b_out  = (const float*)d_in[18];
    const float* lnf_g  = (const float*)d_in[19];
    const float* lnf_b  = (const float*)d_in[20];

    float *xb, *qb, *ab, *hb, *pb;
    cudaGetSymbolAddress((void**)&xb, g_x);
    cudaGetSymbolAddress((void**)&qb, g_qkv);
    cudaGetSymbolAddress((void**)&ab, g_att);
    cudaGetSymbolAddress((void**)&hb, g_h);
    cudaGetSymbolAddress((void**)&pb, g_py);

    embed_kernel<<<MTOK, 128>>>(forest, perm, w_in, b_in, xb);

    const int GR = MTOK / 128;  // 1936
    for (int l = 0; l < 2; l++) {
        gemm_tf32_kernel<<<dim3(3, GR), 256>>>(
            xb, qkv_w + (size_t)l * 384 * 128, qkv_b + l * 384,
            nullptr, nullptr, nullptr, qb, MTOK, 384, 128, 128, 0);
        attn_kernel<<<SEQ * NHEAD, 128>>>(qb, ab);
        gemm_tf32_kernel<<<dim3(1, GR), 256>>>(
            ab, proj_w + (size_t)l * 128 * 128, proj_b + l * 128,
            xb, ln1_g + l * 128, ln1_b + l * 128, xb, MTOK, 128, 128, 128, 2);
        gemm_tf32_kernel<<<dim3(1, GR), 256>>>(
            xb, ff1_w + (size_t)l * 128 * 128, ff1_b + l * 128,
            nullptr, nullptr, nullptr, hb, MTOK, 128, 128, 128, 1);
        gemm_tf32_kernel<<<dim3(1, GR), 256>>>(
            hb, ff2_w + (size_t)l * 128 * 128, ff2_b + l * 128,
            xb, ln2_g + l * 128, ln2_b + l * 128, xb, MTOK, 128, 128, 128, 2);
    }

    // output projection: split-K = 11 in one launch (15488 = 11 * 1408)
    gemm_tf32_kernel<<<dim3(OUTD / 128, SEQ / 128, SPLITK), 256>>>(
        xb, w_out, nullptr, nullptr, nullptr, nullptr,
        pb, SEQ, OUTD, KBIG, KBIG / SPLITK, 3);
    out_ln_kernel<<<SEQ, 256>>>(pb, b_out, lnf_g, lnf_b, (float*)d_out);
}

// round 6
// speedup vs baseline: 2.0094x; 1.0831x over previous
#include <cuda_runtime.h>
#include <cstdint>

#define SEQ   2048          // B*A
#define NT    121           // tokens
#define HDIM  128           // hidden
#define FIND  12            // feature in
#define NHEAD 4
#define HDH   32            // head dim
#define OUTD  256
#define MTOK  (SEQ*NT)      // 247808
#define KBIG  (NT*HDIM)     // 15488
#define SPLITK 11
#define NSTG  3
#define EPSV  1e-5f

// ---------------- scratch (device globals; no allocation allowed) ----------
__device__ float g_x  [(size_t)MTOK * HDIM];
__device__ float g_qkv[(size_t)MTOK * 384];
__device__ float g_att[(size_t)MTOK * HDIM];
__device__ float g_h  [(size_t)MTOK * HDIM];
__device__ float g_py [(size_t)SPLITK * SEQ * OUTD];

__device__ __forceinline__ void cpasync16(uint32_t dst, const float* src) {
    asm volatile("cp.async.cg.shared.global [%0], [%1], 16;" :: "r"(dst), "l"(src));
}

__device__ __forceinline__ void mma_tf32(float c[4], uint32_t a0, uint32_t a1,
                                         uint32_t a2, uint32_t a3,
                                         uint32_t b0, uint32_t b1) {
    asm volatile(
        "mma.sync.aligned.m16n8k8.row.col.f32.tf32.tf32.f32 "
        "{%0,%1,%2,%3},{%4,%5,%6,%7},{%8,%9},{%0,%1,%2,%3};\n"
        : "+f"(c[0]), "+f"(c[1]), "+f"(c[2]), "+f"(c[3])
        : "r"(a0), "r"(a1), "r"(a2), "r"(a3), "r"(b0), "r"(b1));
}

// ---------------- embed: forest @ w_in^T + b_in + tree PE, then permute ----
__global__ void embed_kernel(const float* __restrict__ forest,
                             const int*   __restrict__ perm,
                             const float* __restrict__ w_in,
                             const float* __restrict__ b_in,
                             float* __restrict__ out)
{
    int tok = blockIdx.x;
    int s = tok / NT, i = tok - s * NT;
    int node = perm[i];
    int h = threadIdx.x;               // 128
    __shared__ float fs[FIND];
    const float* f = forest + ((size_t)s * NT + node) * FIND;
    if (h < FIND) fs[h] = f[h];
    __syncthreads();
    float acc = b_in[h];
#pragma unroll
    for (int k = 0; k < FIND; k++) acc += fs[k] * w_in[h * FIND + k];
    if (h < 12) {
        int mask = 0, cur = node;
        while (cur > 0) {
            int d = (cur >= 40) ? 4 : (cur >= 13) ? 3 : (cur >= 4) ? 2 : 1;
            int br = (cur - 1) % 3;
            mask |= 1 << ((d - 1) * 3 + br);
            cur = (cur - 1) / 3;
        }
        acc += (float)((mask >> h) & 1);
    }
    out[(size_t)tok * HDIM + h] = acc;
}

// ============ TF32 tensor-core GEMM: C = X[M,K] @ W[Nc,K]^T + epilogue =====
// CTA 128x128, BK=16 x 3-stage cp.async pipeline, register-double-buffered
// fragments, 8 warps (64x32 warp tiles).
// mode 0: +bias    mode 1: +bias,relu    mode 2: +bias+res, LayerNorm (Nc=128)
// mode 3: raw partial store (split-K over blockIdx.z; kstart = z*kchunk)
struct EpiSmem { float red[128][17]; float stat[128]; };
struct MmSmem  { float As[NSTG][128][20]; float Bs[NSTG][128][20]; };

__global__ __launch_bounds__(256, 2)
void gemm_tf32_kernel(const float* __restrict__ X, const float* __restrict__ W,
                      const float* __restrict__ bias, const float* __restrict__ res,
                      const float* __restrict__ lng, const float* __restrict__ lnb,
                      float* __restrict__ C, int M, int Nc, int K,
                      int kchunk, int mode)
{
    __shared__ union { MmSmem mm; EpiSmem ep; } sm;
    int tid = threadIdx.x;
    int lane = tid & 31, warp = tid >> 5;
    int tq = lane >> 2, tr = lane & 3;
    int warpM = warp & 1, warpN = warp >> 1;          // 2 x 4 warps
    int row0 = blockIdx.y * 128, col0 = blockIdx.x * 128;
    int kstart = blockIdx.z * kchunk;
    if (mode == 3) C += (size_t)blockIdx.z * M * Nc;

    int glr = tid >> 1;                 // row 0..127
    int glc = (tid & 1) * 8;            // float col 0 or 8
    const float* Xp = X + (size_t)(row0 + glr) * K + kstart + glc;
    const float* Wp = W + (size_t)(col0 + glr) * K + kstart + glc;
    uint32_t sa = (uint32_t)__cvta_generic_to_shared(&sm.mm.As[0][glr][glc]);
    uint32_t sb = (uint32_t)__cvta_generic_to_shared(&sm.mm.Bs[0][glr][glc]);
    const uint32_t STGB = 128 * 20 * 4;  // bytes per stage

    int nk16 = kchunk >> 4;              // k16 stages (always >= 3 here)

    // prologue: stages 0..NSTG-2
#pragma unroll
    for (int s = 0; s < NSTG - 1; s++) {
        if (s < nk16) {
            uint32_t so = (uint32_t)s * STGB;
            const float* xp = Xp + s * 16;
            const float* wp = Wp + s * 16;
            cpasync16(sa + so, xp);       cpasync16(sa + so + 16, xp + 4);
            cpasync16(sb + so, wp);       cpasync16(sb + so + 16, wp + 4);
        }
        asm volatile("cp.async.commit_group;");
    }
    asm volatile("cp.async.wait_group %0;" :: "n"(NSTG - 2));
    __syncthreads();

    float acc[4][4][4] = {};
    uint32_t af[2][4][4], bf[2][4][2];

    int arow = warpM * 64 + tq;          // + mi*16 (+8)
    int brow = warpN * 32 + tq;          // + ni*8

    // load frags j=0 of stage 0 into set 0
#pragma unroll
    for (int mi = 0; mi < 4; mi++) {
        af[0][mi][0] = __float_as_uint(sm.mm.As[0][arow + mi * 16    ][tr    ]);
        af[0][mi][1] = __float_as_uint(sm.mm.As[0][arow + mi * 16 + 8][tr    ]);
        af[0][mi][2] = __float_as_uint(sm.mm.As[0][arow + mi * 16    ][tr + 4]);
        af[0][mi][3] = __float_as_uint(sm.mm.As[0][arow + mi * 16 + 8][tr + 4]);
    }
#pragma unroll
    for (int ni = 0; ni < 4; ni++) {
        bf[0][ni][0] = __float_as_uint(sm.mm.Bs[0][brow + ni * 8][tr    ]);
        bf[0][ni][1] = __float_as_uint(sm.mm.Bs[0][brow + ni * 8][tr + 4]);
    }

    int buf = 0;                 // stage being consumed
    int wslot = NSTG - 1;        // stage slot being written next
    for (int kt = 0; kt < nk16; kt++) {
        // load frags j=1 (cols +8) of current stage into set 1
#pragma unroll
        for (int mi = 0; mi < 4; mi++) {
            af[1][mi][0] = __float_as_uint(sm.mm.As[buf][arow + mi * 16    ][8 + tr    ]);
            af[1][mi][1] = __float_as_uint(sm.mm.As[buf][arow + mi * 16 + 8][8 + tr    ]);
            af[1][mi][2] = __float_as_uint(sm.mm.As[buf][arow + mi * 16    ][8 + tr + 4]);
            af[1][mi][3] = __float_as_uint(sm.mm.As[buf][arow + mi * 16 + 8][8 + tr + 4]);
        }
#pragma unroll
        for (int ni = 0; ni < 4; ni++) {
            bf[1][ni][0] = __float_as_uint(sm.mm.Bs[buf][brow + ni * 8][8 + tr    ]);
            bf[1][ni][1] = __float_as_uint(sm.mm.Bs[buf][brow + ni * 8][8 + tr + 4]);
        }
        // MMA on set 0 (covers the set-1 LDS latency)
#pragma unroll
        for (int mi = 0; mi < 4; mi++)
#pragma unroll
            for (int ni = 0; ni < 4; ni++)
                mma_tf32(acc[mi][ni], af[0][mi][0], af[0][mi][1],
                         af[0][mi][2], af[0][mi][3],
                         bf[0][ni][0], bf[0][ni][1]);
        // issue next stage's global loads
        int snext = kt + NSTG - 1;
        if (snext < nk16) {
            uint32_t so = (uint32_t)wslot * STGB;
            const float* xp = Xp + snext * 16;
            const float* wp = Wp + snext * 16;
            cpasync16(sa + so, xp);       cpasync16(sa + so + 16, xp + 4);
            cpasync16(sb + so, wp);       cpasync16(sb + so + 16, wp + 4);
        }
        asm volatile("cp.async.commit_group;");
        asm volatile("cp.async.wait_group %0;" :: "n"(NSTG - 2));
        __syncthreads();                 // stage kt+1 now readable
        if (++wslot == NSTG) wslot = 0;
        int nb = buf + 1; if (nb == NSTG) nb = 0;
        if (kt + 1 < nk16) {
            // prefetch frags j=0 of next stage into set 0
#pragma unroll
            for (int mi = 0; mi < 4; mi++) {
                af[0][mi][0] = __float_as_uint(sm.mm.As[nb][arow + mi * 16    ][tr    ]);
                af[0][mi][1] = __float_as_uint(sm.mm.As[nb][arow + mi * 16 + 8][tr    ]);
                af[0][mi][2] = __float_as_uint(sm.mm.As[nb][arow + mi * 16    ][tr + 4]);
                af[0][mi][3] = __float_as_uint(sm.mm.As[nb][arow + mi * 16 + 8][tr + 4]);
            }
#pragma unroll
            for (int ni = 0; ni < 4; ni++) {
                bf[0][ni][0] = __float_as_uint(sm.mm.Bs[nb][brow + ni * 8][tr    ]);
                bf[0][ni][1] = __float_as_uint(sm.mm.Bs[nb][brow + ni * 8][tr + 4]);
            }
        }
        // MMA on set 1
#pragma unroll
        for (int mi = 0; mi < 4; mi++)
#pragma unroll
            for (int ni = 0; ni < 4; ni++)
                mma_tf32(acc[mi][ni], af[1][mi][0], af[1][mi][1],
                         af[1][mi][2], af[1][mi][3],
                         bf[1][ni][0], bf[1][ni][1]);
        buf = nb;
    }

    // ---------------- epilogues -------------------------------------------
    if (mode == 3) {            // raw partial (split-K)
#pragma unroll
        for (int mi = 0; mi < 4; mi++)
#pragma unroll
            for (int h = 0; h < 2; h++) {
                int r = row0 + warpM * 64 + mi * 16 + tq + 8 * h;
#pragma unroll
                for (int ni = 0; ni < 4; ni++) {
                    int c = col0 + warpN * 32 + ni * 8 + 2 * tr;
                    *(float2*)&C[(size_t)r * Nc + c] =
                        make_float2(acc[mi][ni][2 * h], acc[mi][ni][2 * h + 1]);
                }
            }
        return;
    }
    if (mode != 2) {
#pragma unroll
        for (int mi = 0; mi < 4; mi++)
#pragma unroll
            for (int h = 0; h < 2; h++) {
                int r = row0 + warpM * 64 + mi * 16 + tq + 8 * h;
#pragma unroll
                for (int ni = 0; ni < 4; ni++) {
                    int c = col0 + warpN * 32 + ni * 8 + 2 * tr;
                    float v0 = acc[mi][ni][2 * h]     + bias[c];
                    float v1 = acc[mi][ni][2 * h + 1] + bias[c + 1];
                    if (mode == 1) { v0 = fmaxf(v0, 0.f); v1 = fmaxf(v1, 0.f); }
                    *(float2*)&C[(size_t)r * Nc + c] = make_float2(v0, v1);
                }
            }
        return;
    }

    // mode 2: bias + residual + LayerNorm over 128-wide rows (col0 == 0)
#pragma unroll
    for (int mi = 0; mi < 4; mi++)
#pragma unroll
        for (int h = 0; h < 2; h++) {
            int r = row0 + warpM * 64 + mi * 16 + tq + 8 * h;
#pragma unroll
            for (int ni = 0; ni < 4; ni++) {
                int c = warpN * 32 + ni * 8 + 2 * tr;
                float2 rv = *(const float2*)&res[(size_t)r * 128 + c];
                acc[mi][ni][2 * h]     += bias[c]     + rv.x;
                acc[mi][ni][2 * h + 1] += bias[c + 1] + rv.y;
            }
        }
    __syncthreads();   // all warps done with sm.mm before reusing as sm.ep
    int cid = warpN * 4 + tr;      // 16 column-contributors per row
#pragma unroll
    for (int mi = 0; mi < 4; mi++)
#pragma unroll
        for (int h = 0; h < 2; h++) {
            int rl = warpM * 64 + mi * 16 + tq + 8 * h;
            float s = 0.f;
#pragma unroll
            for (int ni = 0; ni < 4; ni++) s += acc[mi][ni][2 * h] + acc[mi][ni][2 * h + 1];
            sm.ep.red[rl][cid] = s;
        }
    __syncthreads();
    if (tid < 128) {
        float s = 0.f;
#pragma unroll
        for (int t = 0; t < 16; t++) s += sm.ep.red[tid][t];
        sm.ep.stat[tid] = s * (1.f / 128.f);
    }
    __syncthreads();
    float mean[4][2];
#pragma unroll
    for (int mi = 0; mi < 4; mi++)
#pragma unroll
        for (int h = 0; h < 2; h++)
            mean[mi][h] = sm.ep.stat[warpM * 64 + mi * 16 + tq + 8 * h];
    __syncthreads();
#pragma unroll
    for (int mi = 0; mi < 4; mi++)
#pragma unroll
        for (int h = 0; h < 2; h++) {
            int rl = warpM * 64 + mi * 16 + tq + 8 * h;
            float s = 0.f;
#pragma unroll
            for (int ni = 0; ni < 4; ni++) {
                float d0 = acc[mi][ni][2 * h]     - mean[mi][h];
                float d1 = acc[mi][ni][2 * h + 1] - mean[mi][h];
                s += d0 * d0 + d1 * d1;
            }
            sm.ep.red[rl][cid] = s;
        }
    __syncthreads();
    if (tid < 128) {
        float s = 0.f;
#pragma unroll
        for (int t = 0; t < 16; t++) s += sm.ep.red[tid][t];
        sm.ep.stat[tid] = rsqrtf(s * (1.f / 128.f) + EPSV);
    }
    __syncthreads();
#pragma unroll
    for (int mi = 0; mi < 4; mi++)
#pragma unroll
        for (int h = 0; h < 2; h++) {
            int rl = warpM * 64 + mi * 16 + tq + 8 * h;
            int r = row0 + rl;
            float rs = sm.ep.stat[rl];
#pragma unroll
            for (int ni = 0; ni < 4; ni++) {
                int c = warpN * 32 + ni * 8 + 2 * tr;
                float v0 = (acc[mi][ni][2 * h]     - mean[mi][h]) * rs * lng[c]     + lnb[c];
                float v1 = (acc[mi][ni][2 * h + 1] - mean[mi][h]) * rs * lng[c + 1] + lnb[c + 1];
                *(float2*)&C[(size_t)r * 128 + c] = make_float2(v0, v1);
            }
        }
}

// ---------------- fused attention: one block per (seq, head) ---------------
__global__ void attn_kernel(const float* __restrict__ qkv, float* __restrict__ out)
{
    int s  = blockIdx.x >> 2;
    int hh = blockIdx.x & 3;
    int t = threadIdx.x, warp = t >> 5, lane = t & 31;
    __shared__ float qs[NT][33];
    __shared__ float ks[NT][33];
    __shared__ float vs[NT][33];
    const float* base = qkv + (size_t)s * NT * 384;
    for (int idx = t; idx < NT * HDH; idx += 128) {
        int n = idx >> 5, d = idx & 31;
        const float* bn = base + (size_t)n * 384 + hh * HDH + d;
        qs[n][d] = bn[0];
        ks[n][d] = bn[128];
        vs[n][d] = bn[256];
    }
    __syncthreads();
    const float scale = 0.17677669529663687f;  // 1/sqrt(32)
    for (int q = warp; q < NT; q += 4) {
        float lg[4];
        float mx = -1e30f;
#pragma unroll
        for (int j = 0; j < 4; j++) {
            int key = lane + j * 32;
            float a = -1e30f;
            if (key < NT) {
                float acc = 0.f;
#pragma unroll
                for (int d = 0; d < HDH; d++) acc += qs[q][d] * ks[key][d];
                a = acc * scale;
            }
            lg[j] = a;
            mx = fmaxf(mx, a);
        }
#pragma unroll
        for (int o = 16; o; o >>= 1) mx = fmaxf(mx, __shfl_xor_sync(0xffffffffu, mx, o));
        float sum = 0.f;
#pragma unroll
        for (int j = 0; j < 4; j++) {
            int key = lane + j * 32;
            float e = (key < NT) ? __expf(lg[j] - mx) : 0.f;
            lg[j] = e;
            sum += e;
        }
#pragma unroll
        for (int o = 16; o; o >>= 1) sum += __shfl_xor_sync(0xffffffffu, sum, o);
        float inv = 1.f / sum;
#pragma unroll
        for (int j = 0; j < 4; j++) lg[j] *= inv;
        float o0 = 0.f;
        for (int kx = 0; kx < NT; kx++) {
            float p = __shfl_sync(0xffffffffu, lg[kx >> 5], kx & 31);
            o0 += p * vs[kx][lane];
        }
        out[((size_t)s * NT + q) * HDIM + hh * HDH + lane] = o0;
    }
}

// ------- final: reduce split-K partials + bias + LayerNorm over 256 -------
__global__ void out_ln_kernel(const float* __restrict__ part,
                              const float* __restrict__ b_out,
                              const float* __restrict__ g,
                              const float* __restrict__ b,
                              float* __restrict__ out)
{
    int row = blockIdx.x, t = threadIdx.x;  // 256 threads
    size_t idx = (size_t)row * OUTD + t;
    float v = b_out[t];
#pragma unroll
    for (int z = 0; z < SPLITK; z++) v += part[(size_t)z * SEQ * OUTD + idx];
    __shared__ float red[9];
    int lane = t & 31, warp = t >> 5;
    float s = v;
#pragma unroll
    for (int o = 16; o; o >>= 1) s += __shfl_xor_sync(0xffffffffu, s, o);
    if (lane == 0) red[warp] = s;
    __syncthreads();
    if (t == 0) { float tot = 0; for (int i = 0; i < 8; i++) tot += red[i]; red[8] = tot; }
    __syncthreads();
    float mean = red[8] * (1.f / 256.f);
    float d = v - mean;
    float s2 = d * d;
#pragma unroll
    for (int o = 16; o; o >>= 1) s2 += __shfl_xor_sync(0xffffffffu, s2, o);
    __syncthreads();
    if (lane == 0) red[warp] = s2;
    __syncthreads();
    if (t == 0) { float tot = 0; for (int i = 0; i < 8; i++) tot += red[i]; red[8] = tot; }
    __syncthreads();
    float var = red[8] * (1.f / 256.f);
    out[idx] = d * rsqrtf(var + EPSV) * g[t] + b[t];
}

// ---------------- launch ---------------------------------------------------
extern "C" void kernel_launch(void* const* d_in, const int* in_sizes, int n_in,
                              void* d_out, int out_size)
{
    const float* forest = (const float*)d_in[0];
    const int*   perm   = (const int*)  d_in[2];
    const float* w_in   = (const float*)d_in[3];
    const float* b_in   = (const float*)d_in[4];
    const float* qkv_w  = (const float*)d_in[5];
    const float* qkv_b  = (const float*)d_in[6];
    const float* proj_w = (const float*)d_in[7];
    const float* proj_b = (const float*)d_in[8];
    const float* ff1_w  = (const float*)d_in[9];
    const float* ff1_b  = (const float*)d_in[10];
    const float* ff2_w  = (const float*)d_in[11];
    const float* ff2_b  = (const float*)d_in[12];
    const float* ln1_g  = (const float*)d_in[13];
    const float* ln1_b  = (const float*)d_in[14];
    const float* ln2_g  = (const float*)d_in[15];
    const float* ln2_b  = (const float*)d_in[16];
    const float* w_out  = (const float*)d_in[17];
    const float* b_out  = (const float*)d_in[18];
    const float* lnf_g  = (const float*)d_in[19];
    const float* lnf_b  = (const float*)d_in[20];

    float *xb, *qb, *ab, *hb, *pb;
    cudaGetSymbolAddress((void**)&xb, g_x);
    cudaGetSymbolAddress((void**)&qb, g_qkv);
    cudaGetSymbolAddress((void**)&ab, g_att);
    cudaGetSymbolAddress((void**)&hb, g_h);
    cudaGetSymbolAddress((void**)&pb, g_py);

    embed_kernel<<<MTOK, 128>>>(forest, perm, w_in, b_in, xb);

    const int GR = MTOK / 128;  // 1936
    for (int l = 0; l < 2; l++) {
        gemm_tf32_kernel<<<dim3(3, GR), 256>>>(
            xb, qkv_w + (size_t)l * 384 * 128, qkv_b + l * 384,
            nullptr, nullptr, nullptr, qb, MTOK, 384, 128, 128, 0);
        attn_kernel<<<SEQ * NHEAD, 128>>>(qb, ab);
        gemm_tf32_kernel<<<dim3(1, GR), 256>>>(
            ab, proj_w + (size_t)l * 128 * 128, proj_b + l * 128,
            xb, ln1_g + l * 128, ln1_b + l * 128, xb, MTOK, 128, 128, 128, 2);
        gemm_tf32_kernel<<<dim3(1, GR), 256>>>(
            xb, ff1_w + (size_t)l * 128 * 128, ff1_b + l * 128,
            nullptr, nullptr, nullptr, hb, MTOK, 128, 128, 128, 1);
        gemm_tf32_kernel<<<dim3(1, GR), 256>>>(
            hb, ff2_w + (size_t)l * 128 * 128, ff2_b + l * 128,
            xb, ln2_g + l * 128, ln2_b + l * 128, xb, MTOK, 128, 128, 128, 2);
    }

    // output projection: split-K = 11 in one launch (15488 = 11 * 1408)
    gemm_tf32_kernel<<<dim3(OUTD / 128, SEQ / 128, SPLITK), 256>>>(
        xb, w_out, nullptr, nullptr, nullptr, nullptr,
        pb, SEQ, OUTD, KBIG, KBIG / SPLITK, 3);
    out_ln_kernel<<<SEQ, 256>>>(pb, b_out, lnf_g, lnf_b, (float*)d_out);
}

// round 9
// speedup vs baseline: 3.2075x; 1.5962x over previous
#include <cuda_runtime.h>
#include <cstdint>

#define SEQ   2048          // B*A
#define NT    121           // tokens
#define HDIM  128           // hidden
#define FIND  12            // feature in
#define NHEAD 4
#define HDH   32            // head dim
#define OUTD  256
#define MTOK  (SEQ*NT)      // 247808
#define KBIG  (NT*HDIM)     // 15488
#define SPLITK 11
#define NSTG  3
#define EPSV  1e-5f

// ---------------- scratch (device globals; no allocation allowed) ----------
__device__ float g_x  [(size_t)MTOK * HDIM];
__device__ float g_qkv[(size_t)MTOK * 384];
__device__ float g_att[(size_t)MTOK * HDIM];
__device__ float g_h  [(size_t)MTOK * HDIM];
__device__ float g_py [(size_t)SPLITK * SEQ * OUTD];

__device__ __forceinline__ void cpasync16(uint32_t dst, const float* src) {
    asm volatile("cp.async.cg.shared.global [%0], [%1], 16;" :: "r"(dst), "l"(src));
}
__device__ __forceinline__ uint32_t smem_u32(const void* p) {
    uint32_t a;
    asm("{ .reg .u64 t; cvta.to.shared.u64 t, %1; cvt.u32.u64 %0, t; }" : "=r"(a) : "l"(p));
    return a;
}

__device__ __forceinline__ void mma_tf32(float c[4], uint32_t a0, uint32_t a1,
                                         uint32_t a2, uint32_t a3,
                                         uint32_t b0, uint32_t b1) {
    asm volatile(
        "mma.sync.aligned.m16n8k8.row.col.f32.tf32.tf32.f32 "
        "{%0,%1,%2,%3},{%4,%5,%6,%7},{%8,%9},{%0,%1,%2,%3};\n"
        : "+f"(c[0]), "+f"(c[1]), "+f"(c[2]), "+f"(c[3])
        : "r"(a0), "r"(a1), "r"(a2), "r"(a3), "r"(b0), "r"(b1));
}

// ---------------- embed: forest @ w_in^T + b_in + tree PE, then permute ----
__global__ void embed_kernel(const float* __restrict__ forest,
                             const int*   __restrict__ perm,
                             const float* __restrict__ w_in,
                             const float* __restrict__ b_in,
                             float* __restrict__ out)
{
    int tok = blockIdx.x;
    int s = tok / NT, i = tok - s * NT;
    int node = perm[i];
    int h = threadIdx.x;               // 128
    __shared__ float fs[FIND];
    const float* f = forest + ((size_t)s * NT + node) * FIND;
    if (h < FIND) fs[h] = f[h];
    __syncthreads();
    float acc = b_in[h];
#pragma unroll
    for (int k = 0; k < FIND; k++) acc += fs[k] * w_in[h * FIND + k];
    if (h < 12) {
        int mask = 0, cur = node;
        while (cur > 0) {
            int d = (cur >= 40) ? 4 : (cur >= 13) ? 3 : (cur >= 4) ? 2 : 1;
            int br = (cur - 1) % 3;
            mask |= 1 << ((d - 1) * 3 + br);
            cur = (cur - 1) / 3;
        }
        acc += (float)((mask >> h) & 1);
    }
    out[(size_t)tok * HDIM + h] = acc;
}

// ============ TF32 tensor-core GEMM: C = X[M,K] @ W[Nc,K]^T + epilogue =====
// CTA 128x128, BK=16 x 3-stage cp.async pipeline, register-double-buffered
// fragments, 8 warps (64x32 warp tiles).
// mode 0: +bias    mode 1: +bias,relu    mode 2: +bias+res, LayerNorm (Nc=128)
// mode 3: raw partial store (split-K over blockIdx.z; kstart = z*kchunk)
struct EpiSmem { float red[128][17]; float stat[128]; };
struct MmSmem  { float As[NSTG][128][20]; float Bs[NSTG][128][20]; };

__global__ __launch_bounds__(256, 2)
void gemm_tf32_kernel(const float* __restrict__ X, const float* __restrict__ W,
                      const float* __restrict__ bias, const float* __restrict__ res,
                      const float* __restrict__ lng, const float* __restrict__ lnb,
                      float* __restrict__ C, int M, int Nc, int K,
                      int kchunk, int mode)
{
    __shared__ union { MmSmem mm; EpiSmem ep; } sm;
    int tid = threadIdx.x;
    int lane = tid & 31, warp = tid >> 5;
    int tq = lane >> 2, tr = lane & 3;
    int warpM = warp & 1, warpN = warp >> 1;          // 2 x 4 warps
    int row0 = blockIdx.y * 128, col0 = blockIdx.x * 128;
    int kstart = blockIdx.z * kchunk;
    if (mode == 3) C += (size_t)blockIdx.z * M * Nc;

    int glr = tid >> 1;                 // row 0..127
    int glc = (tid & 1) * 8;            // float col 0 or 8
    const float* Xp = X + (size_t)(row0 + glr) * K + kstart + glc;
    const float* Wp = W + (size_t)(col0 + glr) * K + kstart + glc;
    uint32_t sa = smem_u32(&sm.mm.As[0][glr][glc]);
    uint32_t sb = smem_u32(&sm.mm.Bs[0][glr][glc]);
    const uint32_t STGB = 128 * 20 * 4;  // bytes per stage

    int nk16 = kchunk >> 4;              // k16 stages (always >= 3 here)

#pragma unroll
    for (int s = 0; s < NSTG - 1; s++) {
        if (s < nk16) {
            uint32_t so = (uint32_t)s * STGB;
            const float* xp = Xp + s * 16;
            const float* wp = Wp + s * 16;
            cpasync16(sa + so, xp);       cpasync16(sa + so + 16, xp + 4);
            cpasync16(sb + so, wp);       cpasync16(sb + so + 16, wp + 4);
        }
        asm volatile("cp.async.commit_group;");
    }
    asm volatile("cp.async.wait_group %0;" :: "n"(NSTG - 2));
    __syncthreads();

    float acc[4][4][4] = {};
    uint32_t af[2][4][4], bf[2][4][2];

    int arow = warpM * 64 + tq;          // + mi*16 (+8)
    int brow = warpN * 32 + tq;          // + ni*8

#pragma unroll
    for (int mi = 0; mi < 4; mi++) {
        af[0][mi][0] = __float_as_uint(sm.mm.As[0][arow + mi * 16    ][tr    ]);
        af[0][mi][1] = __float_as_uint(sm.mm.As[0][arow + mi * 16 + 8][tr    ]);
        af[0][mi][2] = __float_as_uint(sm.mm.As[0][arow + mi * 16    ][tr + 4]);
        af[0][mi][3] = __float_as_uint(sm.mm.As[0][arow + mi * 16 + 8][tr + 4]);
    }
#pragma unroll
    for (int ni = 0; ni < 4; ni++) {
        bf[0][ni][0] = __float_as_uint(sm.mm.Bs[0][brow + ni * 8][tr    ]);
        bf[0][ni][1] = __float_as_uint(sm.mm.Bs[0][brow + ni * 8][tr + 4]);
    }

    int buf = 0, wslot = NSTG - 1;
    for (int kt = 0; kt < nk16; kt++) {
#pragma unroll
        for (int mi = 0; mi < 4; mi++) {
            af[1][mi][0] = __float_as_uint(sm.mm.As[buf][arow + mi * 16    ][8 + tr    ]);
            af[1][mi][1] = __float_as_uint(sm.mm.As[buf][arow + mi * 16 + 8][8 + tr    ]);
            af[1][mi][2] = __float_as_uint(sm.mm.As[buf][arow + mi * 16    ][8 + tr + 4]);
            af[1][mi][3] = __float_as_uint(sm.mm.As[buf][arow + mi * 16 + 8][8 + tr + 4]);
        }
#pragma unroll
        for (int ni = 0; ni < 4; ni++) {
            bf[1][ni][0] = __float_as_uint(sm.mm.Bs[buf][brow + ni * 8][8 + tr    ]);
            bf[1][ni][1] = __float_as_uint(sm.mm.Bs[buf][brow + ni * 8][8 + tr + 4]);
        }
#pragma unroll
        for (int mi = 0; mi < 4; mi++)
#pragma unroll
            for (int ni = 0; ni < 4; ni++)
                mma_tf32(acc[mi][ni], af[0][mi][0], af[0][mi][1],
                         af[0][mi][2], af[0][mi][3],
                         bf[0][ni][0], bf[0][ni][1]);
        int snext = kt + NSTG - 1;
        if (snext < nk16) {
            uint32_t so = (uint32_t)wslot * STGB;
            const float* xp = Xp + snext * 16;
            const float* wp = Wp + snext * 16;
            cpasync16(sa + so, xp);       cpasync16(sa + so + 16, xp + 4);
            cpasync16(sb + so, wp);       cpasync16(sb + so + 16, wp + 4);
        }
        asm volatile("cp.async.commit_group;");
        asm volatile("cp.async.wait_group %0;" :: "n"(NSTG - 2));
        __syncthreads();
        if (++wslot == NSTG) wslot = 0;
        int nb = buf + 1; if (nb == NSTG) nb = 0;
        if (kt + 1 < nk16) {
#pragma unroll
            for (int mi = 0; mi < 4; mi++) {
                af[0][mi][0] = __float_as_uint(sm.mm.As[nb][arow + mi * 16    ][tr    ]);
                af[0][mi][1] = __float_as_uint(sm.mm.As[nb][arow + mi * 16 + 8][tr    ]);
                af[0][mi][2] = __float_as_uint(sm.mm.As[nb][arow + mi * 16    ][tr + 4]);
                af[0][mi][3] = __float_as_uint(sm.mm.As[nb][arow + mi * 16 + 8][tr + 4]);
            }
#pragma unroll
            for (int ni = 0; ni < 4; ni++) {
                bf[0][ni][0] = __float_as_uint(sm.mm.Bs[nb][brow + ni * 8][tr    ]);
                bf[0][ni][1] = __float_as_uint(sm.mm.Bs[nb][brow + ni * 8][tr + 4]);
            }
        }
#pragma unroll
        for (int mi = 0; mi < 4; mi++)
#pragma unroll
            for (int ni = 0; ni < 4; ni++)
                mma_tf32(acc[mi][ni], af[1][mi][0], af[1][mi][1],
                         af[1][mi][2], af[1][mi][3],
                         bf[1][ni][0], bf[1][ni][1]);
        buf = nb;
    }

    // ---------------- epilogues -------------------------------------------
    if (mode == 3) {            // raw partial (split-K)
#pragma unroll
        for (int mi = 0; mi < 4; mi++)
#pragma unroll
            for (int h = 0; h < 2; h++) {
                int r = row0 + warpM * 64 + mi * 16 + tq + 8 * h;
#pragma unroll
                for (int ni = 0; ni < 4; ni++) {
                    int c = col0 + warpN * 32 + ni * 8 + 2 * tr;
                    *(float2*)&C[(size_t)r * Nc + c] =
                        make_float2(acc[mi][ni][2 * h], acc[mi][ni][2 * h + 1]);
                }
            }
        return;
    }
    if (mode != 2) {
#pragma unroll
        for (int mi = 0; mi < 4; mi++)
#pragma unroll
            for (int h = 0; h < 2; h++) {
                int r = row0 + warpM * 64 + mi * 16 + tq + 8 * h;
#pragma unroll
                for (int ni = 0; ni < 4; ni++) {
                    int c = col0 + warpN * 32 + ni * 8 + 2 * tr;
                    float v0 = acc[mi][ni][2 * h]     + bias[c];
                    float v1 = acc[mi][ni][2 * h + 1] + bias[c + 1];
                    if (mode == 1) { v0 = fmaxf(v0, 0.f); v1 = fmaxf(v1, 0.f); }
                    *(float2*)&C[(size_t)r * Nc + c] = make_float2(v0, v1);
                }
            }
        return;
    }

    // mode 2: bias + residual + LayerNorm over 128-wide rows (col0 == 0)
#pragma unroll
    for (int mi = 0; mi < 4; mi++)
#pragma unroll
        for (int h = 0; h < 2; h++) {
            int r = row0 + warpM * 64 + mi * 16 + tq + 8 * h;
#pragma unroll
            for (int ni = 0; ni < 4; ni++) {
                int c = warpN * 32 + ni * 8 + 2 * tr;
                float2 rv = *(const float2*)&res[(size_t)r * 128 + c];
                acc[mi][ni][2 * h]     += bias[c]     + rv.x;
                acc[mi][ni][2 * h + 1] += bias[c + 1] + rv.y;
            }
        }
    __syncthreads();   // all warps done with sm.mm before reusing as sm.ep
    int cid = warpN * 4 + tr;      // 16 column-contributors per row
#pragma unroll
    for (int mi = 0; mi < 4; mi++)
#pragma unroll
        for (int h = 0; h < 2; h++) {
            int rl = warpM * 64 + mi * 16 + tq + 8 * h;
            float s = 0.f;
#pragma unroll
            for (int ni = 0; ni < 4; ni++) s += acc[mi][ni][2 * h] + acc[mi][ni][2 * h + 1];
            sm.ep.red[rl][cid] = s;
        }
    __syncthreads();
    if (tid < 128) {
        float s = 0.f;
#pragma unroll
        for (int t = 0; t < 16; t++) s += sm.ep.red[tid][t];
        sm.ep.stat[tid] = s * (1.f / 128.f);
    }
    __syncthreads();
    float mean[4][2];
#pragma unroll
    for (int mi = 0; mi < 4; mi++)
#pragma unroll
        for (int h = 0; h < 2; h++)
            mean[mi][h] = sm.ep.stat[warpM * 64 + mi * 16 + tq + 8 * h];
    __syncthreads();
#pragma unroll
    for (int mi = 0; mi < 4; mi++)
#pragma unroll
        for (int h = 0; h < 2; h++) {
            int rl = warpM * 64 + mi * 16 + tq + 8 * h;
            float s = 0.f;
#pragma unroll
            for (int ni = 0; ni < 4; ni++) {
                float d0 = acc[mi][ni][2 * h]     - mean[mi][h];
                float d1 = acc[mi][ni][2 * h + 1] - mean[mi][h];
                s += d0 * d0 + d1 * d1;
            }
            sm.ep.red[rl][cid] = s;
        }
    __syncthreads();
    if (tid < 128) {
        float s = 0.f;
#pragma unroll
        for (int t = 0; t < 16; t++) s += sm.ep.red[tid][t];
        sm.ep.stat[tid] = rsqrtf(s * (1.f / 128.f) + EPSV);
    }
    __syncthreads();
#pragma unroll
    for (int mi = 0; mi < 4; mi++)
#pragma unroll
        for (int h = 0; h < 2; h++) {
            int rl = warpM * 64 + mi * 16 + tq + 8 * h;
            int r = row0 + rl;
            float rs = sm.ep.stat[rl];
#pragma unroll
            for (int ni = 0; ni < 4; ni++) {
                int c = warpN * 32 + ni * 8 + 2 * tr;
                float v0 = (acc[mi][ni][2 * h]     - mean[mi][h]) * rs * lng[c]     + lnb[c];
                float v1 = (acc[mi][ni][2 * h + 1] - mean[mi][h]) * rs * lng[c + 1] + lnb[c + 1];
                *(float2*)&C[(size_t)r * 128 + c] = make_float2(v0, v1);
            }
        }
}

// ======== tensor-core attention: one CTA per (seq, head), 256 threads ======
// dyn smem layout (floats):
//   [0 .. 128*36)            qs[128][36]      (aliased later by sp)
//   [128*36 .. 2*128*36)     ks[128][36]      (aliased later by sp)
//   sp[128][132] occupies [0 .. 128*132)
//   vt[32][132]  at [128*132 .. 128*132 + 32*132)
#define ATTN_SMEM_FLOATS (128 * 132 + 32 * 132)
#define ATTN_SMEM_BYTES  (ATTN_SMEM_FLOATS * 4)

__global__ __launch_bounds__(256)
void attn_mma_kernel(const float* __restrict__ qkv, float* __restrict__ out)
{
    extern __shared__ float smf[];
    float (*qs)[36]  = (float(*)[36])smf;
    float (*ks)[36]  = (float(*)[36])(smf + 128 * 36);
    float (*sp)[132] = (float(*)[132])smf;
    float (*vt)[132] = (float(*)[132])(smf + 128 * 132);

    int s  = blockIdx.x >> 2;
    int hh = blockIdx.x & 3;
    int tid = threadIdx.x;
    int lane = tid & 31, warp = tid >> 5;
    int tq = lane >> 2, tr = lane & 3;
    int warpM = warp & 1, warpN = warp >> 1;     // 2 x 4

    // zero pad rows of qs/ks (121..127) and pad key-cols of vt (121..127)
    for (int idx = tid; idx < 7 * 36; idx += 256) {
        int r = 121 + idx / 36, c = idx % 36;
        qs[r][c] = 0.f;
        ks[r][c] = 0.f;
    }
    for (int idx = tid; idx < 32 * 7; idx += 256) {
        int d = idx / 7, c = 121 + idx % 7;
        vt[d][c] = 0.f;
    }

    const float* base = qkv + (size_t)s * NT * 384 + hh * HDH;
    for (int idx = tid; idx < NT * 8; idx += 256) {
        int n = idx >> 3, d4 = (idx & 7) * 4;
        const float* bp = base + (size_t)n * 384 + d4;
        float4 qv = *(const float4*)(bp);
        float4 kv = *(const float4*)(bp + 128);
        float4 vv = *(const float4*)(bp + 256);
        *(float4*)&qs[n][d4] = qv;
        *(float4*)&ks[n][d4] = kv;
        vt[d4 + 0][n] = vv.x;
        vt[d4 + 1][n] = vv.y;
        vt[d4 + 2][n] = vv.z;
        vt[d4 + 3][n] = vv.w;
    }
    __syncthreads();

    // ---- S = Q @ K^T  (128x128x32) ----
    float acc[4][4][4] = {};
#pragma unroll
    for (int k8 = 0; k8 < 32; k8 += 8) {
        uint32_t af[4][4], bf[4][2];
#pragma unroll
        for (int mi = 0; mi < 4; mi++) {
            int ar = warpM * 64 + mi * 16 + tq;
            af[mi][0] = __float_as_uint(qs[ar    ][k8 + tr    ]);
            af[mi][1] = __float_as_uint(qs[ar + 8][k8 + tr    ]);
            af[mi][2] = __float_as_uint(qs[ar    ][k8 + tr + 4]);
            af[mi][3] = __float_as_uint(qs[ar + 8][k8 + tr + 4]);
        }
#pragma unroll
        for (int ni = 0; ni < 4; ni++) {
            int br = warpN * 32 + ni * 8 + tq;
            bf[ni][0] = __float_as_uint(ks[br][k8 + tr    ]);
            bf[ni][1] = __float_as_uint(ks[br][k8 + tr + 4]);
        }
#pragma unroll
        for (int mi = 0; mi < 4; mi++)
#pragma unroll
            for (int ni = 0; ni < 4; ni++)
                mma_tf32(acc[mi][ni], af[mi][0], af[mi][1], af[mi][2], af[mi][3],
                         bf[ni][0], bf[ni][1]);
    }
    __syncthreads();   // everyone done reading qs/ks before sp overwrites them

#pragma unroll
    for (int mi = 0; mi < 4; mi++)
#pragma unroll
        for (int h = 0; h < 2; h++) {
            int r = warpM * 64 + mi * 16 + tq + 8 * h;
#pragma unroll
            for (int ni = 0; ni < 4; ni++) {
                int c = warpN * 32 + ni * 8 + 2 * tr;
                *(float2*)&sp[r][c] = make_float2(acc[mi][ni][2 * h], acc[mi][ni][2 * h + 1]);
            }
        }
    __syncthreads();

    // ---- softmax over rows (scale folded into exp); mask cols >= NT ----
    const float scale = 0.17677669529663687f;   // 1/sqrt(32)
    if (tid < 128) {
        float mx = -1e30f;
        for (int c = 0; c < NT; c++) mx = fmaxf(mx, sp[tid][c]);
        float sum = 0.f;
        for (int c = 0; c < NT; c++) {
            float e = __expf((sp[tid][c] - mx) * scale);
            sp[tid][c] = e;
            sum += e;
        }
        float inv = 1.f / sum;
        for (int c = 0; c < NT; c++) sp[tid][c] *= inv;
#pragma unroll
        for (int c = NT; c < 128; c++) sp[tid][c] = 0.f;
    }
    __syncthreads();

    // ---- O = P @ V   (128x32x128), V^T in vt[dim][key] ----
    float pacc[4][4] = {};
#pragma unroll
    for (int k8 = 0; k8 < 128; k8 += 8) {
        uint32_t af[4][4], bf[2];
#pragma unroll
        for (int mi = 0; mi < 4; mi++) {
            int ar = warpM * 64 + mi * 16 + tq;
            af[mi][0] = __float_as_uint(sp[ar    ][k8 + tr    ]);
            af[mi][1] = __float_as_uint(sp[ar + 8][k8 + tr    ]);
            af[mi][2] = __float_as_uint(sp[ar    ][k8 + tr + 4]);
            af[mi][3] = __float_as_uint(sp[ar + 8][k8 + tr + 4]);
        }
        int bn = warpN * 8 + tq;
        bf[0] = __float_as_uint(vt[bn][k8 + tr    ]);
        bf[1] = __float_as_uint(vt[bn][k8 + tr + 4]);
#pragma unroll
        for (int mi = 0; mi < 4; mi++)
            mma_tf32(pacc[mi], af[mi][0], af[mi][1], af[mi][2], af[mi][3],
                     bf[0], bf[1]);
    }

#pragma unroll
    for (int mi = 0; mi < 4; mi++)
#pragma unroll
        for (int h = 0; h < 2; h++) {
            int r = warpM * 64 + mi * 16 + tq + 8 * h;
            if (r < NT) {
                int c = warpN * 8 + 2 * tr;
                *(float2*)&out[((size_t)s * NT + r) * HDIM + hh * HDH + c] =
                    make_float2(pacc[mi][2 * h], pacc[mi][2 * h + 1]);
            }
        }
}

// ------- final: reduce split-K partials + bias + LayerNorm over 256 -------
__global__ void out_ln_kernel(const float* __restrict__ part,
                              const float* __restrict__ b_out,
                              const float* __restrict__ g,
                              const float* __restrict__ b,
                              float* __restrict__ out)
{
    int row = blockIdx.x, t = threadIdx.x;  // 256 threads
    size_t idx = (size_t)row * OUTD + t;
    float v = b_out[t];
#pragma unroll
    for (int z = 0; z < SPLITK; z++) v += part[(size_t)z * SEQ * OUTD + idx];
    __shared__ float red[9];
    int lane = t & 31, warp = t >> 5;
    float s = v;
#pragma unroll
    for (int o = 16; o; o >>= 1) s += __shfl_xor_sync(0xffffffffu, s, o);
    if (lane == 0) red[warp] = s;
    __syncthreads();
    if (t == 0) { float tot = 0; for (int i = 0; i < 8; i++) tot += red[i]; red[8] = tot; }
    __syncthreads();
    float mean = red[8] * (1.f / 256.f);
    float d = v - mean;
    float s2 = d * d;
#pragma unroll
    for (int o = 16; o; o >>= 1) s2 += __shfl_xor_sync(0xffffffffu, s2, o);
    __syncthreads();
    if (lane == 0) red[warp] = s2;
    __syncthreads();
    if (t == 0) { float tot = 0; for (int i = 0; i < 8; i++) tot += red[i]; red[8] = tot; }
    __syncthreads();
    float var = red[8] * (1.f / 256.f);
    out[idx] = d * rsqrtf(var + EPSV) * g[t] + b[t];
}

// ---------------- launch ---------------------------------------------------
extern "C" void kernel_launch(void* const* d_in, const int* in_sizes, int n_in,
                              void* d_out, int out_size)
{
    const float* forest = (const float*)d_in[0];
    const int*   perm   = (const int*)  d_in[2];
    const float* w_in   = (const float*)d_in[3];
    const float* b_in   = (const float*)d_in[4];
    const float* qkv_w  = (const float*)d_in[5];
    const float* qkv_b  = (const float*)d_in[6];
    const float* proj_w = (const float*)d_in[7];
    const float* proj_b = (const float*)d_in[8];
    const float* ff1_w  = (const float*)d_in[9];
    const float* ff1_b  = (const float*)d_in[10];
    const float* ff2_w  = (const float*)d_in[11];
    const float* ff2_b  = (const float*)d_in[12];
    const float* ln1_g  = (const float*)d_in[13];
    const float* ln1_b  = (const float*)d_in[14];
    const float* ln2_g  = (const float*)d_in[15];
    const float* ln2_b  = (const float*)d_in[16];
    const float* w_out  = (const float*)d_in[17];
    const float* b_out  = (const float*)d_in[18];
    const float* lnf_g  = (const float*)d_in[19];
    const float* lnf_b  = (const float*)d_in[20];

    float *xb, *qb, *ab, *hb, *pb;
    cudaGetSymbolAddress((void**)&xb, g_x);
    cudaGetSymbolAddress((void**)&qb, g_qkv);
    cudaGetSymbolAddress((void**)&ab, g_att);
    cudaGetSymbolAddress((void**)&hb, g_h);
    cudaGetSymbolAddress((void**)&pb, g_py);

    cudaFuncSetAttribute(attn_mma_kernel,
                         cudaFuncAttributeMaxDynamicSharedMemorySize, ATTN_SMEM_BYTES);

    embed_kernel<<<MTOK, 128>>>(forest, perm, w_in, b_in, xb);

    const int GR = MTOK / 128;  // 1936
    for (int l = 0; l < 2; l++) {
        gemm_tf32_kernel<<<dim3(3, GR), 256>>>(
            xb, qkv_w + (size_t)l * 384 * 128, qkv_b + l * 384,
            nullptr, nullptr, nullptr, qb, MTOK, 384, 128, 128, 0);
        attn_mma_kernel<<<SEQ * NHEAD, 256, ATTN_SMEM_BYTES>>>(qb, ab);
        gemm_tf32_kernel<<<dim3(1, GR), 256>>>(
            ab, proj_w + (size_t)l * 128 * 128, proj_b + l * 128,
            xb, ln1_g + l * 128, ln1_b + l * 128, xb, MTOK, 128, 128, 128, 2);
        gemm_tf32_kernel<<<dim3(1, GR), 256>>>(
            xb, ff1_w + (size_t)l * 128 * 128, ff1_b + l * 128,
            nullptr, nullptr, nullptr, hb, MTOK, 128, 128, 128, 1);
        gemm_tf32_kernel<<<dim3(1, GR), 256>>>(
            hb, ff2_w + (size_t)l * 128 * 128, ff2_b + l * 128,
            xb, ln2_g + l * 128, ln2_b + l * 128, xb, MTOK, 128, 128, 128, 2);
    }

    // output projection: split-K = 11 in one launch (15488 = 11 * 1408)
    gemm_tf32_kernel<<<dim3(OUTD / 128, SEQ / 128, SPLITK), 256>>>(
        xb, w_out, nullptr, nullptr, nullptr, nullptr,
        pb, SEQ, OUTD, KBIG, KBIG / SPLITK, 3);
    out_ln_kernel<<<SEQ, 256>>>(pb, b_out, lnf_g, lnf_b, (float*)d_out);
}

// round 10
// speedup vs baseline: 3.2492x; 1.0130x over previous
#include <cuda_runtime.h>
#include <cstdint>

#define SEQ   2048          // B*A
#define NT    121           // tokens
#define HDIM  128           // hidden
#define FIND  12            // feature in
#define NHEAD 4
#define HDH   32            // head dim
#define OUTD  256
#define MTOK  (SEQ*NT)      // 247808
#define KBIG  (NT*HDIM)     // 15488
#define SPLITK 11
#define NSTG  5
#define EPSV  1e-5f

// per-stage floats per matrix: 128 rows x 20
#define STGF  (128 * 20)
#define GEMM_DYN_BYTES (NSTG * STGF * 4 * 2)   // A stages + B stages = 102400

// ---------------- scratch (device globals; no allocation allowed) ----------
__device__ float g_x  [(size_t)MTOK * HDIM];
__device__ float g_qkv[(size_t)MTOK * 384];
__device__ float g_att[(size_t)MTOK * HDIM];
__device__ float g_h  [(size_t)MTOK * HDIM];
__device__ float g_py [(size_t)SPLITK * SEQ * OUTD];

__device__ __forceinline__ void cpasync16(uint32_t dst, const float* src) {
    asm volatile("cp.async.cg.shared.global [%0], [%1], 16;" :: "r"(dst), "l"(src));
}
__device__ __forceinline__ uint32_t smem_u32(const void* p) {
    uint32_t a;
    asm("{ .reg .u64 t; cvta.to.shared.u64 t, %1; cvt.u32.u64 %0, t; }" : "=r"(a) : "l"(p));
    return a;
}

__device__ __forceinline__ void mma_tf32(float c[4], uint32_t a0, uint32_t a1,
                                         uint32_t a2, uint32_t a3,
                                         uint32_t b0, uint32_t b1) {
    asm volatile(
        "mma.sync.aligned.m16n8k8.row.col.f32.tf32.tf32.f32 "
        "{%0,%1,%2,%3},{%4,%5,%6,%7},{%8,%9},{%0,%1,%2,%3};\n"
        : "+f"(c[0]), "+f"(c[1]), "+f"(c[2]), "+f"(c[3])
        : "r"(a0), "r"(a1), "r"(a2), "r"(a3), "r"(b0), "r"(b1));
}

// ---------------- embed: 16 tokens per CTA, 128 threads --------------------
__global__ void embed_kernel(const float* __restrict__ forest,
                             const int*   __restrict__ perm,
                             const float* __restrict__ w_in,
                             const float* __restrict__ b_in,
                             float* __restrict__ out)
{
    int t0 = blockIdx.x * 16;
    int h = threadIdx.x;               // 128
    float w[FIND];
#pragma unroll
    for (int k = 0; k < FIND; k++) w[k] = w_in[h * FIND + k];
    float bh = b_in[h];
#pragma unroll 1
    for (int j = 0; j < 16; j++) {
        int tok = t0 + j;
        int s = tok / NT, i = tok - s * NT;
        int node = __ldg(&perm[i]);
        const float* f = forest + ((size_t)s * NT + node) * FIND;
        float acc = bh;
#pragma unroll
        for (int k = 0; k < FIND; k++) acc += __ldg(&f[k]) * w[k];
        if (h < 12) {
            int mask = 0, cur = node;
            while (cur > 0) {
                int d = (cur >= 40) ? 4 : (cur >= 13) ? 3 : (cur >= 4) ? 2 : 1;
                int br = (cur - 1) % 3;
                mask |= 1 << ((d - 1) * 3 + br);
                cur = (cur - 1) / 3;
            }
            acc += (float)((mask >> h) & 1);
        }
        out[(size_t)tok * HDIM + h] = acc;
    }
}

// ============ TF32 tensor-core GEMM: C = X[M,K] @ W[Nc,K]^T + epilogue =====
// CTA 128x128, BK=16 x 5-stage cp.async pipeline (dynamic smem), register-
// double-buffered fragments, 8 warps (64x32 warp tiles).
// mode 0: +bias    mode 1: +bias,relu    mode 2: +bias+res, LayerNorm (Nc=128)
// mode 3: raw partial store (split-K over blockIdx.z; kstart = z*kchunk)
__global__ __launch_bounds__(256)
void gemm_tf32_kernel(const float* __restrict__ X, const float* __restrict__ W,
                      const float* __restrict__ bias, const float* __restrict__ res,
                      const float* __restrict__ lng, const float* __restrict__ lnb,
                      float* __restrict__ C, int M, int Nc, int K,
                      int kchunk, int mode)
{
    extern __shared__ float dsm[];
    float* As = dsm;                   // [NSTG][128][20]
    float* Bs = dsm + NSTG * STGF;     // [NSTG][128][20]
#define ASS(s, r, c) As[(s) * STGF + (r) * 20 + (c)]
#define BSS(s, r, c) Bs[(s) * STGF + (r) * 20 + (c)]

    int tid = threadIdx.x;
    int lane = tid & 31, warp = tid >> 5;
    int tq = lane >> 2, tr = lane & 3;
    int warpM = warp & 1, warpN = warp >> 1;          // 2 x 4 warps
    int row0 = blockIdx.y * 128, col0 = blockIdx.x * 128;
    int kstart = blockIdx.z * kchunk;
    if (mode == 3) C += (size_t)blockIdx.z * M * Nc;

    int glr = tid >> 1;                 // row 0..127
    int glc = (tid & 1) * 8;            // float col 0 or 8
    const float* Xp = X + (size_t)(row0 + glr) * K + kstart + glc;
    const float* Wp = W + (size_t)(col0 + glr) * K + kstart + glc;
    uint32_t sa = smem_u32(&ASS(0, glr, glc));
    uint32_t sb = smem_u32(&BSS(0, glr, glc));
    const uint32_t STGB = STGF * 4;      // bytes per stage

    int nk16 = kchunk >> 4;              // k16 stages (always >= NSTG-1 here)

#pragma unroll
    for (int s = 0; s < NSTG - 1; s++) {
        if (s < nk16) {
            uint32_t so = (uint32_t)s * STGB;
            const float* xp = Xp + s * 16;
            const float* wp = Wp + s * 16;
            cpasync16(sa + so, xp);       cpasync16(sa + so + 16, xp + 4);
            cpasync16(sb + so, wp);       cpasync16(sb + so + 16, wp + 4);
        }
        asm volatile("cp.async.commit_group;");
    }
    asm volatile("cp.async.wait_group %0;" :: "n"(NSTG - 2));
    __syncthreads();

    float acc[4][4][4] = {};
    uint32_t af[2][4][4], bf[2][4][2];

    int arow = warpM * 64 + tq;          // + mi*16 (+8)
    int brow = warpN * 32 + tq;          // + ni*8

#pragma unroll
    for (int mi = 0; mi < 4; mi++) {
        af[0][mi][0] = __float_as_uint(ASS(0, arow + mi * 16    , tr    ));
        af[0][mi][1] = __float_as_uint(ASS(0, arow + mi * 16 + 8, tr    ));
        af[0][mi][2] = __float_as_uint(ASS(0, arow + mi * 16    , tr + 4));
        af[0][mi][3] = __float_as_uint(ASS(0, arow + mi * 16 + 8, tr + 4));
    }
#pragma unroll
    for (int ni = 0; ni < 4; ni++) {
        bf[0][ni][0] = __float_as_uint(BSS(0, brow + ni * 8, tr    ));
        bf[0][ni][1] = __float_as_uint(BSS(0, brow + ni * 8, tr + 4));
    }

    int buf = 0, wslot = NSTG - 1;
    for (int kt = 0; kt < nk16; kt++) {
#pragma unroll
        for (int mi = 0; mi < 4; mi++) {
            af[1][mi][0] = __float_as_uint(ASS(buf, arow + mi * 16    , 8 + tr    ));
            af[1][mi][1] = __float_as_uint(ASS(buf, arow + mi * 16 + 8, 8 + tr    ));
            af[1][mi][2] = __float_as_uint(ASS(buf, arow + mi * 16    , 8 + tr + 4));
            af[1][mi][3] = __float_as_uint(ASS(buf, arow + mi * 16 + 8, 8 + tr + 4));
        }
#pragma unroll
        for (int ni = 0; ni < 4; ni++) {
            bf[1][ni][0] = __float_as_uint(BSS(buf, brow + ni * 8, 8 + tr    ));
            bf[1][ni][1] = __float_as_uint(BSS(buf, brow + ni * 8, 8 + tr + 4));
        }
#pragma unroll
        for (int mi = 0; mi < 4; mi++)
#pragma unroll
            for (int ni = 0; ni < 4; ni++)
                mma_tf32(acc[mi][ni], af[0][mi][0], af[0][mi][1],
                         af[0][mi][2], af[0][mi][3],
                         bf[0][ni][0], bf[0][ni][1]);
        int snext = kt + NSTG - 1;
        if (snext < nk16) {
            uint32_t so = (uint32_t)wslot * STGB;
            const float* xp = Xp + snext * 16;
            const float* wp = Wp + snext * 16;
            cpasync16(sa + so, xp);       cpasync16(sa + so + 16, xp + 4);
            cpasync16(sb + so, wp);       cpasync16(sb + so + 16, wp + 4);
        }
        asm volatile("cp.async.commit_group;");
        asm volatile("cp.async.wait_group %0;" :: "n"(NSTG - 2));
        __syncthreads();
        if (++wslot == NSTG) wslot = 0;
        int nb = buf + 1; if (nb == NSTG) nb = 0;
        if (kt + 1 < nk16) {
#pragma unroll
            for (int mi = 0; mi < 4; mi++) {
                af[0][mi][0] = __float_as_uint(ASS(nb, arow + mi * 16    , tr    ));
                af[0][mi][1] = __float_as_uint(ASS(nb, arow + mi * 16 + 8, tr    ));
                af[0][mi][2] = __float_as_uint(ASS(nb, arow + mi * 16    , tr + 4));
                af[0][mi][3] = __float_as_uint(ASS(nb, arow + mi * 16 + 8, tr + 4));
            }
#pragma unroll
            for (int ni = 0; ni < 4; ni++) {
                bf[0][ni][0] = __float_as_uint(BSS(nb, brow + ni * 8, tr    ));
                bf[0][ni][1] = __float_as_uint(BSS(nb, brow + ni * 8, tr + 4));
            }
        }
#pragma unroll
        for (int mi = 0; mi < 4; mi++)
#pragma unroll
            for (int ni = 0; ni < 4; ni++)
                mma_tf32(acc[mi][ni], af[1][mi][0], af[1][mi][1],
                         af[1][mi][2], af[1][mi][3],
                         bf[1][ni][0], bf[1][ni][1]);
        buf = nb;
    }

    // ---------------- epilogues -------------------------------------------
    if (mode == 3) {            // raw partial (split-K)
#pragma unroll
        for (int mi = 0; mi < 4; mi++)
#pragma unroll
            for (int h = 0; h < 2; h++) {
                int r = row0 + warpM * 64 + mi * 16 + tq + 8 * h;
#pragma unroll
                for (int ni = 0; ni < 4; ni++) {
                    int c = col0 + warpN * 32 + ni * 8 + 2 * tr;
                    *(float2*)&C[(size_t)r * Nc + c] =
                        make_float2(acc[mi][ni][2 * h], acc[mi][ni][2 * h + 1]);
                }
            }
        return;
    }
    if (mode != 2) {
#pragma unroll
        for (int mi = 0; mi < 4; mi++)
#pragma unroll
            for (int h = 0; h < 2; h++) {
                int r = row0 + warpM * 64 + mi * 16 + tq + 8 * h;
#pragma unroll
                for (int ni = 0; ni < 4; ni++) {
                    int c = col0 + warpN * 32 + ni * 8 + 2 * tr;
                    float v0 = acc[mi][ni][2 * h]     + bias[c];
                    float v1 = acc[mi][ni][2 * h + 1] + bias[c + 1];
                    if (mode == 1) { v0 = fmaxf(v0, 0.f); v1 = fmaxf(v1, 0.f); }
                    *(float2*)&C[(size_t)r * Nc + c] = make_float2(v0, v1);
                }
            }
        return;
    }

    // mode 2: bias + residual + LayerNorm over 128-wide rows (col0 == 0)
    // reduction buffers live in the (now dead) stage memory
    float* red  = dsm;                  // [128][17]
    float* stat = dsm + 128 * 17;       // [128]
#pragma unroll
    for (int mi = 0; mi < 4; mi++)
#pragma unroll
        for (int h = 0; h < 2; h++) {
            int r = row0 + warpM * 64 + mi * 16 + tq + 8 * h;
#pragma unroll
            for (int ni = 0; ni < 4; ni++) {
                int c = warpN * 32 + ni * 8 + 2 * tr;
                float2 rv = *(const float2*)&res[(size_t)r * 128 + c];
                acc[mi][ni][2 * h]     += bias[c]     + rv.x;
                acc[mi][ni][2 * h + 1] += bias[c + 1] + rv.y;
            }
        }
    __syncthreads();   // all warps done with stage smem before reuse
    int cid = warpN * 4 + tr;      // 16 column-contributors per row
#pragma unroll
    for (int mi = 0; mi < 4; mi++)
#pragma unroll
        for (int h = 0; h < 2; h++) {
            int rl = warpM * 64 + mi * 16 + tq + 8 * h;
            float s = 0.f;
#pragma unroll
            for (int ni = 0; ni < 4; ni++) s += acc[mi][ni][2 * h] + acc[mi][ni][2 * h + 1];
            red[rl * 17 + cid] = s;
        }
    __syncthreads();
    if (tid < 128) {
        float s = 0.f;
#pragma unroll
        for (int t = 0; t < 16; t++) s += red[tid * 17 + t];
        stat[tid] = s * (1.f / 128.f);
    }
    __syncthreads();
    float mean[4][2];
#pragma unroll
    for (int mi = 0; mi < 4; mi++)
#pragma unroll
        for (int h = 0; h < 2; h++)
            mean[mi][h] = stat[warpM * 64 + mi * 16 + tq + 8 * h];
    __syncthreads();
#pragma unroll
    for (int mi = 0; mi < 4; mi++)
#pragma unroll
        for (int h = 0; h < 2; h++) {
            int rl = warpM * 64 + mi * 16 + tq + 8 * h;
            float s = 0.f;
#pragma unroll
            for (int ni = 0; ni < 4; ni++) {
                float d0 = acc[mi][ni][2 * h]     - mean[mi][h];
                float d1 = acc[mi][ni][2 * h + 1] - mean[mi][h];
                s += d0 * d0 + d1 * d1;
            }
            red[rl * 17 + cid] = s;
        }
    __syncthreads();
    if (tid < 128) {
        float s = 0.f;
#pragma unroll
        for (int t = 0; t < 16; t++) s += red[tid * 17 + t];
        stat[tid] = rsqrtf(s * (1.f / 128.f) + EPSV);
    }
    __syncthreads();
#pragma unroll
    for (int mi = 0; mi < 4; mi++)
#pragma unroll
        for (int h = 0; h < 2; h++) {
            int rl = warpM * 64 + mi * 16 + tq + 8 * h;
            int r = row0 + rl;
            float rs = stat[rl];
#pragma unroll
            for (int ni = 0; ni < 4; ni++) {
                int c = warpN * 32 + ni * 8 + 2 * tr;
                float v0 = (acc[mi][ni][2 * h]     - mean[mi][h]) * rs * lng[c]     + lnb[c];
                float v1 = (acc[mi][ni][2 * h + 1] - mean[mi][h]) * rs * lng[c + 1] + lnb[c + 1];
                *(float2*)&C[(size_t)r * 128 + c] = make_float2(v0, v1);
            }
        }
#undef ASS
#undef BSS
}

// ======== tensor-core attention: one CTA per (seq, head), 256 threads ======
#define ATTN_SMEM_FLOATS (128 * 132 + 32 * 132)
#define ATTN_SMEM_BYTES  (ATTN_SMEM_FLOATS * 4)

__global__ __launch_bounds__(256)
void attn_mma_kernel(const float* __restrict__ qkv, float* __restrict__ out)
{
    extern __shared__ float smf[];
    float (*qs)[36]  = (float(*)[36])smf;
    float (*ks)[36]  = (float(*)[36])(smf + 128 * 36);
    float (*sp)[132] = (float(*)[132])smf;
    float (*vt)[132] = (float(*)[132])(smf + 128 * 132);

    int s  = blockIdx.x >> 2;
    int hh = blockIdx.x & 3;
    int tid = threadIdx.x;
    int lane = tid & 31, warp = tid >> 5;
    int tq = lane >> 2, tr = lane & 3;
    int warpM = warp & 1, warpN = warp >> 1;     // 2 x 4

    for (int idx = tid; idx < 7 * 36; idx += 256) {
        int r = 121 + idx / 36, c = idx % 36;
        qs[r][c] = 0.f;
        ks[r][c] = 0.f;
    }
    for (int idx = tid; idx < 32 * 7; idx += 256) {
        int d = idx / 7, c = 121 + idx % 7;
        vt[d][c] = 0.f;
    }

    const float* base = qkv + (size_t)s * NT * 384 + hh * HDH;
    for (int idx = tid; idx < NT * 8; idx += 256) {
        int n = idx >> 3, d4 = (idx & 7) * 4;
        const float* bp = base + (size_t)n * 384 + d4;
        float4 qv = *(const float4*)(bp);
        float4 kv = *(const float4*)(bp + 128);
        float4 vv = *(const float4*)(bp + 256);
        *(float4*)&qs[n][d4] = qv;
        *(float4*)&ks[n][d4] = kv;
        vt[d4 + 0][n] = vv.x;
        vt[d4 + 1][n] = vv.y;
        vt[d4 + 2][n] = vv.z;
        vt[d4 + 3][n] = vv.w;
    }
    __syncthreads();

    // ---- S = Q @ K^T  (128x128x32) ----
    float acc[4][4][4] = {};
#pragma unroll
    for (int k8 = 0; k8 < 32; k8 += 8) {
        uint32_t af[4][4], bf[4][2];
#pragma unroll
        for (int mi = 0; mi < 4; mi++) {
            int ar = warpM * 64 + mi * 16 + tq;
            af[mi][0] = __float_as_uint(qs[ar    ][k8 + tr    ]);
            af[mi][1] = __float_as_uint(qs[ar + 8][k8 + tr    ]);
            af[mi][2] = __float_as_uint(qs[ar    ][k8 + tr + 4]);
            af[mi][3] = __float_as_uint(qs[ar + 8][k8 + tr + 4]);
        }
#pragma unroll
        for (int ni = 0; ni < 4; ni++) {
            int br = warpN * 32 + ni * 8 + tq;
            bf[ni][0] = __float_as_uint(ks[br][k8 + tr    ]);
            bf[ni][1] = __float_as_uint(ks[br][k8 + tr + 4]);
        }
#pragma unroll
        for (int mi = 0; mi < 4; mi++)
#pragma unroll
            for (int ni = 0; ni < 4; ni++)
                mma_tf32(acc[mi][ni], af[mi][0], af[mi][1], af[mi][2], af[mi][3],
                         bf[ni][0], bf[ni][1]);
    }
    __syncthreads();   // everyone done reading qs/ks before sp overwrites them

#pragma unroll
    for (int mi = 0; mi < 4; mi++)
#pragma unroll
        for (int h = 0; h < 2; h++) {
            int r = warpM * 64 + mi * 16 + tq + 8 * h;
#pragma unroll
            for (int ni = 0; ni < 4; ni++) {
                int c = warpN * 32 + ni * 8 + 2 * tr;
                *(float2*)&sp[r][c] = make_float2(acc[mi][ni][2 * h], acc[mi][ni][2 * h + 1]);
            }
        }
    __syncthreads();

    // ---- softmax over rows (scale folded into exp); mask cols >= NT ----
    const float scale = 0.17677669529663687f;   // 1/sqrt(32)
    if (tid < 128) {
        float mx = -1e30f;
        for (int c = 0; c < NT; c++) mx = fmaxf(mx, sp[tid][c]);
        float sum = 0.f;
        for (int c = 0; c < NT; c++) {
            float e = __expf((sp[tid][c] - mx) * scale);
            sp[tid][c] = e;
            sum += e;
        }
        float inv = 1.f / sum;
        for (int c = 0; c < NT; c++) sp[tid][c] *= inv;
#pragma unroll
        for (int c = NT; c < 128; c++) sp[tid][c] = 0.f;
    }
    __syncthreads();

    // ---- O = P @ V   (128x32x128), V^T in vt[dim][key] ----
    float pacc[4][4] = {};
#pragma unroll
    for (int k8 = 0; k8 < 128; k8 += 8) {
        uint32_t af[4][4], bf[2];
#pragma unroll
        for (int mi = 0; mi < 4; mi++) {
            int ar = warpM * 64 + mi * 16 + tq;
            af[mi][0] = __float_as_uint(sp[ar    ][k8 + tr    ]);
            af[mi][1] = __float_as_uint(sp[ar + 8][k8 + tr    ]);
            af[mi][2] = __float_as_uint(sp[ar    ][k8 + tr + 4]);
            af[mi][3] = __float_as_uint(sp[ar + 8][k8 + tr + 4]);
        }
        int bn = warpN * 8 + tq;
        bf[0] = __float_as_uint(vt[bn][k8 + tr    ]);
        bf[1] = __float_as_uint(vt[bn][k8 + tr + 4]);
#pragma unroll
        for (int mi = 0; mi < 4; mi++)
            mma_tf32(pacc[mi], af[mi][0], af[mi][1], af[mi][2], af[mi][3],
                     bf[0], bf[1]);
    }

#pragma unroll
    for (int mi = 0; mi < 4; mi++)
#pragma unroll
        for (int h = 0; h < 2; h++) {
            int r = warpM * 64 + mi * 16 + tq + 8 * h;
            if (r < NT) {
                int c = warpN * 8 + 2 * tr;
                *(float2*)&out[((size_t)s * NT + r) * HDIM + hh * HDH + c] =
                    make_float2(pacc[mi][2 * h], pacc[mi][2 * h + 1]);
            }
        }
}

// ------- final: reduce split-K partials + bias + LayerNorm over 256 -------
__global__ void out_ln_kernel(const float* __restrict__ part,
                              const float* __restrict__ b_out,
                              const float* __restrict__ g,
                              const float* __restrict__ b,
                              float* __restrict__ out)
{
    int row = blockIdx.x, t = threadIdx.x;  // 256 threads
    size_t idx = (size_t)row * OUTD + t;
    float v = b_out[t];
#pragma unroll
    for (int z = 0; z < SPLITK; z++) v += part[(size_t)z * SEQ * OUTD + idx];
    __shared__ float red[9];
    int lane = t & 31, warp = t >> 5;
    float s = v;
#pragma unroll
    for (int o = 16; o; o >>= 1) s += __shfl_xor_sync(0xffffffffu, s, o);
    if (lane == 0) red[warp] = s;
    __syncthreads();
    if (t == 0) { float tot = 0; for (int i = 0; i < 8; i++) tot += red[i]; red[8] = tot; }
    __syncthreads();
    float mean = red[8] * (1.f / 256.f);
    float d = v - mean;
    float s2 = d * d;
#pragma unroll
    for (int o = 16; o; o >>= 1) s2 += __shfl_xor_sync(0xffffffffu, s2, o);
    __syncthreads();
    if (lane == 0) red[warp] = s2;
    __syncthreads();
    if (t == 0) { float tot = 0; for (int i = 0; i < 8; i++) tot += red[i]; red[8] = tot; }
    __syncthreads();
    float var = red[8] * (1.f / 256.f);
    out[idx] = d * rsqrtf(var + EPSV) * g[t] + b[t];
}

// ---------------- launch ---------------------------------------------------
extern "C" void kernel_launch(void* const* d_in, const int* in_sizes, int n_in,
                              void* d_out, int out_size)
{
    const float* forest = (const float*)d_in[0];
    const int*   perm   = (const int*)  d_in[2];
    const float* w_in   = (const float*)d_in[3];
    const float* b_in   = (const float*)d_in[4];
    const float* qkv_w  = (const float*)d_in[5];
    const float* qkv_b  = (const float*)d_in[6];
    const float* proj_w = (const float*)d_in[7];
    const float* proj_b = (const float*)d_in[8];
    const float* ff1_w  = (const float*)d_in[9];
    const float* ff1_b  = (const float*)d_in[10];
    const float* ff2_w  = (const float*)d_in[11];
    const float* ff2_b  = (const float*)d_in[12];
    const float* ln1_g  = (const float*)d_in[13];
    const float* ln1_b  = (const float*)d_in[14];
    const float* ln2_g  = (const float*)d_in[15];
    const float* ln2_b  = (const float*)d_in[16];
    const float* w_out  = (const float*)d_in[17];
    const float* b_out  = (const float*)d_in[18];
    const float* lnf_g  = (const float*)d_in[19];
    const float* lnf_b  = (const float*)d_in[20];

    float *xb, *qb, *ab, *hb, *pb;
    cudaGetSymbolAddress((void**)&xb, g_x);
    cudaGetSymbolAddress((void**)&qb, g_qkv);
    cudaGetSymbolAddress((void**)&ab, g_att);
    cudaGetSymbolAddress((void**)&hb, g_h);
    cudaGetSymbolAddress((void**)&pb, g_py);

    cudaFuncSetAttribute(gemm_tf32_kernel,
                         cudaFuncAttributeMaxDynamicSharedMemorySize, GEMM_DYN_BYTES);
    cudaFuncSetAttribute(attn_mma_kernel,
                         cudaFuncAttributeMaxDynamicSharedMemorySize, ATTN_SMEM_BYTES);

    embed_kernel<<<MTOK / 16, 128>>>(forest, perm, w_in, b_in, xb);

    const int GR = MTOK / 128;  // 1936
    for (int l = 0; l < 2; l++) {
        gemm_tf32_kernel<<<dim3(3, GR), 256, GEMM_DYN_BYTES>>>(
            xb, qkv_w + (size_t)l * 384 * 128, qkv_b + l * 384,
            nullptr, nullptr, nullptr, qb, MTOK, 384, 128, 128, 0);
        attn_mma_kernel<<<SEQ * NHEAD, 256, ATTN_SMEM_BYTES>>>(qb, ab);
        gemm_tf32_kernel<<<dim3(1, GR), 256, GEMM_DYN_BYTES>>>(
            ab, proj_w + (size_t)l * 128 * 128, proj_b + l * 128,
            xb, ln1_g + l * 128, ln1_b + l * 128, xb, MTOK, 128, 128, 128, 2);
        gemm_tf32_kernel<<<dim3(1, GR), 256, GEMM_DYN_BYTES>>>(
            xb, ff1_w + (size_t)l * 128 * 128, ff1_b + l * 128,
            nullptr, nullptr, nullptr, hb, MTOK, 128, 128, 128, 1);
        gemm_tf32_kernel<<<dim3(1, GR), 256, GEMM_DYN_BYTES>>>(
            hb, ff2_w + (size_t)l * 128 * 128, ff2_b + l * 128,
            xb, ln2_g + l * 128, ln2_b + l * 128, xb, MTOK, 128, 128, 128, 2);
    }

    // output projection: split-K = 11 in one launch (15488 = 11 * 1408)
    gemm_tf32_kernel<<<dim3(OUTD / 128, SEQ / 128, SPLITK), 256, GEMM_DYN_BYTES>>>(
        xb, w_out, nullptr, nullptr, nullptr, nullptr,
        pb, SEQ, OUTD, KBIG, KBIG / SPLITK, 3);
    out_ln_kernel<<<SEQ, 256>>>(pb, b_out, lnf_g, lnf_b, (float*)d_out);
}

// round 11
// speedup vs baseline: 3.5338x; 1.0876x over previous
#include <cuda_runtime.h>
#include <cstdint>

#define SEQ   2048          // B*A
#define NT    121           // tokens
#define HDIM  128           // hidden
#define FIND  12            // feature in
#define NHEAD 4
#define HDH   32            // head dim
#define OUTD  256
#define MTOK  (SEQ*NT)      // 247808
#define KBIG  (NT*HDIM)     // 15488
#define SPLITK 11
#define NSTG  3
#define STGF  (128 * 20)
#define EPSV  1e-5f

// ---------------- scratch (device globals; no allocation allowed) ----------
__device__ float g_x  [(size_t)MTOK * HDIM];
__device__ float g_qkv[(size_t)MTOK * 384];
__device__ float g_att[(size_t)MTOK * HDIM];
__device__ float g_py [(size_t)SPLITK * SEQ * OUTD];

__device__ __forceinline__ void cpasync16(uint32_t dst, const float* src) {
    asm volatile("cp.async.cg.shared.global [%0], [%1], 16;" :: "r"(dst), "l"(src));
}
__device__ __forceinline__ uint32_t smem_u32(const void* p) {
    uint32_t a;
    asm("{ .reg .u64 t; cvta.to.shared.u64 t, %1; cvt.u32.u64 %0, t; }" : "=r"(a) : "l"(p));
    return a;
}

__device__ __forceinline__ void mma_tf32(float c[4], uint32_t a0, uint32_t a1,
                                         uint32_t a2, uint32_t a3,
                                         uint32_t b0, uint32_t b1) {
    asm volatile(
        "mma.sync.aligned.m16n8k8.row.col.f32.tf32.tf32.f32 "
        "{%0,%1,%2,%3},{%4,%5,%6,%7},{%8,%9},{%0,%1,%2,%3};\n"
        : "+f"(c[0]), "+f"(c[1]), "+f"(c[2]), "+f"(c[3])
        : "r"(a0), "r"(a1), "r"(a2), "r"(a3), "r"(b0), "r"(b1));
}

// ---------------- embed: 16 tokens per CTA, 128 threads --------------------
__global__ void embed_kernel(const float* __restrict__ forest,
                             const int*   __restrict__ perm,
                             const float* __restrict__ w_in,
                             const float* __restrict__ b_in,
                             float* __restrict__ out)
{
    int t0 = blockIdx.x * 16;
    int h = threadIdx.x;               // 128
    float w[FIND];
#pragma unroll
    for (int k = 0; k < FIND; k++) w[k] = w_in[h * FIND + k];
    float bh = b_in[h];
#pragma unroll 1
    for (int j = 0; j < 16; j++) {
        int tok = t0 + j;
        int s = tok / NT, i = tok - s * NT;
        int node = __ldg(&perm[i]);
        const float* f = forest + ((size_t)s * NT + node) * FIND;
        float acc = bh;
#pragma unroll
        for (int k = 0; k < FIND; k++) acc += __ldg(&f[k]) * w[k];
        if (h < 12) {
            int mask = 0, cur = node;
            while (cur > 0) {
                int d = (cur >= 40) ? 4 : (cur >= 13) ? 3 : (cur >= 4) ? 2 : 1;
                int br = (cur - 1) % 3;
                mask |= 1 << ((d - 1) * 3 + br);
                cur = (cur - 1) / 3;
            }
            acc += (float)((mask >> h) & 1);
        }
        out[(size_t)tok * HDIM + h] = acc;
    }
}

// ============ TF32 tensor-core GEMM: C = X[M,K] @ W[Nc,K]^T + epilogue =====
// CTA 128x128, BK=16 x 3-stage cp.async pipeline, register-double-buffered
// fragments, 8 warps (64x32 warp tiles).  (proven R9 config)
// mode 0: +bias    mode 1: +bias,relu    mode 2: +bias+res, LayerNorm (Nc=128)
// mode 3: raw partial store (split-K over blockIdx.z; kstart = z*kchunk)
struct EpiSmem { float red[128][17]; float stat[128]; };
struct MmSmem  { float As[NSTG][128][20]; float Bs[NSTG][128][20]; };

__global__ __launch_bounds__(256, 2)
void gemm_tf32_kernel(const float* __restrict__ X, const float* __restrict__ W,
                      const float* __restrict__ bias, const float* __restrict__ res,
                      const float* __restrict__ lng, const float* __restrict__ lnb,
                      float* __restrict__ C, int M, int Nc, int K,
                      int kchunk, int mode)
{
    __shared__ union { MmSmem mm; EpiSmem ep; } sm;
    int tid = threadIdx.x;
    int lane = tid & 31, warp = tid >> 5;
    int tq = lane >> 2, tr = lane & 3;
    int warpM = warp & 1, warpN = warp >> 1;          // 2 x 4 warps
    int row0 = blockIdx.y * 128, col0 = blockIdx.x * 128;
    int kstart = blockIdx.z * kchunk;
    if (mode == 3) C += (size_t)blockIdx.z * M * Nc;

    int glr = tid >> 1;
    int glc = (tid & 1) * 8;
    const float* Xp = X + (size_t)(row0 + glr) * K + kstart + glc;
    const float* Wp = W + (size_t)(col0 + glr) * K + kstart + glc;
    uint32_t sa = smem_u32(&sm.mm.As[0][glr][glc]);
    uint32_t sb = smem_u32(&sm.mm.Bs[0][glr][glc]);
    const uint32_t STGB = STGF * 4;

    int nk16 = kchunk >> 4;

#pragma unroll
    for (int s = 0; s < NSTG - 1; s++) {
        if (s < nk16) {
            uint32_t so = (uint32_t)s * STGB;
            const float* xp = Xp + s * 16;
            const float* wp = Wp + s * 16;
            cpasync16(sa + so, xp);       cpasync16(sa + so + 16, xp + 4);
            cpasync16(sb + so, wp);       cpasync16(sb + so + 16, wp + 4);
        }
        asm volatile("cp.async.commit_group;");
    }
    asm volatile("cp.async.wait_group %0;" :: "n"(NSTG - 2));
    __syncthreads();

    float acc[4][4][4] = {};
    uint32_t af[2][4][4], bf[2][4][2];
    int arow = warpM * 64 + tq;
    int brow = warpN * 32 + tq;

#pragma unroll
    for (int mi = 0; mi < 4; mi++) {
        af[0][mi][0] = __float_as_uint(sm.mm.As[0][arow + mi * 16    ][tr    ]);
        af[0][mi][1] = __float_as_uint(sm.mm.As[0][arow + mi * 16 + 8][tr    ]);
        af[0][mi][2] = __float_as_uint(sm.mm.As[0][arow + mi * 16    ][tr + 4]);
        af[0][mi][3] = __float_as_uint(sm.mm.As[0][arow + mi * 16 + 8][tr + 4]);
    }
#pragma unroll
    for (int ni = 0; ni < 4; ni++) {
        bf[0][ni][0] = __float_as_uint(sm.mm.Bs[0][brow + ni * 8][tr    ]);
        bf[0][ni][1] = __float_as_uint(sm.mm.Bs[0][brow + ni * 8][tr + 4]);
    }

    int buf = 0, wslot = NSTG - 1;
    for (int kt = 0; kt < nk16; kt++) {
#pragma unroll
        for (int mi = 0; mi < 4; mi++) {
            af[1][mi][0] = __float_as_uint(sm.mm.As[buf][arow + mi * 16    ][8 + tr    ]);
            af[1][mi][1] = __float_as_uint(sm.mm.As[buf][arow + mi * 16 + 8][8 + tr    ]);
            af[1][mi][2] = __float_as_uint(sm.mm.As[buf][arow + mi * 16    ][8 + tr + 4]);
            af[1][mi][3] = __float_as_uint(sm.mm.As[buf][arow + mi * 16 + 8][8 + tr + 4]);
        }
#pragma unroll
        for (int ni = 0; ni < 4; ni++) {
            bf[1][ni][0] = __float_as_uint(sm.mm.Bs[buf][brow + ni * 8][8 + tr    ]);
            bf[1][ni][1] = __float_as_uint(sm.mm.Bs[buf][brow + ni * 8][8 + tr + 4]);
        }
#pragma unroll
        for (int mi = 0; mi < 4; mi++)
#pragma unroll
            for (int ni = 0; ni < 4; ni++)
                mma_tf32(acc[mi][ni], af[0][mi][0], af[0][mi][1],
                         af[0][mi][2], af[0][mi][3],
                         bf[0][ni][0], bf[0][ni][1]);
        int snext = kt + NSTG - 1;
        if (snext < nk16) {
            uint32_t so = (uint32_t)wslot * STGB;
            const float* xp = Xp + snext * 16;
            const float* wp = Wp + snext * 16;
            cpasync16(sa + so, xp);       cpasync16(sa + so + 16, xp + 4);
            cpasync16(sb + so, wp);       cpasync16(sb + so + 16, wp + 4);
        }
        asm volatile("cp.async.commit_group;");
        asm volatile("cp.async.wait_group %0;" :: "n"(NSTG - 2));
        __syncthreads();
        if (++wslot == NSTG) wslot = 0;
        int nb = buf + 1; if (nb == NSTG) nb = 0;
        if (kt + 1 < nk16) {
#pragma unroll
            for (int mi = 0; mi < 4; mi++) {
                af[0][mi][0] = __float_as_uint(sm.mm.As[nb][arow + mi * 16    ][tr    ]);
                af[0][mi][1] = __float_as_uint(sm.mm.As[nb][arow + mi * 16 + 8][tr    ]);
                af[0][mi][2] = __float_as_uint(sm.mm.As[nb][arow + mi * 16    ][tr + 4]);
                af[0][mi][3] = __float_as_uint(sm.mm.As[nb][arow + mi * 16 + 8][tr + 4]);
            }
#pragma unroll
            for (int ni = 0; ni < 4; ni++) {
                bf[0][ni][0] = __float_as_uint(sm.mm.Bs[nb][brow + ni * 8][tr    ]);
                bf[0][ni][1] = __float_as_uint(sm.mm.Bs[nb][brow + ni * 8][tr + 4]);
            }
        }
#pragma unroll
        for (int mi = 0; mi < 4; mi++)
#pragma unroll
            for (int ni = 0; ni < 4; ni++)
                mma_tf32(acc[mi][ni], af[1][mi][0], af[1][mi][1],
                         af[1][mi][2], af[1][mi][3],
                         bf[1][ni][0], bf[1][ni][1]);
        buf = nb;
    }

    if (mode == 3) {
#pragma unroll
        for (int mi = 0; mi < 4; mi++)
#pragma unroll
            for (int h = 0; h < 2; h++) {
                int r = row0 + warpM * 64 + mi * 16 + tq + 8 * h;
#pragma unroll
                for (int ni = 0; ni < 4; ni++) {
                    int c = col0 + warpN * 32 + ni * 8 + 2 * tr;
                    *(float2*)&C[(size_t)r * Nc + c] =
                        make_float2(acc[mi][ni][2 * h], acc[mi][ni][2 * h + 1]);
                }
            }
        return;
    }
    if (mode != 2) {
#pragma unroll
        for (int mi = 0; mi < 4; mi++)
#pragma unroll
            for (int h = 0; h < 2; h++) {
                int r = row0 + warpM * 64 + mi * 16 + tq + 8 * h;
#pragma unroll
                for (int ni = 0; ni < 4; ni++) {
                    int c = col0 + warpN * 32 + ni * 8 + 2 * tr;
                    float v0 = acc[mi][ni][2 * h]     + bias[c];
                    float v1 = acc[mi][ni][2 * h + 1] + bias[c + 1];
                    if (mode == 1) { v0 = fmaxf(v0, 0.f); v1 = fmaxf(v1, 0.f); }
                    *(float2*)&C[(size_t)r * Nc + c] = make_float2(v0, v1);
                }
            }
        return;
    }

    // mode 2: bias + residual + LayerNorm over 128-wide rows (col0 == 0)
#pragma unroll
    for (int mi = 0; mi < 4; mi++)
#pragma unroll
        for (int h = 0; h < 2; h++) {
            int r = row0 + warpM * 64 + mi * 16 + tq + 8 * h;
#pragma unroll
            for (int ni = 0; ni < 4; ni++) {
                int c = warpN * 32 + ni * 8 + 2 * tr;
                float2 rv = *(const float2*)&res[(size_t)r * 128 + c];
                acc[mi][ni][2 * h]     += bias[c]     + rv.x;
                acc[mi][ni][2 * h + 1] += bias[c + 1] + rv.y;
            }
        }
    __syncthreads();
    int cid = warpN * 4 + tr;
#pragma unroll
    for (int mi = 0; mi < 4; mi++)
#pragma unroll
        for (int h = 0; h < 2; h++) {
            int rl = warpM * 64 + mi * 16 + tq + 8 * h;
            float s = 0.f;
#pragma unroll
            for (int ni = 0; ni < 4; ni++) s += acc[mi][ni][2 * h] + acc[mi][ni][2 * h + 1];
            sm.ep.red[rl][cid] = s;
        }
    __syncthreads();
    if (tid < 128) {
        float s = 0.f;
#pragma unroll
        for (int t = 0; t < 16; t++) s += sm.ep.red[tid][t];
        sm.ep.stat[tid] = s * (1.f / 128.f);
    }
    __syncthreads();
    float mean[4][2];
#pragma unroll
    for (int mi = 0; mi < 4; mi++)
#pragma unroll
        for (int h = 0; h < 2; h++)
            mean[mi][h] = sm.ep.stat[warpM * 64 + mi * 16 + tq + 8 * h];
    __syncthreads();
#pragma unroll
    for (int mi = 0; mi < 4; mi++)
#pragma unroll
        for (int h = 0; h < 2; h++) {
            int rl = warpM * 64 + mi * 16 + tq + 8 * h;
            float s = 0.f;
#pragma unroll
            for (int ni = 0; ni < 4; ni++) {
                float d0 = acc[mi][ni][2 * h]     - mean[mi][h];
                float d1 = acc[mi][ni][2 * h + 1] - mean[mi][h];
                s += d0 * d0 + d1 * d1;
            }
            sm.ep.red[rl][cid] = s;
        }
    __syncthreads();
    if (tid < 128) {
        float s = 0.f;
#pragma unroll
        for (int t = 0; t < 16; t++) s += sm.ep.red[tid][t];
        sm.ep.stat[tid] = rsqrtf(s * (1.f / 128.f) + EPSV);
    }
    __syncthreads();
#pragma unroll
    for (int mi = 0; mi < 4; mi++)
#pragma unroll
        for (int h = 0; h < 2; h++) {
            int rl = warpM * 64 + mi * 16 + tq + 8 * h;
            int r = row0 + rl;
            float rs = sm.ep.stat[rl];
#pragma unroll
            for (int ni = 0; ni < 4; ni++) {
                int c = warpN * 32 + ni * 8 + 2 * tr;
                float v0 = (acc[mi][ni][2 * h]     - mean[mi][h]) * rs * lng[c]     + lnb[c];
                float v1 = (acc[mi][ni][2 * h + 1] - mean[mi][h]) * rs * lng[c + 1] + lnb[c + 1];
                *(float2*)&C[(size_t)r * 128 + c] = make_float2(v0, v1);
            }
        }
}

// ========== fused FFN: x = LN(x + relu(x@W1^T+b1)@W2^T + b2) ==============
// one CTA per 128 rows; phase1 pipelined GEMM, h -> smem, phase2 GEMM from
// smem A with W2 staged through the same B ring. 96 KB dyn smem, 2 CTA/SM.
#define FFN_DYN_BYTES (NSTG * STGF * 4 + 128 * 132 * 4)   // 30720 + 67584

__global__ __launch_bounds__(256, 2)
void ffn_kernel(const float* __restrict__ X,
                const float* __restrict__ W1, const float* __restrict__ b1,
                const float* __restrict__ W2, const float* __restrict__ b2,
                const float* __restrict__ lng, const float* __restrict__ lnb,
                float* __restrict__ C)
{
    extern __shared__ float dsm[];
    float* BsR = dsm;                       // [NSTG][128][20] stage ring
    float* AR  = dsm + NSTG * STGF;         // phase1 A stages; phase2 hs[128][132]
#define FB(s, r, c) BsR[(s) * STGF + (r) * 20 + (c)]
#define FA(s, r, c) AR[(s) * STGF + (r) * 20 + (c)]
#define HS(r, c)    AR[(r) * 132 + (c)]

    int tid = threadIdx.x;
    int lane = tid & 31, warp = tid >> 5;
    int tq = lane >> 2, tr = lane & 3;
    int warpM = warp & 1, warpN = warp >> 1;
    int row0 = blockIdx.x * 128;

    int glr = tid >> 1;
    int glc = (tid & 1) * 8;
    const float* Xp  = X  + (size_t)(row0 + glr) * 128 + glc;
    const float* W1p = W1 + (size_t)glr * 128 + glc;
    const float* W2p = W2 + (size_t)glr * 128 + glc;
    uint32_t sa = smem_u32(&FA(0, glr, glc));
    uint32_t sb = smem_u32(&FB(0, glr, glc));
    const uint32_t STGB = STGF * 4;

    int arow = warpM * 64 + tq;
    int brow = warpN * 32 + tq;
    float acc[4][4][4] = {};
    uint32_t af[2][4][4], bf[2][4][2];

    // ---------------- phase 1: acc = X @ W1^T (nk16 = 8) -------------------
#pragma unroll
    for (int s = 0; s < NSTG - 1; s++) {
        uint32_t so = (uint32_t)s * STGB;
        cpasync16(sa + so, Xp + s * 16);       cpasync16(sa + so + 16, Xp + s * 16 + 4);
        cpasync16(sb + so, W1p + s * 16);      cpasync16(sb + so + 16, W1p + s * 16 + 4);
        asm volatile("cp.async.commit_group;");
    }
    asm volatile("cp.async.wait_group %0;" :: "n"(NSTG - 2));
    __syncthreads();

#pragma unroll
    for (int mi = 0; mi < 4; mi++) {
        af[0][mi][0] = __float_as_uint(FA(0, arow + mi * 16    , tr    ));
        af[0][mi][1] = __float_as_uint(FA(0, arow + mi * 16 + 8, tr    ));
        af[0][mi][2] = __float_as_uint(FA(0, arow + mi * 16    , tr + 4));
        af[0][mi][3] = __float_as_uint(FA(0, arow + mi * 16 + 8, tr + 4));
    }
#pragma unroll
    for (int ni = 0; ni < 4; ni++) {
        bf[0][ni][0] = __float_as_uint(FB(0, brow + ni * 8, tr    ));
        bf[0][ni][1] = __float_as_uint(FB(0, brow + ni * 8, tr + 4));
    }

    int buf = 0, wslot = NSTG - 1;
    for (int kt = 0; kt < 8; kt++) {
#pragma unroll
        for (int mi = 0; mi < 4; mi++) {
            af[1][mi][0] = __float_as_uint(FA(buf, arow + mi * 16    , 8 + tr    ));
            af[1][mi][1] = __float_as_uint(FA(buf, arow + mi * 16 + 8, 8 + tr    ));
            af[1][mi][2] = __float_as_uint(FA(buf, arow + mi * 16    , 8 + tr + 4));
            af[1][mi][3] = __float_as_uint(FA(buf, arow + mi * 16 + 8, 8 + tr + 4));
        }
#pragma unroll
        for (int ni = 0; ni < 4; ni++) {
            bf[1][ni][0] = __float_as_uint(FB(buf, brow + ni * 8, 8 + tr    ));
            bf[1][ni][1] = __float_as_uint(FB(buf, brow + ni * 8, 8 + tr + 4));
        }
#pragma unroll
        for (int mi = 0; mi < 4; mi++)
#pragma unroll
            for (int ni = 0; ni < 4; ni++)
                mma_tf32(acc[mi][ni], af[0][mi][0], af[0][mi][1],
                         af[0][mi][2], af[0][mi][3],
                         bf[0][ni][0], bf[0][ni][1]);
        int snext = kt + NSTG - 1;
        if (snext < 8) {
            uint32_t so = (uint32_t)wslot * STGB;
            cpasync16(sa + so, Xp + snext * 16);   cpasync16(sa + so + 16, Xp + snext * 16 + 4);
            cpasync16(sb + so, W1p + snext * 16);  cpasync16(sb + so + 16, W1p + snext * 16 + 4);
        }
        asm volatile("cp.async.commit_group;");
        asm volatile("cp.async.wait_group %0;" :: "n"(NSTG - 2));
        __syncthreads();
        if (++wslot == NSTG) wslot = 0;
        int nb = buf + 1; if (nb == NSTG) nb = 0;
        if (kt + 1 < 8) {
#pragma unroll
            for (int mi = 0; mi < 4; mi++) {
                af[0][mi][0] = __float_as_uint(FA(nb, arow + mi * 16    , tr    ));
                af[0][mi][1] = __float_as_uint(FA(nb, arow + mi * 16 + 8, tr    ));
                af[0][mi][2] = __float_as_uint(FA(nb, arow + mi * 16    , tr + 4));
                af[0][mi][3] = __float_as_uint(FA(nb, arow + mi * 16 + 8, tr + 4));
            }
#pragma unroll
            for (int ni = 0; ni < 4; ni++) {
                bf[0][ni][0] = __float_as_uint(FB(nb, brow + ni * 8, tr    ));
                bf[0][ni][1] = __float_as_uint(FB(nb, brow + ni * 8, tr + 4));
            }
        }
#pragma unroll
        for (int mi = 0; mi < 4; mi++)
#pragma unroll
            for (int ni = 0; ni < 4; ni++)
                mma_tf32(acc[mi][ni], af[1][mi][0], af[1][mi][1],
                         af[1][mi][2], af[1][mi][3],
                         bf[1][ni][0], bf[1][ni][1]);
        buf = nb;
    }

    // issue phase-2 W2 prologue into B ring slots 0,1 (stage ring all free now)
#pragma unroll
    for (int s = 0; s < NSTG - 1; s++) {
        uint32_t so = (uint32_t)s * STGB;
        cpasync16(sb + so, W2p + s * 16);      cpasync16(sb + so + 16, W2p + s * 16 + 4);
        asm volatile("cp.async.commit_group;");
    }

    // h = relu(acc + b1) -> smem (safe: all FA reads done at last loop barrier)
#pragma unroll
    for (int mi = 0; mi < 4; mi++)
#pragma unroll
        for (int h2 = 0; h2 < 2; h2++) {
            int r = warpM * 64 + mi * 16 + tq + 8 * h2;
#pragma unroll
            for (int ni = 0; ni < 4; ni++) {
                int c = warpN * 32 + ni * 8 + 2 * tr;
                HS(r, c)     = fmaxf(acc[mi][ni][2 * h2]     + b1[c],     0.f);
                HS(r, c + 1) = fmaxf(acc[mi][ni][2 * h2 + 1] + b1[c + 1], 0.f);
            }
        }
    asm volatile("cp.async.wait_group %0;" :: "n"(NSTG - 2));
    __syncthreads();     // hs visible + stage 0 ready for all

    // ---------------- phase 2: acc = h @ W2^T (A from hs) ------------------
#pragma unroll
    for (int mi = 0; mi < 4; mi++)
#pragma unroll
        for (int ni = 0; ni < 4; ni++)
#pragma unroll
            for (int q = 0; q < 4; q++) acc[mi][ni][q] = 0.f;

#pragma unroll
    for (int mi = 0; mi < 4; mi++) {
        af[0][mi][0] = __float_as_uint(HS(arow + mi * 16    , tr    ));
        af[0][mi][1] = __float_as_uint(HS(arow + mi * 16 + 8, tr    ));
        af[0][mi][2] = __float_as_uint(HS(arow + mi * 16    , tr + 4));
        af[0][mi][3] = __float_as_uint(HS(arow + mi * 16 + 8, tr + 4));
    }
#pragma unroll
    for (int ni = 0; ni < 4; ni++) {
        bf[0][ni][0] = __float_as_uint(FB(0, brow + ni * 8, tr    ));
        bf[0][ni][1] = __float_as_uint(FB(0, brow + ni * 8, tr + 4));
    }

    buf = 0; wslot = NSTG - 1;
    for (int kt = 0; kt < 8; kt++) {
        int kb = kt * 16;
#pragma unroll
        for (int mi = 0; mi < 4; mi++) {
            af[1][mi][0] = __float_as_uint(HS(arow + mi * 16    , kb + 8 + tr    ));
            af[1][mi][1] = __float_as_uint(HS(arow + mi * 16 + 8, kb + 8 + tr    ));
            af[1][mi][2] = __float_as_uint(HS(arow + mi * 16    , kb + 8 + tr + 4));
            af[1][mi][3] = __float_as_uint(HS(arow + mi * 16 + 8, kb + 8 + tr + 4));
        }
#pragma unroll
        for (int ni = 0; ni < 4; ni++) {
            bf[1][ni][0] = __float_as_uint(FB(buf, brow + ni * 8, 8 + tr    ));
            bf[1][ni][1] = __float_as_uint(FB(buf, brow + ni * 8, 8 + tr + 4));
        }
#pragma unroll
        for (int mi = 0; mi < 4; mi++)
#pragma unroll
            for (int ni = 0; ni < 4; ni++)
                mma_tf32(acc[mi][ni], af[0][mi][0], af[0][mi][1],
                         af[0][mi][2], af[0][mi][3],
                         bf[0][ni][0], bf[0][ni][1]);
        int snext = kt + NSTG - 1;
        if (snext < 8) {
            uint32_t so = (uint32_t)wslot * STGB;
            cpasync16(sb + so, W2p + snext * 16);  cpasync16(sb + so + 16, W2p + snext * 16 + 4);
        }
        asm volatile("cp.async.commit_group;");
        asm volatile("cp.async.wait_group %0;" :: "n"(NSTG - 2));
        __syncthreads();
        if (++wslot == NSTG) wslot = 0;
        int nb = buf + 1; if (nb == NSTG) nb = 0;
        if (kt + 1 < 8) {
            int kn = (kt + 1) * 16;
#pragma unroll
            for (int mi = 0; mi < 4; mi++) {
                af[0][mi][0] = __float_as_uint(HS(arow + mi * 16    , kn + tr    ));
                af[0][mi][1] = __float_as_uint(HS(arow + mi * 16 + 8, kn + tr    ));
                af[0][mi][2] = __float_as_uint(HS(arow + mi * 16    , kn + tr + 4));
                af[0][mi][3] = __float_as_uint(HS(arow + mi * 16 + 8, kn + tr + 4));
            }
#pragma unroll
            for (int ni = 0; ni < 4; ni++) {
                bf[0][ni][0] = __float_as_uint(FB(nb, brow + ni * 8, tr    ));
                bf[0][ni][1] = __float_as_uint(FB(nb, brow + ni * 8, tr + 4));
            }
        }
#pragma unroll
        for (int mi = 0; mi < 4; mi++)
#pragma unroll
            for (int ni = 0; ni < 4; ni++)
                mma_tf32(acc[mi][ni], af[1][mi][0], af[1][mi][1],
                         af[1][mi][2], af[1][mi][3],
                         bf[1][ni][0], bf[1][ni][1]);
        buf = nb;
    }

    // ---------------- epilogue: + b2 + residual x, then LayerNorm ----------
    float* red  = dsm;                  // [128][17] in dead stage memory
    float* stat = dsm + 128 * 17;
#pragma unroll
    for (int mi = 0; mi < 4; mi++)
#pragma unroll
        for (int h2 = 0; h2 < 2; h2++) {
            int r = row0 + warpM * 64 + mi * 16 + tq + 8 * h2;
#pragma unroll
            for (int ni = 0; ni < 4; ni++) {
                int c = warpN * 32 + ni * 8 + 2 * tr;
                float2 rv = *(const float2*)&X[(size_t)r * 128 + c];
                acc[mi][ni][2 * h2]     += b2[c]     + rv.x;
                acc[mi][ni][2 * h2 + 1] += b2[c + 1] + rv.y;
            }
        }
    __syncthreads();
    int cid = warpN * 4 + tr;
#pragma unroll
    for (int mi = 0; mi < 4; mi++)
#pragma unroll
        for (int h2 = 0; h2 < 2; h2++) {
            int rl = warpM * 64 + mi * 16 + tq + 8 * h2;
            float s = 0.f;
#pragma unroll
            for (int ni = 0; ni < 4; ni++) s += acc[mi][ni][2 * h2] + acc[mi][ni][2 * h2 + 1];
            red[rl * 17 + cid] = s;
        }
    __syncthreads();
    if (tid < 128) {
        float s = 0.f;
#pragma unroll
        for (int t = 0; t < 16; t++) s += red[tid * 17 + t];
        stat[tid] = s * (1.f / 128.f);
    }
    __syncthreads();
    float mean[4][2];
#pragma unroll
    for (int mi = 0; mi < 4; mi++)
#pragma unroll
        for (int h2 = 0; h2 < 2; h2++)
            mean[mi][h2] = stat[warpM * 64 + mi * 16 + tq + 8 * h2];
    __syncthreads();
#pragma unroll
    for (int mi = 0; mi < 4; mi++)
#pragma unroll
        for (int h2 = 0; h2 < 2; h2++) {
            int rl = warpM * 64 + mi * 16 + tq + 8 * h2;
            float s = 0.f;
#pragma unroll
            for (int ni = 0; ni < 4; ni++) {
                float d0 = acc[mi][ni][2 * h2]     - mean[mi][h2];
                float d1 = acc[mi][ni][2 * h2 + 1] - mean[mi][h2];
                s += d0 * d0 + d1 * d1;
            }
            red[rl * 17 + cid] = s;
        }
    __syncthreads();
    if (tid < 128) {
        float s = 0.f;
#pragma unroll
        for (int t = 0; t < 16; t++) s += red[tid * 17 + t];
        stat[tid] = rsqrtf(s * (1.f / 128.f) + EPSV);
    }
    __syncthreads();
#pragma unroll
    for (int mi = 0; mi < 4; mi++)
#pragma unroll
        for (int h2 = 0; h2 < 2; h2++) {
            int rl = warpM * 64 + mi * 16 + tq + 8 * h2;
            int r = row0 + rl;
            float rs = stat[rl];
#pragma unroll
            for (int ni = 0; ni < 4; ni++) {
                int c = warpN * 32 + ni * 8 + 2 * tr;
                float v0 = (acc[mi][ni][2 * h2]     - mean[mi][h2]) * rs * lng[c]     + lnb[c];
                float v1 = (acc[mi][ni][2 * h2 + 1] - mean[mi][h2]) * rs * lng[c + 1] + lnb[c + 1];
                *(float2*)&C[(size_t)r * 128 + c] = make_float2(v0, v1);
            }
        }
#undef FB
#undef FA
#undef HS
}

// ======== tensor-core attention: one CTA per (seq, head), 256 threads ======
#define ATTN_SMEM_FLOATS (128 * 132 + 32 * 132)
#define ATTN_SMEM_BYTES  (ATTN_SMEM_FLOATS * 4)

__global__ __launch_bounds__(256)
void attn_mma_kernel(const float* __restrict__ qkv, float* __restrict__ out)
{
    extern __shared__ float smf[];
    float (*qs)[36]  = (float(*)[36])smf;
    float (*ks)[36]  = (float(*)[36])(smf + 128 * 36);
    float (*sp)[132] = (float(*)[132])smf;
    float (*vt)[132] = (float(*)[132])(smf + 128 * 132);

    int s  = blockIdx.x >> 2;
    int hh = blockIdx.x & 3;
    int tid = threadIdx.x;
    int lane = tid & 31, warp = tid >> 5;
    int tq = lane >> 2, tr = lane & 3;
    int warpM = warp & 1, warpN = warp >> 1;

    for (int idx = tid; idx < 7 * 36; idx += 256) {
        int r = 121 + idx / 36, c = idx % 36;
        qs[r][c] = 0.f;
        ks[r][c] = 0.f;
    }
    for (int idx = tid; idx < 32 * 7; idx += 256) {
        int d = idx / 7, c = 121 + idx % 7;
        vt[d][c] = 0.f;
    }

    const float* base = qkv + (size_t)s * NT * 384 + hh * HDH;
    for (int idx = tid; idx < NT * 8; idx += 256) {
        int n = idx >> 3, d4 = (idx & 7) * 4;
        const float* bp = base + (size_t)n * 384 + d4;
        float4 qv = *(const float4*)(bp);
        float4 kv = *(const float4*)(bp + 128);
        float4 vv = *(const float4*)(bp + 256);
        *(float4*)&qs[n][d4] = qv;
        *(float4*)&ks[n][d4] = kv;
        vt[d4 + 0][n] = vv.x;
        vt[d4 + 1][n] = vv.y;
        vt[d4 + 2][n] = vv.z;
        vt[d4 + 3][n] = vv.w;
    }
    __syncthreads();

    float acc[4][4][4] = {};
#pragma unroll
    for (int k8 = 0; k8 < 32; k8 += 8) {
        uint32_t af[4][4], bf[4][2];
#pragma unroll
        for (int mi = 0; mi < 4; mi++) {
            int ar = warpM * 64 + mi * 16 + tq;
            af[mi][0] = __float_as_uint(qs[ar    ][k8 + tr    ]);
            af[mi][1] = __float_as_uint(qs[ar + 8][k8 + tr    ]);
            af[mi][2] = __float_as_uint(qs[ar    ][k8 + tr + 4]);
            af[mi][3] = __float_as_uint(qs[ar + 8][k8 + tr + 4]);
        }
#pragma unroll
        for (int ni = 0; ni < 4; ni++) {
            int br = warpN * 32 + ni * 8 + tq;
            bf[ni][0] = __float_as_uint(ks[br][k8 + tr    ]);
            bf[ni][1] = __float_as_uint(ks[br][k8 + tr + 4]);
        }
#pragma unroll
        for (int mi = 0; mi < 4; mi++)
#pragma unroll
            for (int ni = 0; ni < 4; ni++)
                mma_tf32(acc[mi][ni], af[mi][0], af[mi][1], af[mi][2], af[mi][3],
                         bf[ni][0], bf[ni][1]);
    }
    __syncthreads();

#pragma unroll
    for (int mi = 0; mi < 4; mi++)
#pragma unroll
        for (int h = 0; h < 2; h++) {
            int r = warpM * 64 + mi * 16 + tq + 8 * h;
#pragma unroll
            for (int ni = 0; ni < 4; ni++) {
                int c = warpN * 32 + ni * 8 + 2 * tr;
                *(float2*)&sp[r][c] = make_float2(acc[mi][ni][2 * h], acc[mi][ni][2 * h + 1]);
            }
        }
    __syncthreads();

    const float scale = 0.17677669529663687f;
    if (tid < 128) {
        float mx = -1e30f;
        for (int c = 0; c < NT; c++) mx = fmaxf(mx, sp[tid][c]);
        float sum = 0.f;
        for (int c = 0; c < NT; c++) {
            float e = __expf((sp[tid][c] - mx) * scale);
            sp[tid][c] = e;
            sum += e;
        }
        float inv = 1.f / sum;
        for (int c = 0; c < NT; c++) sp[tid][c] *= inv;
#pragma unroll
        for (int c = NT; c < 128; c++) sp[tid][c] = 0.f;
    }
    __syncthreads();

    float pacc[4][4] = {};
#pragma unroll
    for (int k8 = 0; k8 < 128; k8 += 8) {
        uint32_t af[4][4], bf[2];
#pragma unroll
        for (int mi = 0; mi < 4; mi++) {
            int ar = warpM * 64 + mi * 16 + tq;
            af[mi][0] = __float_as_uint(sp[ar    ][k8 + tr    ]);
            af[mi][1] = __float_as_uint(sp[ar + 8][k8 + tr    ]);
            af[mi][2] = __float_as_uint(sp[ar    ][k8 + tr + 4]);
            af[mi][3] = __float_as_uint(sp[ar + 8][k8 + tr + 4]);
        }
        int bn = warpN * 8 + tq;
        bf[0] = __float_as_uint(vt[bn][k8 + tr    ]);
        bf[1] = __float_as_uint(vt[bn][k8 + tr + 4]);
#pragma unroll
        for (int mi = 0; mi < 4; mi++)
            mma_tf32(pacc[mi], af[mi][0], af[mi][1], af[mi][2], af[mi][3],
                     bf[0], bf[1]);
    }

#pragma unroll
    for (int mi = 0; mi < 4; mi++)
#pragma unroll
        for (int h = 0; h < 2; h++) {
            int r = warpM * 64 + mi * 16 + tq + 8 * h;
            if (r < NT) {
                int c = warpN * 8 + 2 * tr;
                *(float2*)&out[((size_t)s * NT + r) * HDIM + hh * HDH + c] =
                    make_float2(pacc[mi][2 * h], pacc[mi][2 * h + 1]);
            }
        }
}

// ------- final: reduce split-K partials + bias + LayerNorm over 256 -------
__global__ void out_ln_kernel(const float* __restrict__ part,
                              const float* __restrict__ b_out,
                              const float* __restrict__ g,
                              const float* __restrict__ b,
                              float* __restrict__ out)
{
    int row = blockIdx.x, t = threadIdx.x;
    size_t idx = (size_t)row * OUTD + t;
    float v = b_out[t];
#pragma unroll
    for (int z = 0; z < SPLITK; z++) v += part[(size_t)z * SEQ * OUTD + idx];
    __shared__ float red[9];
    int lane = t & 31, warp = t >> 5;
    float s = v;
#pragma unroll
    for (int o = 16; o; o >>= 1) s += __shfl_xor_sync(0xffffffffu, s, o);
    if (lane == 0) red[warp] = s;
    __syncthreads();
    if (t == 0) { float tot = 0; for (int i = 0; i < 8; i++) tot += red[i]; red[8] = tot; }
    __syncthreads();
    float mean = red[8] * (1.f / 256.f);
    float d = v - mean;
    float s2 = d * d;
#pragma unroll
    for (int o = 16; o; o >>= 1) s2 += __shfl_xor_sync(0xffffffffu, s2, o);
    __syncthreads();
    if (lane == 0) red[warp] = s2;
    __syncthreads();
    if (t == 0) { float tot = 0; for (int i = 0; i < 8; i++) tot += red[i]; red[8] = tot; }
    __syncthreads();
    float var = red[8] * (1.f / 256.f);
    out[idx] = d * rsqrtf(var + EPSV) * g[t] + b[t];
}

// ---------------- launch ---------------------------------------------------
extern "C" void kernel_launch(void* const* d_in, const int* in_sizes, int n_in,
                              void* d_out, int out_size)
{
    const float* forest = (const float*)d_in[0];
    const int*   perm   = (const int*)  d_in[2];
    const float* w_in   = (const float*)d_in[3];
    const float* b_in   = (const float*)d_in[4];
    const float* qkv_w  = (const float*)d_in[5];
    const float* qkv_b  = (const float*)d_in[6];
    const float* proj_w = (const float*)d_in[7];
    const float* proj_b = (const float*)d_in[8];
    const float* ff1_w  = (const float*)d_in[9];
    const float* ff1_b  = (const float*)d_in[10];
    const float* ff2_w  = (const float*)d_in[11];
    const float* ff2_b  = (const float*)d_in[12];
    const float* ln1_g  = (const float*)d_in[13];
    const float* ln1_b  = (const float*)d_in[14];
    const float* ln2_g  = (const float*)d_in[15];
    const float* ln2_b  = (const float*)d_in[16];
    const float* w_out  = (const float*)d_in[17];
    const float* b_out  = (const float*)d_in[18];
    const float* lnf_g  = (const float*)d_in[19];
    const float* lnf_b  = (const float*)d_in[20];

    float *xb, *qb, *ab, *pb;
    cudaGetSymbolAddress((void**)&xb, g_x);
    cudaGetSymbolAddress((void**)&qb, g_qkv);
    cudaGetSymbolAddress((void**)&ab, g_att);
    cudaGetSymbolAddress((void**)&pb, g_py);

    cudaFuncSetAttribute(ffn_kernel,
                         cudaFuncAttributeMaxDynamicSharedMemorySize, FFN_DYN_BYTES);
    cudaFuncSetAttribute(attn_mma_kernel,
                         cudaFuncAttributeMaxDynamicSharedMemorySize, ATTN_SMEM_BYTES);

    embed_kernel<<<MTOK / 16, 128>>>(forest, perm, w_in, b_in, xb);

    const int GR = MTOK / 128;  // 1936
    for (int l = 0; l < 2; l++) {
        gemm_tf32_kernel<<<dim3(3, GR), 256>>>(
            xb, qkv_w + (size_t)l * 384 * 128, qkv_b + l * 384,
            nullptr, nullptr, nullptr, qb, MTOK, 384, 128, 128, 0);
        attn_mma_kernel<<<SEQ * NHEAD, 256, ATTN_SMEM_BYTES>>>(qb, ab);
        gemm_tf32_kernel<<<dim3(1, GR), 256>>>(
            ab, proj_w + (size_t)l * 128 * 128, proj_b + l * 128,
            xb, ln1_g + l * 128, ln1_b + l * 128, xb, MTOK, 128, 128, 128, 2);
        ffn_kernel<<<GR, 256, FFN_DYN_BYTES>>>(
            xb, ff1_w + (size_t)l * 128 * 128, ff1_b + l * 128,
            ff2_w + (size_t)l * 128 * 128, ff2_b + l * 128,
            ln2_g + l * 128, ln2_b + l * 128, xb);
    }

    // output projection: split-K = 11 in one launch (15488 = 11 * 1408)
    gemm_tf32_kernel<<<dim3(OUTD / 128, SEQ / 128, SPLITK), 256>>>(
        xb, w_out, nullptr, nullptr, nullptr, nullptr,
        pb, SEQ, OUTD, KBIG, KBIG / SPLITK, 3);
    out_ln_kernel<<<SEQ, 256>>>(pb, b_out, lnf_g, lnf_b, (float*)d_out);
}

// round 12
// speedup vs baseline: 3.5571x; 1.0066x over previous
#include <cuda_runtime.h>
#include <cstdint>

#define SEQ   2048          // B*A
#define NT    121           // tokens
#define HDIM  128           // hidden
#define FIND  12            // feature in
#define NHEAD 4
#define HDH   32            // head dim
#define OUTD  256
#define MTOK  (SEQ*NT)      // 247808
#define KBIG  (NT*HDIM)     // 15488
#define SPLITK 11
#define NSTG  3
#define STGF  (128 * 20)
#define EPSV  1e-5f

// ---------------- scratch (device globals; no allocation allowed) ----------
__device__ float g_x  [(size_t)MTOK * HDIM];
__device__ float g_qkv[(size_t)MTOK * 384];
__device__ float g_att[(size_t)MTOK * HDIM];
__device__ float g_py [(size_t)SPLITK * SEQ * OUTD];

__device__ __forceinline__ void cpasync16(uint32_t dst, const float* src) {
    asm volatile("cp.async.cg.shared.global [%0], [%1], 16;" :: "r"(dst), "l"(src));
}
__device__ __forceinline__ uint32_t smem_u32(const void* p) {
    uint32_t a;
    asm("{ .reg .u64 t; cvta.to.shared.u64 t, %1; cvt.u32.u64 %0, t; }" : "=r"(a) : "l"(p));
    return a;
}

__device__ __forceinline__ void mma_tf32(float c[4], uint32_t a0, uint32_t a1,
                                         uint32_t a2, uint32_t a3,
                                         uint32_t b0, uint32_t b1) {
    asm volatile(
        "mma.sync.aligned.m16n8k8.row.col.f32.tf32.tf32.f32 "
        "{%0,%1,%2,%3},{%4,%5,%6,%7},{%8,%9},{%0,%1,%2,%3};\n"
        : "+f"(c[0]), "+f"(c[1]), "+f"(c[2]), "+f"(c[3])
        : "r"(a0), "r"(a1), "r"(a2), "r"(a3), "r"(b0), "r"(b1));
}

// ---------------- embed: 16 tokens per CTA, 128 threads --------------------
__global__ void embed_kernel(const float* __restrict__ forest,
                             const int*   __restrict__ perm,
                             const float* __restrict__ w_in,
                             const float* __restrict__ b_in,
                             float* __restrict__ out)
{
    int t0 = blockIdx.x * 16;
    int h = threadIdx.x;               // 128
    float w[FIND];
#pragma unroll
    for (int k = 0; k < FIND; k++) w[k] = w_in[h * FIND + k];
    float bh = b_in[h];
#pragma unroll 1
    for (int j = 0; j < 16; j++) {
        int tok = t0 + j;
        int s = tok / NT, i = tok - s * NT;
        int node = __ldg(&perm[i]);
        const float* f = forest + ((size_t)s * NT + node) * FIND;
        float acc = bh;
#pragma unroll
        for (int k = 0; k < FIND; k++) acc += __ldg(&f[k]) * w[k];
        if (h < 12) {
            int mask = 0, cur = node;
            while (cur > 0) {
                int d = (cur >= 40) ? 4 : (cur >= 13) ? 3 : (cur >= 4) ? 2 : 1;
                int br = (cur - 1) % 3;
                mask |= 1 << ((d - 1) * 3 + br);
                cur = (cur - 1) / 3;
            }
            acc += (float)((mask >> h) & 1);
        }
        out[(size_t)tok * HDIM + h] = acc;
    }
}

// ============ TF32 tensor-core GEMM: C = X[M,K] @ W[Nc,K]^T + epilogue =====
// CTA 128x128, BK=16 x 3-stage cp.async pipeline, register-double-buffered
// fragments, 8 warps (64x32 warp tiles).  (proven R9 config)
// mode 0: +bias    mode 1: +bias,relu    mode 2: +bias+res, LayerNorm (Nc=128)
// mode 3: raw partial store (split-K over blockIdx.z; kstart = z*kchunk)
struct EpiSmem { float red[128][17]; float stat[128]; };
struct MmSmem  { float As[NSTG][128][20]; float Bs[NSTG][128][20]; };

__global__ __launch_bounds__(256, 2)
void gemm_tf32_kernel(const float* __restrict__ X, const float* __restrict__ W,
                      const float* __restrict__ bias, const float* __restrict__ res,
                      const float* __restrict__ lng, const float* __restrict__ lnb,
                      float* __restrict__ C, int M, int Nc, int K,
                      int kchunk, int mode)
{
    __shared__ union { MmSmem mm; EpiSmem ep; } sm;
    int tid = threadIdx.x;
    int lane = tid & 31, warp = tid >> 5;
    int tq = lane >> 2, tr = lane & 3;
    int warpM = warp & 1, warpN = warp >> 1;          // 2 x 4 warps
    int row0 = blockIdx.y * 128, col0 = blockIdx.x * 128;
    int kstart = blockIdx.z * kchunk;
    if (mode == 3) C += (size_t)blockIdx.z * M * Nc;

    int glr = tid >> 1;
    int glc = (tid & 1) * 8;
    const float* Xp = X + (size_t)(row0 + glr) * K + kstart + glc;
    const float* Wp = W + (size_t)(col0 + glr) * K + kstart + glc;
    uint32_t sa = smem_u32(&sm.mm.As[0][glr][glc]);
    uint32_t sb = smem_u32(&sm.mm.Bs[0][glr][glc]);
    const uint32_t STGB = STGF * 4;

    int nk16 = kchunk >> 4;

#pragma unroll
    for (int s = 0; s < NSTG - 1; s++) {
        if (s < nk16) {
            uint32_t so = (uint32_t)s * STGB;
            const float* xp = Xp + s * 16;
            const float* wp = Wp + s * 16;
            cpasync16(sa + so, xp);       cpasync16(sa + so + 16, xp + 4);
            cpasync16(sb + so, wp);       cpasync16(sb + so + 16, wp + 4);
        }
        asm volatile("cp.async.commit_group;");
    }
    asm volatile("cp.async.wait_group %0;" :: "n"(NSTG - 2));
    __syncthreads();

    float acc[4][4][4] = {};
    uint32_t af[2][4][4], bf[2][4][2];
    int arow = warpM * 64 + tq;
    int brow = warpN * 32 + tq;

#pragma unroll
    for (int mi = 0; mi < 4; mi++) {
        af[0][mi][0] = __float_as_uint(sm.mm.As[0][arow + mi * 16    ][tr    ]);
        af[0][mi][1] = __float_as_uint(sm.mm.As[0][arow + mi * 16 + 8][tr    ]);
        af[0][mi][2] = __float_as_uint(sm.mm.As[0][arow + mi * 16    ][tr + 4]);
        af[0][mi][3] = __float_as_uint(sm.mm.As[0][arow + mi * 16 + 8][tr + 4]);
    }
#pragma unroll
    for (int ni = 0; ni < 4; ni++) {
        bf[0][ni][0] = __float_as_uint(sm.mm.Bs[0][brow + ni * 8][tr    ]);
        bf[0][ni][1] = __float_as_uint(sm.mm.Bs[0][brow + ni * 8][tr + 4]);
    }

    int buf = 0, wslot = NSTG - 1;
    for (int kt = 0; kt < nk16; kt++) {
#pragma unroll
        for (int mi = 0; mi < 4; mi++) {
            af[1][mi][0] = __float_as_uint(sm.mm.As[buf][arow + mi * 16    ][8 + tr    ]);
            af[1][mi][1] = __float_as_uint(sm.mm.As[buf][arow + mi * 16 + 8][8 + tr    ]);
            af[1][mi][2] = __float_as_uint(sm.mm.As[buf][arow + mi * 16    ][8 + tr + 4]);
            af[1][mi][3] = __float_as_uint(sm.mm.As[buf][arow + mi * 16 + 8][8 + tr + 4]);
        }
#pragma unroll
        for (int ni = 0; ni < 4; ni++) {
            bf[1][ni][0] = __float_as_uint(sm.mm.Bs[buf][brow + ni * 8][8 + tr    ]);
            bf[1][ni][1] = __float_as_uint(sm.mm.Bs[buf][brow + ni * 8][8 + tr + 4]);
        }
#pragma unroll
        for (int mi = 0; mi < 4; mi++)
#pragma unroll
            for (int ni = 0; ni < 4; ni++)
                mma_tf32(acc[mi][ni], af[0][mi][0], af[0][mi][1],
                         af[0][mi][2], af[0][mi][3],
                         bf[0][ni][0], bf[0][ni][1]);
        int snext = kt + NSTG - 1;
        if (snext < nk16) {
            uint32_t so = (uint32_t)wslot * STGB;
            const float* xp = Xp + snext * 16;
            const float* wp = Wp + snext * 16;
            cpasync16(sa + so, xp);       cpasync16(sa + so + 16, xp + 4);
            cpasync16(sb + so, wp);       cpasync16(sb + so + 16, wp + 4);
        }
        asm volatile("cp.async.commit_group;");
        asm volatile("cp.async.wait_group %0;" :: "n"(NSTG - 2));
        __syncthreads();
        if (++wslot == NSTG) wslot = 0;
        int nb = buf + 1; if (nb == NSTG) nb = 0;
        if (kt + 1 < nk16) {
#pragma unroll
            for (int mi = 0; mi < 4; mi++) {
                af[0][mi][0] = __float_as_uint(sm.mm.As[nb][arow + mi * 16    ][tr    ]);
                af[0][mi][1] = __float_as_uint(sm.mm.As[nb][arow + mi * 16 + 8][tr    ]);
                af[0][mi][2] = __float_as_uint(sm.mm.As[nb][arow + mi * 16    ][tr + 4]);
                af[0][mi][3] = __float_as_uint(sm.mm.As[nb][arow + mi * 16 + 8][tr + 4]);
            }
#pragma unroll
            for (int ni = 0; ni < 4; ni++) {
                bf[0][ni][0] = __float_as_uint(sm.mm.Bs[nb][brow + ni * 8][tr    ]);
                bf[0][ni][1] = __float_as_uint(sm.mm.Bs[nb][brow + ni * 8][tr + 4]);
            }
        }
#pragma unroll
        for (int mi = 0; mi < 4; mi++)
#pragma unroll
            for (int ni = 0; ni < 4; ni++)
                mma_tf32(acc[mi][ni], af[1][mi][0], af[1][mi][1],
                         af[1][mi][2], af[1][mi][3],
                         bf[1][ni][0], bf[1][ni][1]);
        buf = nb;
    }

    if (mode == 3) {
#pragma unroll
        for (int mi = 0; mi < 4; mi++)
#pragma unroll
            for (int h = 0; h < 2; h++) {
                int r = row0 + warpM * 64 + mi * 16 + tq + 8 * h;
#pragma unroll
                for (int ni = 0; ni < 4; ni++) {
                    int c = col0 + warpN * 32 + ni * 8 + 2 * tr;
                    *(float2*)&C[(size_t)r * Nc + c] =
                        make_float2(acc[mi][ni][2 * h], acc[mi][ni][2 * h + 1]);
                }
            }
        return;
    }
    if (mode != 2) {
#pragma unroll
        for (int mi = 0; mi < 4; mi++)
#pragma unroll
            for (int h = 0; h < 2; h++) {
                int r = row0 + warpM * 64 + mi * 16 + tq + 8 * h;
#pragma unroll
                for (int ni = 0; ni < 4; ni++) {
                    int c = col0 + warpN * 32 + ni * 8 + 2 * tr;
                    float v0 = acc[mi][ni][2 * h]     + bias[c];
                    float v1 = acc[mi][ni][2 * h + 1] + bias[c + 1];
                    if (mode == 1) { v0 = fmaxf(v0, 0.f); v1 = fmaxf(v1, 0.f); }
                    *(float2*)&C[(size_t)r * Nc + c] = make_float2(v0, v1);
                }
            }
        return;
    }

    // mode 2: bias + residual + LayerNorm over 128-wide rows (col0 == 0)
#pragma unroll
    for (int mi = 0; mi < 4; mi++)
#pragma unroll
        for (int h = 0; h < 2; h++) {
            int r = row0 + warpM * 64 + mi * 16 + tq + 8 * h;
#pragma unroll
            for (int ni = 0; ni < 4; ni++) {
                int c = warpN * 32 + ni * 8 + 2 * tr;
                float2 rv = *(const float2*)&res[(size_t)r * 128 + c];
                acc[mi][ni][2 * h]     += bias[c]     + rv.x;
                acc[mi][ni][2 * h + 1] += bias[c + 1] + rv.y;
            }
        }
    __syncthreads();
    int cid = warpN * 4 + tr;
#pragma unroll
    for (int mi = 0; mi < 4; mi++)
#pragma unroll
        for (int h = 0; h < 2; h++) {
            int rl = warpM * 64 + mi * 16 + tq + 8 * h;
            float s = 0.f;
#pragma unroll
            for (int ni = 0; ni < 4; ni++) s += acc[mi][ni][2 * h] + acc[mi][ni][2 * h + 1];
            sm.ep.red[rl][cid] = s;
        }
    __syncthreads();
    if (tid < 128) {
        float s = 0.f;
#pragma unroll
        for (int t = 0; t < 16; t++) s += sm.ep.red[tid][t];
        sm.ep.stat[tid] = s * (1.f / 128.f);
    }
    __syncthreads();
    float mean[4][2];
#pragma unroll
    for (int mi = 0; mi < 4; mi++)
#pragma unroll
        for (int h = 0; h < 2; h++)
            mean[mi][h] = sm.ep.stat[warpM * 64 + mi * 16 + tq + 8 * h];
    __syncthreads();
#pragma unroll
    for (int mi = 0; mi < 4; mi++)
#pragma unroll
        for (int h = 0; h < 2; h++) {
            int rl = warpM * 64 + mi * 16 + tq + 8 * h;
            float s = 0.f;
#pragma unroll
            for (int ni = 0; ni < 4; ni++) {
                float d0 = acc[mi][ni][2 * h]     - mean[mi][h];
                float d1 = acc[mi][ni][2 * h + 1] - mean[mi][h];
                s += d0 * d0 + d1 * d1;
            }
            sm.ep.red[rl][cid] = s;
        }
    __syncthreads();
    if (tid < 128) {
        float s = 0.f;
#pragma unroll
        for (int t = 0; t < 16; t++) s += sm.ep.red[tid][t];
        sm.ep.stat[tid] = rsqrtf(s * (1.f / 128.f) + EPSV);
    }
    __syncthreads();
#pragma unroll
    for (int mi = 0; mi < 4; mi++)
#pragma unroll
        for (int h = 0; h < 2; h++) {
            int rl = warpM * 64 + mi * 16 + tq + 8 * h;
            int r = row0 + rl;
            float rs = sm.ep.stat[rl];
#pragma unroll
            for (int ni = 0; ni < 4; ni++) {
                int c = warpN * 32 + ni * 8 + 2 * tr;
                float v0 = (acc[mi][ni][2 * h]     - mean[mi][h]) * rs * lng[c]     + lnb[c];
                float v1 = (acc[mi][ni][2 * h + 1] - mean[mi][h]) * rs * lng[c + 1] + lnb[c + 1];
                *(float2*)&C[(size_t)r * 128 + c] = make_float2(v0, v1);
            }
        }
}

// ========= QKV GEMM with smem-resident A: C[M,384] = X @ W^T + bias =======
// one CTA per 128 rows; x tile (64 KB) loaded once, then 3 column tiles
// stream only W through the B ring (ffn-phase2 structure). 96 KB dyn smem.
#define QKV_DYN_BYTES (128 * 132 * 4 + NSTG * STGF * 4)   // 67584 + 30720

__global__ __launch_bounds__(256, 2)
void qkv_kernel(const float* __restrict__ X, const float* __restrict__ W,
                const float* __restrict__ bias, float* __restrict__ C)
{
    extern __shared__ float dsm[];
    float* Afull = dsm;                     // [128][132]
    float* BsR   = dsm + 128 * 132;         // [NSTG][128][20]
#define QA(r, c)    Afull[(r) * 132 + (c)]
#define QB(s, r, c) BsR[(s) * STGF + (r) * 20 + (c)]

    int tid = threadIdx.x;
    int lane = tid & 31, warp = tid >> 5;
    int tq = lane >> 2, tr = lane & 3;
    int warpM = warp & 1, warpN = warp >> 1;
    int row0 = blockIdx.x * 128;

    // ---- A full load: 128x128 floats = 4096 16B chunks, 16 per thread ----
    uint32_t abase = smem_u32(&QA(0, 0));
    const float* Xb = X + (size_t)row0 * 128;
#pragma unroll
    for (int t = 0; t < 16; t++) {
        int m = tid + t * 256;
        int r = m >> 5, c4 = (m & 31) * 4;
        cpasync16(abase + (uint32_t)(r * 132 + c4) * 4, Xb + r * 128 + c4);
    }
    asm volatile("cp.async.commit_group;");

    int glr = tid >> 1, glc = (tid & 1) * 8;
    uint32_t sb = smem_u32(&QB(0, glr, glc));
    const uint32_t STGB = STGF * 4;

    // B stages for flattened iterations g = 0, 1 (ct=0, kt=g)
#pragma unroll
    for (int s = 0; s < 2; s++) {
        const float* wp = W + (size_t)glr * 128 + s * 16 + glc;
        cpasync16(sb + (uint32_t)s * STGB, wp);
        cpasync16(sb + (uint32_t)s * STGB + 16, wp + 4);
        asm volatile("cp.async.commit_group;");
    }
    asm volatile("cp.async.wait_group 1;");   // A + stage 0 complete
    __syncthreads();

    float acc[4][4][4] = {};
    uint32_t af[2][4][4], bf[2][4][2];
    int arow = warpM * 64 + tq;
    int brow = warpN * 32 + tq;

    // set0 frags for g=0
#pragma unroll
    for (int mi = 0; mi < 4; mi++) {
        af[0][mi][0] = __float_as_uint(QA(arow + mi * 16    , tr    ));
        af[0][mi][1] = __float_as_uint(QA(arow + mi * 16 + 8, tr    ));
        af[0][mi][2] = __float_as_uint(QA(arow + mi * 16    , tr + 4));
        af[0][mi][3] = __float_as_uint(QA(arow + mi * 16 + 8, tr + 4));
    }
#pragma unroll
    for (int ni = 0; ni < 4; ni++) {
        bf[0][ni][0] = __float_as_uint(QB(0, brow + ni * 8, tr    ));
        bf[0][ni][1] = __float_as_uint(QB(0, brow + ni * 8, tr + 4));
    }

    for (int g = 0; g < 24; g++) {
        int kt = g & 7;
        int buf = g % 3;
        int kb = kt * 16;
        // set1 frags (cols +8)
#pragma unroll
        for (int mi = 0; mi < 4; mi++) {
            af[1][mi][0] = __float_as_uint(QA(arow + mi * 16    , kb + 8 + tr    ));
            af[1][mi][1] = __float_as_uint(QA(arow + mi * 16 + 8, kb + 8 + tr    ));
            af[1][mi][2] = __float_as_uint(QA(arow + mi * 16    , kb + 8 + tr + 4));
            af[1][mi][3] = __float_as_uint(QA(arow + mi * 16 + 8, kb + 8 + tr + 4));
        }
#pragma unroll
        for (int ni = 0; ni < 4; ni++) {
            bf[1][ni][0] = __float_as_uint(QB(buf, brow + ni * 8, 8 + tr    ));
            bf[1][ni][1] = __float_as_uint(QB(buf, brow + ni * 8, 8 + tr + 4));
        }
#pragma unroll
        for (int mi = 0; mi < 4; mi++)
#pragma unroll
            for (int ni = 0; ni < 4; ni++)
                mma_tf32(acc[mi][ni], af[0][mi][0], af[0][mi][1],
                         af[0][mi][2], af[0][mi][3],
                         bf[0][ni][0], bf[0][ni][1]);
        // prefetch B stage g+2
        int gn = g + 2;
        if (gn < 24) {
            int ctn = gn >> 3, ktn = gn & 7;
            const float* wp = W + (size_t)(ctn * 128 + glr) * 128 + ktn * 16 + glc;
            uint32_t so = (uint32_t)(gn % 3) * STGB;
            cpasync16(sb + so, wp);   cpasync16(sb + so + 16, wp + 4);
        }
        asm volatile("cp.async.commit_group;");
        asm volatile("cp.async.wait_group 1;");
        __syncthreads();
        // set0 frags for g+1
        if (g + 1 < 24) {
            int k2 = ((g + 1) & 7) * 16;
            int b2 = (g + 1) % 3;
#pragma unroll
            for (int mi = 0; mi < 4; mi++) {
                af[0][mi][0] = __float_as_uint(QA(arow + mi * 16    , k2 + tr    ));
                af[0][mi][1] = __float_as_uint(QA(arow + mi * 16 + 8, k2 + tr    ));
                af[0][mi][2] = __float_as_uint(QA(arow + mi * 16    , k2 + tr + 4));
                af[0][mi][3] = __float_as_uint(QA(arow + mi * 16 + 8, k2 + tr + 4));
            }
#pragma unroll
            for (int ni = 0; ni < 4; ni++) {
                bf[0][ni][0] = __float_as_uint(QB(b2, brow + ni * 8, tr    ));
                bf[0][ni][1] = __float_as_uint(QB(b2, brow + ni * 8, tr + 4));
            }
        }
#pragma unroll
        for (int mi = 0; mi < 4; mi++)
#pragma unroll
            for (int ni = 0; ni < 4; ni++)
                mma_tf32(acc[mi][ni], af[1][mi][0], af[1][mi][1],
                         af[1][mi][2], af[1][mi][3],
                         bf[1][ni][0], bf[1][ni][1]);
        // column-tile epilogue
        if (kt == 7) {
            int ct = g >> 3;
            int cb = ct * 128;
#pragma unroll
            for (int mi = 0; mi < 4; mi++)
#pragma unroll
                for (int h = 0; h < 2; h++) {
                    int r = row0 + warpM * 64 + mi * 16 + tq + 8 * h;
#pragma unroll
                    for (int ni = 0; ni < 4; ni++) {
                        int c = warpN * 32 + ni * 8 + 2 * tr;
                        float v0 = acc[mi][ni][2 * h]     + bias[cb + c];
                        float v1 = acc[mi][ni][2 * h + 1] + bias[cb + c + 1];
                        *(float2*)&C[(size_t)r * 384 + cb + c] = make_float2(v0, v1);
                        acc[mi][ni][2 * h] = 0.f;
                        acc[mi][ni][2 * h + 1] = 0.f;
                    }
                }
        }
    }
#undef QA
#undef QB
}

// ========== fused FFN: x = LN(x + relu(x@W1^T+b1)@W2^T + b2) ==============
#define FFN_DYN_BYTES (NSTG * STGF * 4 + 128 * 132 * 4)   // 30720 + 67584

__global__ __launch_bounds__(256, 2)
void ffn_kernel(const float* __restrict__ X,
                const float* __restrict__ W1, const float* __restrict__ b1,
                const float* __restrict__ W2, const float* __restrict__ b2,
                const float* __restrict__ lng, const float* __restrict__ lnb,
                float* __restrict__ C)
{
    extern __shared__ float dsm[];
    float* BsR = dsm;                       // [NSTG][128][20] stage ring
    float* AR  = dsm + NSTG * STGF;         // phase1 A stages; phase2 hs[128][132]
#define FB(s, r, c) BsR[(s) * STGF + (r) * 20 + (c)]
#define FA(s, r, c) AR[(s) * STGF + (r) * 20 + (c)]
#define HS(r, c)    AR[(r) * 132 + (c)]

    int tid = threadIdx.x;
    int lane = tid & 31, warp = tid >> 5;
    int tq = lane >> 2, tr = lane & 3;
    int warpM = warp & 1, warpN = warp >> 1;
    int row0 = blockIdx.x * 128;

    int glr = tid >> 1;
    int glc = (tid & 1) * 8;
    const float* Xp  = X  + (size_t)(row0 + glr) * 128 + glc;
    const float* W1p = W1 + (size_t)glr * 128 + glc;
    const float* W2p = W2 + (size_t)glr * 128 + glc;
    uint32_t sa = smem_u32(&FA(0, glr, glc));
    uint32_t sb = smem_u32(&FB(0, glr, glc));
    const uint32_t STGB = STGF * 4;

    int arow = warpM * 64 + tq;
    int brow = warpN * 32 + tq;
    float acc[4][4][4] = {};
    uint32_t af[2][4][4], bf[2][4][2];

    // ---------------- phase 1: acc = X @ W1^T (nk16 = 8) -------------------
#pragma unroll
    for (int s = 0; s < NSTG - 1; s++) {
        uint32_t so = (uint32_t)s * STGB;
        cpasync16(sa + so, Xp + s * 16);       cpasync16(sa + so + 16, Xp + s * 16 + 4);
        cpasync16(sb + so, W1p + s * 16);      cpasync16(sb + so + 16, W1p + s * 16 + 4);
        asm volatile("cp.async.commit_group;");
    }
    asm volatile("cp.async.wait_group %0;" :: "n"(NSTG - 2));
    __syncthreads();

#pragma unroll
    for (int mi = 0; mi < 4; mi++) {
        af[0][mi][0] = __float_as_uint(FA(0, arow + mi * 16    , tr    ));
        af[0][mi][1] = __float_as_uint(FA(0, arow + mi * 16 + 8, tr    ));
        af[0][mi][2] = __float_as_uint(FA(0, arow + mi * 16    , tr + 4));
        af[0][mi][3] = __float_as_uint(FA(0, arow + mi * 16 + 8, tr + 4));
    }
#pragma unroll
    for (int ni = 0; ni < 4; ni++) {
        bf[0][ni][0] = __float_as_uint(FB(0, brow + ni * 8, tr    ));
        bf[0][ni][1] = __float_as_uint(FB(0, brow + ni * 8, tr + 4));
    }

    int buf = 0, wslot = NSTG - 1;
    for (int kt = 0; kt < 8; kt++) {
#pragma unroll
        for (int mi = 0; mi < 4; mi++) {
            af[1][mi][0] = __float_as_uint(FA(buf, arow + mi * 16    , 8 + tr    ));
            af[1][mi][1] = __float_as_uint(FA(buf, arow + mi * 16 + 8, 8 + tr    ));
            af[1][mi][2] = __float_as_uint(FA(buf, arow + mi * 16    , 8 + tr + 4));
            af[1][mi][3] = __float_as_uint(FA(buf, arow + mi * 16 + 8, 8 + tr + 4));
        }
#pragma unroll
        for (int ni = 0; ni < 4; ni++) {
            bf[1][ni][0] = __float_as_uint(FB(buf, brow + ni * 8, 8 + tr    ));
            bf[1][ni][1] = __float_as_uint(FB(buf, brow + ni * 8, 8 + tr + 4));
        }
#pragma unroll
        for (int mi = 0; mi < 4; mi++)
#pragma unroll
            for (int ni = 0; ni < 4; ni++)
                mma_tf32(acc[mi][ni], af[0][mi][0], af[0][mi][1],
                         af[0][mi][2], af[0][mi][3],
                         bf[0][ni][0], bf[0][ni][1]);
        int snext = kt + NSTG - 1;
        if (snext < 8) {
            uint32_t so = (uint32_t)wslot * STGB;
            cpasync16(sa + so, Xp + snext * 16);   cpasync16(sa + so + 16, Xp + snext * 16 + 4);
            cpasync16(sb + so, W1p + snext * 16);  cpasync16(sb + so + 16, W1p + snext * 16 + 4);
        }
        asm volatile("cp.async.commit_group;");
        asm volatile("cp.async.wait_group %0;" :: "n"(NSTG - 2));
        __syncthreads();
        if (++wslot == NSTG) wslot = 0;
        int nb = buf + 1; if (nb == NSTG) nb = 0;
        if (kt + 1 < 8) {
#pragma unroll
            for (int mi = 0; mi < 4; mi++) {
                af[0][mi][0] = __float_as_uint(FA(nb, arow + mi * 16    , tr    ));
                af[0][mi][1] = __float_as_uint(FA(nb, arow + mi * 16 + 8, tr    ));
                af[0][mi][2] = __float_as_uint(FA(nb, arow + mi * 16    , tr + 4));
                af[0][mi][3] = __float_as_uint(FA(nb, arow + mi * 16 + 8, tr + 4));
            }
#pragma unroll
            for (int ni = 0; ni < 4; ni++) {
                bf[0][ni][0] = __float_as_uint(FB(nb, brow + ni * 8, tr    ));
                bf[0][ni][1] = __float_as_uint(FB(nb, brow + ni * 8, tr + 4));
            }
        }
#pragma unroll
        for (int mi = 0; mi < 4; mi++)
#pragma unroll
            for (int ni = 0; ni < 4; ni++)
                mma_tf32(acc[mi][ni], af[1][mi][0], af[1][mi][1],
                         af[1][mi][2], af[1][mi][3],
                         bf[1][ni][0], bf[1][ni][1]);
        buf = nb;
    }

    // issue phase-2 W2 prologue into B ring slots 0,1
#pragma unroll
    for (int s = 0; s < NSTG - 1; s++) {
        uint32_t so = (uint32_t)s * STGB;
        cpasync16(sb + so, W2p + s * 16);      cpasync16(sb + so + 16, W2p + s * 16 + 4);
        asm volatile("cp.async.commit_group;");
    }

    // h = relu(acc + b1) -> smem
#pragma unroll
    for (int mi = 0; mi < 4; mi++)
#pragma unroll
        for (int h2 = 0; h2 < 2; h2++) {
            int r = warpM * 64 + mi * 16 + tq + 8 * h2;
#pragma unroll
            for (int ni = 0; ni < 4; ni++) {
                int c = warpN * 32 + ni * 8 + 2 * tr;
                HS(r, c)     = fmaxf(acc[mi][ni][2 * h2]     + b1[c],     0.f);
                HS(r, c + 1) = fmaxf(acc[mi][ni][2 * h2 + 1] + b1[c + 1], 0.f);
            }
        }
    asm volatile("cp.async.wait_group %0;" :: "n"(NSTG - 2));
    __syncthreads();

    // ---------------- phase 2: acc = h @ W2^T (A from hs) ------------------
#pragma unroll
    for (int mi = 0; mi < 4; mi++)
#pragma unroll
        for (int ni = 0; ni < 4; ni++)
#pragma unroll
            for (int q = 0; q < 4; q++) acc[mi][ni][q] = 0.f;

#pragma unroll
    for (int mi = 0; mi < 4; mi++) {
        af[0][mi][0] = __float_as_uint(HS(arow + mi * 16    , tr    ));
        af[0][mi][1] = __float_as_uint(HS(arow + mi * 16 + 8, tr    ));
        af[0][mi][2] = __float_as_uint(HS(arow + mi * 16    , tr + 4));
        af[0][mi][3] = __float_as_uint(HS(arow + mi * 16 + 8, tr + 4));
    }
#pragma unroll
    for (int ni = 0; ni < 4; ni++) {
        bf[0][ni][0] = __float_as_uint(FB(0, brow + ni * 8, tr    ));
        bf[0][ni][1] = __float_as_uint(FB(0, brow + ni * 8, tr + 4));
    }

    buf = 0; wslot = NSTG - 1;
    for (int kt = 0; kt < 8; kt++) {
        int kb = kt * 16;
#pragma unroll
        for (int mi = 0; mi < 4; mi++) {
            af[1][mi][0] = __float_as_uint(HS(arow + mi * 16    , kb + 8 + tr    ));
            af[1][mi][1] = __float_as_uint(HS(arow + mi * 16 + 8, kb + 8 + tr    ));
            af[1][mi][2] = __float_as_uint(HS(arow + mi * 16    , kb + 8 + tr + 4));
            af[1][mi][3] = __float_as_uint(HS(arow + mi * 16 + 8, kb + 8 + tr + 4));
        }
#pragma unroll
        for (int ni = 0; ni < 4; ni++) {
            bf[1][ni][0] = __float_as_uint(FB(buf, brow + ni * 8, 8 + tr    ));
            bf[1][ni][1] = __float_as_uint(FB(buf, brow + ni * 8, 8 + tr + 4));
        }
#pragma unroll
        for (int mi = 0; mi < 4; mi++)
#pragma unroll
            for (int ni = 0; ni < 4; ni++)
                mma_tf32(acc[mi][ni], af[0][mi][0], af[0][mi][1],
                         af[0][mi][2], af[0][mi][3],
                         bf[0][ni][0], bf[0][ni][1]);
        int snext = kt + NSTG - 1;
        if (snext < 8) {
            uint32_t so = (uint32_t)wslot * STGB;
            cpasync16(sb + so, W2p + snext * 16);  cpasync16(sb + so + 16, W2p + snext * 16 + 4);
        }
        asm volatile("cp.async.commit_group;");
        asm volatile("cp.async.wait_group %0;" :: "n"(NSTG - 2));
        __syncthreads();
        if (++wslot == NSTG) wslot = 0;
        int nb = buf + 1; if (nb == NSTG) nb = 0;
        if (kt + 1 < 8) {
            int kn = (kt + 1) * 16;
#pragma unroll
            for (int mi = 0; mi < 4; mi++) {
                af[0][mi][0] = __float_as_uint(HS(arow + mi * 16    , kn + tr    ));
                af[0][mi][1] = __float_as_uint(HS(arow + mi * 16 + 8, kn + tr    ));
                af[0][mi][2] = __float_as_uint(HS(arow + mi * 16    , kn + tr + 4));
                af[0][mi][3] = __float_as_uint(HS(arow + mi * 16 + 8, kn + tr + 4));
            }
#pragma unroll
            for (int ni = 0; ni < 4; ni++) {
                bf[0][ni][0] = __float_as_uint(FB(nb, brow + ni * 8, tr    ));
                bf[0][ni][1] = __float_as_uint(FB(nb, brow + ni * 8, tr + 4));
            }
        }
#pragma unroll
        for (int mi = 0; mi < 4; mi++)
#pragma unroll
            for (int ni = 0; ni < 4; ni++)
                mma_tf32(acc[mi][ni], af[1][mi][0], af[1][mi][1],
                         af[1][mi][2], af[1][mi][3],
                         bf[1][ni][0], bf[1][ni][1]);
        buf = nb;
    }

    // ---------------- epilogue: + b2 + residual x, then LayerNorm ----------
    float* red  = dsm;
    float* stat = dsm + 128 * 17;
#pragma unroll
    for (int mi = 0; mi < 4; mi++)
#pragma unroll
        for (int h2 = 0; h2 < 2; h2++) {
            int r = row0 + warpM * 64 + mi * 16 + tq + 8 * h2;
#pragma unroll
            for (int ni = 0; ni < 4; ni++) {
                int c = warpN * 32 + ni * 8 + 2 * tr;
                float2 rv = *(const float2*)&X[(size_t)r * 128 + c];
                acc[mi][ni][2 * h2]     += b2[c]     + rv.x;
                acc[mi][ni][2 * h2 + 1] += b2[c + 1] + rv.y;
            }
        }
    __syncthreads();
    int cid = warpN * 4 + tr;
#pragma unroll
    for (int mi = 0; mi < 4; mi++)
#pragma unroll
        for (int h2 = 0; h2 < 2; h2++) {
            int rl = warpM * 64 + mi * 16 + tq + 8 * h2;
            float s = 0.f;
#pragma unroll
            for (int ni = 0; ni < 4; ni++) s += acc[mi][ni][2 * h2] + acc[mi][ni][2 * h2 + 1];
            red[rl * 17 + cid] = s;
        }
    __syncthreads();
    if (tid < 128) {
        float s = 0.f;
#pragma unroll
        for (int t = 0; t < 16; t++) s += red[tid * 17 + t];
        stat[tid] = s * (1.f / 128.f);
    }
    __syncthreads();
    float mean[4][2];
#pragma unroll
    for (int mi = 0; mi < 4; mi++)
#pragma unroll
        for (int h2 = 0; h2 < 2; h2++)
            mean[mi][h2] = stat[warpM * 64 + mi * 16 + tq + 8 * h2];
    __syncthreads();
#pragma unroll
    for (int mi = 0; mi < 4; mi++)
#pragma unroll
        for (int h2 = 0; h2 < 2; h2++) {
            int rl = warpM * 64 + mi * 16 + tq + 8 * h2;
            float s = 0.f;
#pragma unroll
            for (int ni = 0; ni < 4; ni++) {
                float d0 = acc[mi][ni][2 * h2]     - mean[mi][h2];
                float d1 = acc[mi][ni][2 * h2 + 1] - mean[mi][h2];
                s += d0 * d0 + d1 * d1;
            }
            red[rl * 17 + cid] = s;
        }
    __syncthreads();
    if (tid < 128) {
        float s = 0.f;
#pragma unroll
        for (int t = 0; t < 16; t++) s += red[tid * 17 + t];
        stat[tid] = rsqrtf(s * (1.f / 128.f) + EPSV);
    }
    __syncthreads();
#pragma unroll
    for (int mi = 0; mi < 4; mi++)
#pragma unroll
        for (int h2 = 0; h2 < 2; h2++) {
            int rl = warpM * 64 + mi * 16 + tq + 8 * h2;
            int r = row0 + rl;
            float rs = stat[rl];
#pragma unroll
            for (int ni = 0; ni < 4; ni++) {
                int c = warpN * 32 + ni * 8 + 2 * tr;
                float v0 = (acc[mi][ni][2 * h2]     - mean[mi][h2]) * rs * lng[c]     + lnb[c];
                float v1 = (acc[mi][ni][2 * h2 + 1] - mean[mi][h2]) * rs * lng[c + 1] + lnb[c + 1];
                *(float2*)&C[(size_t)r * 128 + c] = make_float2(v0, v1);
            }
        }
#undef FB
#undef FA
#undef HS
}

// ======== tensor-core attention: one CTA per (seq, head), 256 threads ======
#define ATTN_SMEM_FLOATS (128 * 132 + 32 * 132)
#define ATTN_SMEM_BYTES  (ATTN_SMEM_FLOATS * 4)

__global__ __launch_bounds__(256)
void attn_mma_kernel(const float* __restrict__ qkv, float* __restrict__ out)
{
    extern __shared__ float smf[];
    float (*qs)[36]  = (float(*)[36])smf;
    float (*ks)[36]  = (float(*)[36])(smf + 128 * 36);
    float (*sp)[132] = (float(*)[132])smf;
    float (*vt)[132] = (float(*)[132])(smf + 128 * 132);

    int s  = blockIdx.x >> 2;
    int hh = blockIdx.x & 3;
    int tid = threadIdx.x;
    int lane = tid & 31, warp = tid >> 5;
    int tq = lane >> 2, tr = lane & 3;
    int warpM = warp & 1, warpN = warp >> 1;

    for (int idx = tid; idx < 7 * 36; idx += 256) {
        int r = 121 + idx / 36, c = idx % 36;
        qs[r][c] = 0.f;
        ks[r][c] = 0.f;
    }
    for (int idx = tid; idx < 32 * 7; idx += 256) {
        int d = idx / 7, c = 121 + idx % 7;
        vt[d][c] = 0.f;
    }

    const float* base = qkv + (size_t)s * NT * 384 + hh * HDH;
    for (int idx = tid; idx < NT * 8; idx += 256) {
        int n = idx >> 3, d4 = (idx & 7) * 4;
        const float* bp = base + (size_t)n * 384 + d4;
        float4 qv = *(const float4*)(bp);
        float4 kv = *(const float4*)(bp + 128);
        float4 vv = *(const float4*)(bp + 256);
        *(float4*)&qs[n][d4] = qv;
        *(float4*)&ks[n][d4] = kv;
        vt[d4 + 0][n] = vv.x;
        vt[d4 + 1][n] = vv.y;
        vt[d4 + 2][n] = vv.z;
        vt[d4 + 3][n] = vv.w;
    }
    __syncthreads();

    float acc[4][4][4] = {};
#pragma unroll
    for (int k8 = 0; k8 < 32; k8 += 8) {
        uint32_t af[4][4], bf[4][2];
#pragma unroll
        for (int mi = 0; mi < 4; mi++) {
            int ar = warpM * 64 + mi * 16 + tq;
            af[mi][0] = __float_as_uint(qs[ar    ][k8 + tr    ]);
            af[mi][1] = __float_as_uint(qs[ar + 8][k8 + tr    ]);
            af[mi][2] = __float_as_uint(qs[ar    ][k8 + tr + 4]);
            af[mi][3] = __float_as_uint(qs[ar + 8][k8 + tr + 4]);
        }
#pragma unroll
        for (int ni = 0; ni < 4; ni++) {
            int br = warpN * 32 + ni * 8 + tq;
            bf[ni][0] = __float_as_uint(ks[br][k8 + tr    ]);
            bf[ni][1] = __float_as_uint(ks[br][k8 + tr + 4]);
        }
#pragma unroll
        for (int mi = 0; mi < 4; mi++)
#pragma unroll
            for (int ni = 0; ni < 4; ni++)
                mma_tf32(acc[mi][ni], af[mi][0], af[mi][1], af[mi][2], af[mi][3],
                         bf[ni][0], bf[ni][1]);
    }
    __syncthreads();

#pragma unroll
    for (int mi = 0; mi < 4; mi++)
#pragma unroll
        for (int h = 0; h < 2; h++) {
            int r = warpM * 64 + mi * 16 + tq + 8 * h;
#pragma unroll
            for (int ni = 0; ni < 4; ni++) {
                int c = warpN * 32 + ni * 8 + 2 * tr;
                *(float2*)&sp[r][c] = make_float2(acc[mi][ni][2 * h], acc[mi][ni][2 * h + 1]);
            }
        }
    __syncthreads();

    const float scale = 0.17677669529663687f;
    if (tid < 128) {
        float mx = -1e30f;
        for (int c = 0; c < NT; c++) mx = fmaxf(mx, sp[tid][c]);
        float sum = 0.f;
        for (int c = 0; c < NT; c++) {
            float e = __expf((sp[tid][c] - mx) * scale);
            sp[tid][c] = e;
            sum += e;
        }
        float inv = 1.f / sum;
        for (int c = 0; c < NT; c++) sp[tid][c] *= inv;
#pragma unroll
        for (int c = NT; c < 128; c++) sp[tid][c] = 0.f;
    }
    __syncthreads();

    float pacc[4][4] = {};
#pragma unroll
    for (int k8 = 0; k8 < 128; k8 += 8) {
        uint32_t af[4][4], bf[2];
#pragma unroll
        for (int mi = 0; mi < 4; mi++) {
            int ar = warpM * 64 + mi * 16 + tq;
            af[mi][0] = __float_as_uint(sp[ar    ][k8 + tr    ]);
            af[mi][1] = __float_as_uint(sp[ar + 8][k8 + tr    ]);
            af[mi][2] = __float_as_uint(sp[ar    ][k8 + tr + 4]);
            af[mi][3] = __float_as_uint(sp[ar + 8][k8 + tr + 4]);
        }
        int bn = warpN * 8 + tq;
        bf[0] = __float_as_uint(vt[bn][k8 + tr    ]);
        bf[1] = __float_as_uint(vt[bn][k8 + tr + 4]);
#pragma unroll
        for (int mi = 0; mi < 4; mi++)
            mma_tf32(pacc[mi], af[mi][0], af[mi][1], af[mi][2], af[mi][3],
                     bf[0], bf[1]);
    }

#pragma unroll
    for (int mi = 0; mi < 4; mi++)
#pragma unroll
        for (int h = 0; h < 2; h++) {
            int r = warpM * 64 + mi * 16 + tq + 8 * h;
            if (r < NT) {
                int c = warpN * 8 + 2 * tr;
                *(float2*)&out[((size_t)s * NT + r) * HDIM + hh * HDH + c] =
                    make_float2(pacc[mi][2 * h], pacc[mi][2 * h + 1]);
            }
        }
}

// ------- final: reduce split-K partials + bias + LayerNorm over 256 -------
__global__ void out_ln_kernel(const float* __restrict__ part,
                              const float* __restrict__ b_out,
                              const float* __restrict__ g,
                              const float* __restrict__ b,
                              float* __restrict__ out)
{
    int row = blockIdx.x, t = threadIdx.x;
    size_t idx = (size_t)row * OUTD + t;
    float v = b_out[t];
#pragma unroll
    for (int z = 0; z < SPLITK; z++) v += part[(size_t)z * SEQ * OUTD + idx];
    __shared__ float red[9];
    int lane = t & 31, warp = t >> 5;
    float s = v;
#pragma unroll
    for (int o = 16; o; o >>= 1) s += __shfl_xor_sync(0xffffffffu, s, o);
    if (lane == 0) red[warp] = s;
    __syncthreads();
    if (t == 0) { float tot = 0; for (int i = 0; i < 8; i++) tot += red[i]; red[8] = tot; }
    __syncthreads();
    float mean = red[8] * (1.f / 256.f);
    float d = v - mean;
    float s2 = d * d;
#pragma unroll
    for (int o = 16; o; o >>= 1) s2 += __shfl_xor_sync(0xffffffffu, s2, o);
    __syncthreads();
    if (lane == 0) red[warp] = s2;
    __syncthreads();
    if (t == 0) { float tot = 0; for (int i = 0; i < 8; i++) tot += red[i]; red[8] = tot; }
    __syncthreads();
    float var = red[8] * (1.f / 256.f);
    out[idx] = d * rsqrtf(var + EPSV) * g[t] + b[t];
}

// ---------------- launch ---------------------------------------------------
extern "C" void kernel_launch(void* const* d_in, const int* in_sizes, int n_in,
                              void* d_out, int out_size)
{
    const float* forest = (const float*)d_in[0];
    const int*   perm   = (const int*)  d_in[2];
    const float* w_in   = (const float*)d_in[3];
    const float* b_in   = (const float*)d_in[4];
    const float* qkv_w  = (const float*)d_in[5];
    const float* qkv_b  = (const float*)d_in[6];
    const float* proj_w = (const float*)d_in[7];
    const float* proj_b = (const float*)d_in[8];
    const float* ff1_w  = (const float*)d_in[9];
    const float* ff1_b  = (const float*)d_in[10];
    const float* ff2_w  = (const float*)d_in[11];
    const float* ff2_b  = (const float*)d_in[12];
    const float* ln1_g  = (const float*)d_in[13];
    const float* ln1_b  = (const float*)d_in[14];
    const float* ln2_g  = (const float*)d_in[15];
    const float* ln2_b  = (const float*)d_in[16];
    const float* w_out  = (const float*)d_in[17];
    const float* b_out  = (const float*)d_in[18];
    const float* lnf_g  = (const float*)d_in[19];
    const float* lnf_b  = (const float*)d_in[20];

    float *xb, *qb, *ab, *pb;
    cudaGetSymbolAddress((void**)&xb, g_x);
    cudaGetSymbolAddress((void**)&qb, g_qkv);
    cudaGetSymbolAddress((void**)&ab, g_att);
    cudaGetSymbolAddress((void**)&pb, g_py);

    cudaFuncSetAttribute(qkv_kernel,
                         cudaFuncAttributeMaxDynamicSharedMemorySize, QKV_DYN_BYTES);
    cudaFuncSetAttribute(ffn_kernel,
                         cudaFuncAttributeMaxDynamicSharedMemorySize, FFN_DYN_BYTES);
    cudaFuncSetAttribute(attn_mma_kernel,
                         cudaFuncAttributeMaxDynamicSharedMemorySize, ATTN_SMEM_BYTES);

    embed_kernel<<<MTOK / 16, 128>>>(forest, perm, w_in, b_in, xb);

    const int GR = MTOK / 128;  // 1936
    for (int l = 0; l < 2; l++) {
        qkv_kernel<<<GR, 256, QKV_DYN_BYTES>>>(
            xb, qkv_w + (size_t)l * 384 * 128, qkv_b + l * 384, qb);
        attn_mma_kernel<<<SEQ * NHEAD, 256, ATTN_SMEM_BYTES>>>(qb, ab);
        gemm_tf32_kernel<<<dim3(1, GR), 256>>>(
            ab, proj_w + (size_t)l * 128 * 128, proj_b + l * 128,
            xb, ln1_g + l * 128, ln1_b + l * 128, xb, MTOK, 128, 128, 128, 2);
        ffn_kernel<<<GR, 256, FFN_DYN_BYTES>>>(
            xb, ff1_w + (size_t)l * 128 * 128, ff1_b + l * 128,
            ff2_w + (size_t)l * 128 * 128, ff2_b + l * 128,
            ln2_g + l * 128, ln2_b + l * 128, xb);
    }

    // output projection: split-K = 11 in one launch (15488 = 11 * 1408)
    gemm_tf32_kernel<<<dim3(OUTD / 128, SEQ / 128, SPLITK), 256>>>(
        xb, w_out, nullptr, nullptr, nullptr, nullptr,
        pb, SEQ, OUTD, KBIG, KBIG / SPLITK, 3);
    out_ln_kernel<<<SEQ, 256>>>(pb, b_out, lnf_g, lnf_b, (float*)d_out);
}